// round 1
// baseline (speedup 1.0000x reference)
#include <cuda_runtime.h>
#include <math.h>

// ---------------- problem constants ----------------
#define ROWS  16384        // B*S = 32*512
#define DMODEL 512
#define NHEADS 4
#define HDIM   128
#define SEQ    512
#define BATCH  32
#define NQ     8
#define DIMQ   256         // 2^8

// ---------------- scratch (static device memory; no allocs) ----------------
__device__ float  g_qkv    [ROWS * 1536];
__device__ float  g_scores [BATCH * NHEADS * SEQ * SEQ];
__device__ float  g_attnc  [ROWS * DMODEL];
__device__ float  g_attnproj[ROWS * DMODEL];
__device__ float  g_x1     [ROWS * DMODEL];
__device__ float  g_xnorm  [ROWS * DMODEL];
__device__ float  g_angles [ROWS * NQ];
__device__ float2 g_U      [DIMQ * DIMQ];
__device__ float2 g_psi    [ROWS * DIMQ];
__device__ float2 g_phi    [ROWS * DIMQ];
__device__ float  g_z      [ROWS * NQ];
__device__ float  g_x2     [ROWS * DMODEL];
__device__ float  g_hbuf   [ROWS * 2048];
__device__ float  g_ffnout [ROWS * DMODEL];

// ---------------- helpers ----------------
__device__ __forceinline__ float warp_sum(float v) {
    #pragma unroll
    for (int o = 16; o; o >>= 1) v += __shfl_xor_sync(0xffffffffu, v, o);
    return v;
}
__device__ __forceinline__ float warp_max(float v) {
    #pragma unroll
    for (int o = 16; o; o >>= 1) v = fmaxf(v, __shfl_xor_sync(0xffffffffu, v, o));
    return v;
}
__device__ __forceinline__ float gelu_exact(float x) {
    return 0.5f * x * (1.0f + erff(x * 0.7071067811865476f));
}

// ---------------- generic tiled SGEMM ----------------
// C[m,n] = alpha * sum_k A[m,k] * (TB ? B[n,k] : B[k,n])  (+bias, +gelu per EPI)
// Batched via blockIdx.z: b = z/nh, h = z%nh; offsets b*s?b + h*s?h.
// Requires: M%128==0, N%128==0, K%16==0, all ld %4==0, 16B-aligned bases.
#define BM 128
#define BN 128
#define BKT 16
#define TM 8
#define TN 8

template<bool TB, int EPI>
__global__ void __launch_bounds__(256) sgemm_kernel(
    const float* __restrict__ A, const float* __restrict__ B,
    const float* __restrict__ bias, float* __restrict__ C,
    int K, int lda, int ldb, int ldc,
    int nh, long sAb, long sAh, long sBb, long sBh, long sCb, long sCh,
    float alpha)
{
    int bz = blockIdx.z;
    int bb = bz / nh, hh = bz % nh;
    A += bb * sAb + hh * sAh;
    B += bb * sBb + hh * sBh;
    C += bb * sCb + hh * sCh;

    __shared__ float As[BKT][BM + 4];
    __shared__ float Bs[BKT][BN + 4];

    const int tid = threadIdx.x;
    const int tx = tid & 15;      // 0..15  -> N
    const int ty = tid >> 4;      // 0..15  -> M
    const int rowBase = blockIdx.y * BM;
    const int colBase = blockIdx.x * BN;

    float acc[TM][TN];
    #pragma unroll
    for (int i = 0; i < TM; i++)
        #pragma unroll
        for (int j = 0; j < TN; j++) acc[i][j] = 0.f;

    for (int kt = 0; kt < K; kt += BKT) {
        // load A tile: 128 rows x 16 k
        #pragma unroll
        for (int it = 0; it < 2; it++) {
            int idx = tid + it * 256;          // 0..511 float4 slots
            int r  = idx >> 2;
            int c4 = idx & 3;
            float4 v = *(const float4*)(A + (long)(rowBase + r) * lda + kt + c4 * 4);
            As[c4 * 4 + 0][r] = v.x;
            As[c4 * 4 + 1][r] = v.y;
            As[c4 * 4 + 2][r] = v.z;
            As[c4 * 4 + 3][r] = v.w;
        }
        if (TB) {
            #pragma unroll
            for (int it = 0; it < 2; it++) {
                int idx = tid + it * 256;
                int r  = idx >> 2;
                int c4 = idx & 3;
                float4 v = *(const float4*)(B + (long)(colBase + r) * ldb + kt + c4 * 4);
                Bs[c4 * 4 + 0][r] = v.x;
                Bs[c4 * 4 + 1][r] = v.y;
                Bs[c4 * 4 + 2][r] = v.z;
                Bs[c4 * 4 + 3][r] = v.w;
            }
        } else {
            #pragma unroll
            for (int it = 0; it < 2; it++) {
                int idx = tid + it * 256;
                int kk = idx >> 5;             // 0..15
                int n4 = idx & 31;             // 0..31 float4 along n
                float4 v = *(const float4*)(B + (long)(kt + kk) * ldb + colBase + n4 * 4);
                *(float4*)&Bs[kk][n4 * 4] = v;
            }
        }
        __syncthreads();

        #pragma unroll
        for (int kk = 0; kk < BKT; kk++) {
            float ar[TM], br[TN];
            float4 a0 = *(const float4*)&As[kk][ty * 8];
            float4 a1 = *(const float4*)&As[kk][ty * 8 + 4];
            float4 b0 = *(const float4*)&Bs[kk][tx * 8];
            float4 b1 = *(const float4*)&Bs[kk][tx * 8 + 4];
            ar[0]=a0.x; ar[1]=a0.y; ar[2]=a0.z; ar[3]=a0.w;
            ar[4]=a1.x; ar[5]=a1.y; ar[6]=a1.z; ar[7]=a1.w;
            br[0]=b0.x; br[1]=b0.y; br[2]=b0.z; br[3]=b0.w;
            br[4]=b1.x; br[5]=b1.y; br[6]=b1.z; br[7]=b1.w;
            #pragma unroll
            for (int i = 0; i < TM; i++)
                #pragma unroll
                for (int j = 0; j < TN; j++)
                    acc[i][j] = fmaf(ar[i], br[j], acc[i][j]);
        }
        __syncthreads();
    }

    #pragma unroll
    for (int i = 0; i < TM; i++) {
        int r = rowBase + ty * 8 + i;
        #pragma unroll
        for (int j = 0; j < TN; j += 4) {
            int c = colBase + tx * 8 + j;
            float4 v;
            v.x = acc[i][j + 0] * alpha;
            v.y = acc[i][j + 1] * alpha;
            v.z = acc[i][j + 2] * alpha;
            v.w = acc[i][j + 3] * alpha;
            if (EPI >= 1) {
                float4 bv = *(const float4*)(bias + c);
                v.x += bv.x; v.y += bv.y; v.z += bv.z; v.w += bv.w;
            }
            if (EPI == 2) {
                v.x = gelu_exact(v.x); v.y = gelu_exact(v.y);
                v.z = gelu_exact(v.z); v.w = gelu_exact(v.w);
            }
            *(float4*)(C + (long)r * ldc + c) = v;
        }
    }
}

// ---------------- complex GEMM: Phi[r,s] = sum_c Psi[r,c] * U[s,c] ----------------
__global__ void __launch_bounds__(256) cgemm_nt_kernel(
    const float2* __restrict__ A, const float2* __restrict__ B, float2* __restrict__ C)
{
    __shared__ float2 As[16][66];
    __shared__ float2 Bs[16][66];
    const int tid = threadIdx.x;
    const int tx = tid & 15;
    const int ty = tid >> 4;
    const int rowBase = blockIdx.y * 64;
    const int colBase = blockIdx.x * 64;

    float2 acc[4][4];
    #pragma unroll
    for (int i = 0; i < 4; i++)
        #pragma unroll
        for (int j = 0; j < 4; j++) acc[i][j] = make_float2(0.f, 0.f);

    for (int kt = 0; kt < 256; kt += 16) {
        #pragma unroll
        for (int it = 0; it < 4; it++) {
            int idx = tid + it * 256;    // 0..1023
            int r = idx >> 4;            // 0..63
            int c = idx & 15;
            As[c][r] = A[(long)(rowBase + r) * 256 + kt + c];
            Bs[c][r] = B[(long)(colBase + r) * 256 + kt + c];
        }
        __syncthreads();
        #pragma unroll
        for (int kk = 0; kk < 16; kk++) {
            float2 a[4], b[4];
            #pragma unroll
            for (int i = 0; i < 4; i++) a[i] = As[kk][ty * 4 + i];
            #pragma unroll
            for (int j = 0; j < 4; j++) b[j] = Bs[kk][tx * 4 + j];
            #pragma unroll
            for (int i = 0; i < 4; i++)
                #pragma unroll
                for (int j = 0; j < 4; j++) {
                    acc[i][j].x = fmaf(a[i].x, b[j].x, acc[i][j].x);
                    acc[i][j].x = fmaf(-a[i].y, b[j].y, acc[i][j].x);
                    acc[i][j].y = fmaf(a[i].x, b[j].y, acc[i][j].y);
                    acc[i][j].y = fmaf(a[i].y, b[j].x, acc[i][j].y);
                }
        }
        __syncthreads();
    }
    #pragma unroll
    for (int i = 0; i < 4; i++)
        #pragma unroll
        for (int j = 0; j < 4; j++)
            C[(long)(rowBase + ty * 4 + i) * 256 + colBase + tx * 4 + j] = acc[i][j];
}

// ---------------- LayerNorm: out = LN(A (+R)) * g + b, one warp per row ----------------
__global__ void ln_kernel(const float* __restrict__ A, const float* __restrict__ R,
                          const float* __restrict__ g, const float* __restrict__ b,
                          float* __restrict__ out, int nrows)
{
    int warp = (blockIdx.x * blockDim.x + threadIdx.x) >> 5;
    int lane = threadIdx.x & 31;
    if (warp >= nrows) return;
    const float* a = A + (long)warp * DMODEL;
    float4 v[4];
    float s = 0.f;
    #pragma unroll
    for (int t = 0; t < 4; t++) {
        int c = (t * 32 + lane) * 4;
        v[t] = *(const float4*)(a + c);
        if (R) {
            float4 r4 = *(const float4*)(R + (long)warp * DMODEL + c);
            v[t].x += r4.x; v[t].y += r4.y; v[t].z += r4.z; v[t].w += r4.w;
        }
        s += v[t].x + v[t].y + v[t].z + v[t].w;
    }
    s = warp_sum(s);
    float mean = s * (1.f / DMODEL);
    float vs = 0.f;
    #pragma unroll
    for (int t = 0; t < 4; t++) {
        float dx = v[t].x - mean, dy = v[t].y - mean, dz = v[t].z - mean, dw = v[t].w - mean;
        vs += dx * dx + dy * dy + dz * dz + dw * dw;
    }
    vs = warp_sum(vs);
    float rstd = rsqrtf(vs * (1.f / DMODEL) + 1e-5f);
    #pragma unroll
    for (int t = 0; t < 4; t++) {
        int c = (t * 32 + lane) * 4;
        float4 gv = *(const float4*)(g + c);
        float4 bv = *(const float4*)(b + c);
        float4 o;
        o.x = (v[t].x - mean) * rstd * gv.x + bv.x;
        o.y = (v[t].y - mean) * rstd * gv.y + bv.y;
        o.z = (v[t].z - mean) * rstd * gv.z + bv.z;
        o.w = (v[t].w - mean) * rstd * gv.w + bv.w;
        *(float4*)(out + (long)warp * DMODEL + c) = o;
    }
}

// ---------------- row softmax over 512, one warp per row ----------------
__global__ void softmax_kernel(float* __restrict__ S, int nrows)
{
    int warp = (blockIdx.x * blockDim.x + threadIdx.x) >> 5;
    int lane = threadIdx.x & 31;
    if (warp >= nrows) return;
    float* r = S + (long)warp * SEQ;
    float4 v[4];
    float m = -3.4e38f;
    #pragma unroll
    for (int t = 0; t < 4; t++) {
        v[t] = *(const float4*)(r + (t * 32 + lane) * 4);
        m = fmaxf(m, fmaxf(fmaxf(v[t].x, v[t].y), fmaxf(v[t].z, v[t].w)));
    }
    m = warp_max(m);
    float s = 0.f;
    #pragma unroll
    for (int t = 0; t < 4; t++) {
        v[t].x = __expf(v[t].x - m); v[t].y = __expf(v[t].y - m);
        v[t].z = __expf(v[t].z - m); v[t].w = __expf(v[t].w - m);
        s += v[t].x + v[t].y + v[t].z + v[t].w;
    }
    s = warp_sum(s);
    float inv = 1.f / s;
    #pragma unroll
    for (int t = 0; t < 4; t++) {
        v[t].x *= inv; v[t].y *= inv; v[t].z *= inv; v[t].w *= inv;
        *(float4*)(r + (t * 32 + lane) * 4) = v[t];
    }
}

// ---------------- angles = xnorm @ qin_w^T + qin_b, one warp per row ----------------
__global__ void qin_kernel(const float* __restrict__ xn, const float* __restrict__ w,
                           const float* __restrict__ b, float* __restrict__ ang)
{
    int warp = (blockIdx.x * blockDim.x + threadIdx.x) >> 5;
    int lane = threadIdx.x & 31;
    if (warp >= ROWS) return;
    const float* xr = xn + (long)warp * DMODEL;
    float4 xv[4];
    #pragma unroll
    for (int t = 0; t < 4; t++) xv[t] = *(const float4*)(xr + (t * 32 + lane) * 4);
    float myang = 0.f;
    #pragma unroll
    for (int o = 0; o < NQ; o++) {
        const float* wr = w + o * DMODEL;
        float p = 0.f;
        #pragma unroll
        for (int t = 0; t < 4; t++) {
            float4 wv = *(const float4*)(wr + (t * 32 + lane) * 4);
            p += xv[t].x * wv.x + xv[t].y * wv.y + xv[t].z * wv.z + xv[t].w * wv.w;
        }
        p = warp_sum(p);
        if (lane == o) myang = p + b[o];
    }
    if (lane < NQ) ang[(long)warp * NQ + lane] = myang;
}

// ---------------- build fixed circuit unitary U (256x256), one block per column ----------------
__global__ void build_u_kernel(const float* __restrict__ qw, float2* __restrict__ U)
{
    __shared__ float2 st[DIMQ];
    int col = blockIdx.x;
    int t = threadIdx.x;   // 128 threads
    st[t] = make_float2(0.f, 0.f);
    st[t + 128] = make_float2(0.f, 0.f);
    __syncthreads();
    if (t == 0) st[col] = make_float2(1.f, 0.f);
    __syncthreads();

    for (int l = 0; l < 4; l++) {
        for (int i = 0; i < NQ; i++) {
            float w0 = qw[(l * 2 + 0) * NQ + i];
            float w1 = qw[(l * 2 + 1) * NQ + i];
            float sn, cs, sn2, cs2;
            sincosf(0.5f * w0, &sn, &cs);
            sincosf(0.5f * w1, &sn2, &cs2);
            // M = RZ(w1) * RX(w0)
            float2 M00 = make_float2( cs * cs2, -cs * sn2);
            float2 M01 = make_float2(-sn * sn2, -sn * cs2);
            float2 M10 = make_float2( sn * sn2, -sn * cs2);
            float2 M11 = make_float2( cs * cs2,  cs * sn2);
            int bpos = 7 - i;
            int lowmask = (1 << bpos) - 1;
            int s0 = ((t >> bpos) << (bpos + 1)) | (t & lowmask);
            int s1 = s0 | (1 << bpos);
            float2 a0 = st[s0], a1 = st[s1];
            float2 n0, n1;
            n0.x = M00.x * a0.x - M00.y * a0.y + M01.x * a1.x - M01.y * a1.y;
            n0.y = M00.x * a0.y + M00.y * a0.x + M01.x * a1.y + M01.y * a1.x;
            n1.x = M10.x * a0.x - M10.y * a0.y + M11.x * a1.x - M11.y * a1.y;
            n1.y = M10.x * a0.y + M10.y * a0.x + M11.x * a1.y + M11.y * a1.x;
            st[s0] = n0; st[s1] = n1;
            __syncthreads();
        }
        for (int i = 0; i < NQ - 1; i++) {
            int cb = 7 - i, tb = 6 - i;
            if (t < 64) {
                int tlow = t & ((1 << tb) - 1);
                int s0 = ((t >> tb) << (tb + 2)) | (1 << cb) | tlow;
                int s1 = s0 | (1 << tb);
                float2 tmp = st[s0]; st[s0] = st[s1]; st[s1] = tmp;
            }
            __syncthreads();
        }
    }
    U[(long)t * DIMQ + col] = st[t];
    U[(long)(t + 128) * DIMQ + col] = st[t + 128];
}

// ---------------- product state Psi, one block (256 thr) per row ----------------
__global__ void psi_kernel(const float* __restrict__ ang, float2* __restrict__ psi)
{
    __shared__ float2 sq[NQ][2];
    int row = blockIdx.x;
    int s = threadIdx.x;
    if (s < NQ) {
        float a = ang[(long)row * NQ + s];
        float sn, cs;
        sincosf(0.5f * a, &sn, &cs);
        sq[s][0] = make_float2(cs * cs, -cs * sn);   // RZ(a)RX(a)|0> component 0
        sq[s][1] = make_float2(sn * sn, -sn * cs);   // component 1
    }
    __syncthreads();
    float2 amp = make_float2(1.f, 0.f);
    #pragma unroll
    for (int i = 0; i < NQ; i++) {
        float2 q = sq[i][(s >> (7 - i)) & 1];
        float2 na;
        na.x = amp.x * q.x - amp.y * q.y;
        na.y = amp.x * q.y + amp.y * q.x;
        amp = na;
    }
    psi[(long)row * DIMQ + s] = amp;
}

// ---------------- z_i = sum_s sign_i(s) |phi_s|^2, one block per row ----------------
__global__ void zexp_kernel(const float2* __restrict__ Phi, float* __restrict__ Z)
{
    __shared__ float partial[8][9];
    int row = blockIdx.x;
    int s = threadIdx.x;
    float2 p2 = Phi[(long)row * DIMQ + s];
    float p = p2.x * p2.x + p2.y * p2.y;
    int lane = s & 31, wid = s >> 5;
    float vals[NQ];
    #pragma unroll
    for (int i = 0; i < NQ; i++)
        vals[i] = ((s >> (7 - i)) & 1) ? -p : p;
    #pragma unroll
    for (int o = 16; o; o >>= 1)
        #pragma unroll
        for (int i = 0; i < NQ; i++)
            vals[i] += __shfl_xor_sync(0xffffffffu, vals[i], o);
    if (lane == 0)
        #pragma unroll
        for (int i = 0; i < NQ; i++) partial[wid][i] = vals[i];
    __syncthreads();
    if (s < NQ) {
        float acc = 0.f;
        #pragma unroll
        for (int w = 0; w < 8; w++) acc += partial[w][s];
        Z[(long)row * NQ + s] = acc;
    }
}

// ---------------- x2 = x1 + z @ qout_w^T + qout_b ----------------
__global__ void qout_add_kernel(const float* __restrict__ x1, const float* __restrict__ z,
                                const float* __restrict__ w, const float* __restrict__ b,
                                float* __restrict__ out)
{
    long gidx = (long)blockIdx.x * 256 + threadIdx.x;
    int row = (int)(gidx >> 9);
    int col = (int)(gidx & 511);
    const float* zr = z + (long)row * NQ;
    float4 w0 = *(const float4*)(w + (long)col * NQ);
    float4 w1 = *(const float4*)(w + (long)col * NQ + 4);
    float acc = b[col];
    acc += zr[0] * w0.x + zr[1] * w0.y + zr[2] * w0.z + zr[3] * w0.w;
    acc += zr[4] * w1.x + zr[5] * w1.y + zr[6] * w1.z + zr[7] * w1.w;
    out[gidx] = x1[gidx] + acc;
}

// ---------------- launch ----------------
extern "C" void kernel_launch(void* const* d_in, const int* in_sizes, int n_in,
                              void* d_out, int out_size)
{
    const float* x          = (const float*)d_in[0];
    const float* attn_in_w  = (const float*)d_in[1];
    const float* attn_in_b  = (const float*)d_in[2];
    const float* attn_out_w = (const float*)d_in[3];
    const float* attn_out_b = (const float*)d_in[4];
    const float* ln1_g      = (const float*)d_in[5];
    const float* ln1_b      = (const float*)d_in[6];
    const float* ln2_g      = (const float*)d_in[7];
    const float* ln2_b      = (const float*)d_in[8];
    const float* ln3_g      = (const float*)d_in[9];
    const float* ln3_b      = (const float*)d_in[10];
    const float* qin_w      = (const float*)d_in[11];
    const float* qin_b      = (const float*)d_in[12];
    const float* qweights   = (const float*)d_in[13];
    const float* qout_w     = (const float*)d_in[14];
    const float* qout_b     = (const float*)d_in[15];
    const float* ffn_w1     = (const float*)d_in[16];
    const float* ffn_b1     = (const float*)d_in[17];
    const float* ffn_w2     = (const float*)d_in[18];
    const float* ffn_b2     = (const float*)d_in[19];
    float* out = (float*)d_out;

    float  *qkv, *scores, *attnc, *attnproj, *x1, *xnorm, *angles, *zbuf, *x2, *hbuf, *ffnout;
    float2 *U, *psi, *phi;
    cudaGetSymbolAddress((void**)&qkv,      g_qkv);
    cudaGetSymbolAddress((void**)&scores,   g_scores);
    cudaGetSymbolAddress((void**)&attnc,    g_attnc);
    cudaGetSymbolAddress((void**)&attnproj, g_attnproj);
    cudaGetSymbolAddress((void**)&x1,       g_x1);
    cudaGetSymbolAddress((void**)&xnorm,    g_xnorm);
    cudaGetSymbolAddress((void**)&angles,   g_angles);
    cudaGetSymbolAddress((void**)&U,        g_U);
    cudaGetSymbolAddress((void**)&psi,      g_psi);
    cudaGetSymbolAddress((void**)&phi,      g_phi);
    cudaGetSymbolAddress((void**)&zbuf,     g_z);
    cudaGetSymbolAddress((void**)&x2,       g_x2);
    cudaGetSymbolAddress((void**)&hbuf,     g_hbuf);
    cudaGetSymbolAddress((void**)&ffnout,   g_ffnout);

    const float inv_sqrt_hd = 0.08838834764831845f;   // 1/sqrt(128)

    // 1) qkv = x @ in_w^T + in_b          [16384,1536]
    sgemm_kernel<true, 1><<<dim3(1536 / 128, ROWS / 128, 1), 256>>>(
        x, attn_in_w, attn_in_b, qkv, DMODEL, DMODEL, DMODEL, 1536,
        1, 0, 0, 0, 0, 0, 0, 1.f);

    // 2) scores[bh] = Q K^T / sqrt(hd)    batched over 128 bh
    sgemm_kernel<true, 0><<<dim3(SEQ / 128, SEQ / 128, BATCH * NHEADS), 256>>>(
        qkv, qkv + 512, nullptr, scores, HDIM, 1536, 1536, SEQ,
        NHEADS,
        (long)SEQ * 1536, 128,               // A (Q) strides: batch, head
        (long)SEQ * 1536, 128,               // B (K)
        (long)NHEADS * SEQ * SEQ, (long)SEQ * SEQ,  // C
        inv_sqrt_hd);

    // 3) softmax rows
    softmax_kernel<<<(BATCH * NHEADS * SEQ) / 8, 256>>>(scores, BATCH * NHEADS * SEQ);

    // 4) attnc[bh] = P V  (write in concat layout [row, h*128+j])
    sgemm_kernel<false, 0><<<dim3(HDIM / 128, SEQ / 128, BATCH * NHEADS), 256>>>(
        scores, qkv + 1024, nullptr, attnc, SEQ, SEQ, 1536, DMODEL,
        NHEADS,
        (long)NHEADS * SEQ * SEQ, (long)SEQ * SEQ,  // A (P)
        (long)SEQ * 1536, 128,                      // B (V)
        (long)SEQ * DMODEL, 128,                    // C
        1.f);

    // 5) attnproj = attnc @ out_w^T + out_b
    sgemm_kernel<true, 1><<<dim3(DMODEL / 128, ROWS / 128, 1), 256>>>(
        attnc, attn_out_w, attn_out_b, attnproj, DMODEL, DMODEL, DMODEL, DMODEL,
        1, 0, 0, 0, 0, 0, 0, 1.f);

    // 6) x1 = LN(x + attnproj; ln1)
    ln_kernel<<<ROWS / 8, 256>>>(x, attnproj, ln1_g, ln1_b, x1, ROWS);

    // 7) xnorm = LN(x1; ln3)
    ln_kernel<<<ROWS / 8, 256>>>(x1, nullptr, ln3_g, ln3_b, xnorm, ROWS);

    // 8) angles = xnorm @ qin_w^T + qin_b
    qin_kernel<<<ROWS / 8, 256>>>(xnorm, qin_w, qin_b, angles);

    // 9) fixed circuit unitary U (depends only on qweights)
    build_u_kernel<<<DIMQ, 128>>>(qweights, U);

    // 10) product state Psi per row
    psi_kernel<<<ROWS, 256>>>(angles, psi);

    // 11) Phi = Psi @ U^T (complex)
    cgemm_nt_kernel<<<dim3(DIMQ / 64, ROWS / 64), 256>>>(psi, U, phi);

    // 12) z expectations
    zexp_kernel<<<ROWS, 256>>>(phi, zbuf);

    // 13) x2 = x1 + z @ qout_w^T + qout_b
    qout_add_kernel<<<(ROWS * DMODEL) / 256, 256>>>(x1, zbuf, qout_w, qout_b, x2);

    // 14) hbuf = gelu(x2 @ ffn_w1^T + ffn_b1)   [16384,2048]
    sgemm_kernel<true, 2><<<dim3(2048 / 128, ROWS / 128, 1), 256>>>(
        x2, ffn_w1, ffn_b1, hbuf, DMODEL, DMODEL, DMODEL, 2048,
        1, 0, 0, 0, 0, 0, 0, 1.f);

    // 15) ffnout = hbuf @ ffn_w2^T + ffn_b2
    sgemm_kernel<true, 1><<<dim3(DMODEL / 128, ROWS / 128, 1), 256>>>(
        hbuf, ffn_w2, ffn_b2, ffnout, 2048, 2048, 2048, DMODEL,
        1, 0, 0, 0, 0, 0, 0, 1.f);

    // 16) out = LN(x2 + ffnout; ln2)
    ln_kernel<<<ROWS / 8, 256>>>(x2, ffnout, ln2_g, ln2_b, out, ROWS);
}

// round 2
// speedup vs baseline: 2.3569x; 2.3569x over previous
#include <cuda_runtime.h>
#include <math.h>
#include <stdint.h>

// ---------------- problem constants ----------------
#define ROWS  16384        // B*S = 32*512
#define DMODEL 512
#define NHEADS 4
#define HDIM   128
#define SEQ    512
#define BATCH  32
#define NQ     8
#define DIMQ   256         // 2^8

// ---------------- scratch (static device memory; no allocs) ----------------
__device__ float  g_qkv    [ROWS * 1536];
__device__ float  g_scores [BATCH * NHEADS * SEQ * SEQ];
__device__ float  g_attnc  [ROWS * DMODEL];
__device__ float  g_attnproj[ROWS * DMODEL];
__device__ float  g_x1     [ROWS * DMODEL];
__device__ float  g_xnorm  [ROWS * DMODEL];
__device__ float  g_angles [ROWS * NQ];
__device__ float  g_uq     [512 * 512];       // real-ified circuit unitary
__device__ float  g_psis   [ROWS * 512];      // [Re(256) | Im(256)] per row
__device__ float  g_phis   [ROWS * 512];      // [Re(256) | Im(256)] per row
__device__ float  g_z      [ROWS * NQ];
__device__ float  g_x2     [ROWS * DMODEL];
__device__ float  g_hbuf   [ROWS * 2048];
__device__ float  g_ffnout [ROWS * DMODEL];

// ---------------- helpers ----------------
__device__ __forceinline__ float warp_sum(float v) {
    #pragma unroll
    for (int o = 16; o; o >>= 1) v += __shfl_xor_sync(0xffffffffu, v, o);
    return v;
}
__device__ __forceinline__ float warp_max(float v) {
    #pragma unroll
    for (int o = 16; o; o >>= 1) v = fmaxf(v, __shfl_xor_sync(0xffffffffu, v, o));
    return v;
}
__device__ __forceinline__ float gelu_exact(float x) {
    return 0.5f * x * (1.0f + erff(x * 0.7071067811865476f));
}
__device__ __forceinline__ uint32_t f2tf(float x) {
    uint32_t r;
    asm("cvt.rna.tf32.f32 %0, %1;" : "=r"(r) : "f"(x));
    return r;
}

// ---------------- tf32 tensor-core GEMM ----------------
// C[m,n] = alpha * sum_k A[m,k] * (TB ? B[n,k] : B[k,n])  (+bias, +gelu per EPI)
// Batched via blockIdx.z. Requires M%128==0, N%128==0, K%16==0, lds %4==0.
#define GS 20   // smem row stride (16 k + 4 pad) -> conflict-free fragment loads

template<bool TB, int EPI>
__global__ void __launch_bounds__(256, 2) gemm_tf32(
    const float* __restrict__ A, const float* __restrict__ B,
    const float* __restrict__ bias, float* __restrict__ C,
    int K, int lda, int ldb, int ldc,
    int nh, long sAb, long sAh, long sBb, long sBh, long sCb, long sCh,
    float alpha)
{
    int bz = blockIdx.z;
    int bb = bz / nh, hh = bz - bb * nh;
    A += bb * sAb + hh * sAh;
    B += bb * sBb + hh * sBh;
    C += bb * sCb + hh * sCh;

    __shared__ float As[2][128 * GS];
    __shared__ float Bs[2][128 * GS];

    const int tid  = threadIdx.x;
    const int warp = tid >> 5, lane = tid & 31;
    const int wm   = warp >> 1, wn = warp & 1;       // 4 x 2 warp grid
    const int g    = lane >> 2, tq = lane & 3;
    const int rowBase = blockIdx.y * 128;
    const int colBase = blockIdx.x * 128;

    // staging indices (NT path: [row][k] float4 copy)
    const int r0 = tid >> 2;            // 0..63 (+64 on it=1)
    const int c4 = (tid & 3) * 4;
    // NN B staging: kk row, n contiguous
    const int kkn = tid >> 5;           // 0..7 (+8 on it=1)
    const int n4  = (tid & 31) * 4;

    float4 ra[2], rb[2];
    float acc[2][8][4];
    #pragma unroll
    for (int i = 0; i < 2; i++)
        #pragma unroll
        for (int j = 0; j < 8; j++)
            #pragma unroll
            for (int q = 0; q < 4; q++) acc[i][j][q] = 0.f;

#define LDG_TILE(KT)                                                            \
    {                                                                           \
        _Pragma("unroll")                                                       \
        for (int it = 0; it < 2; it++) {                                        \
            int r = r0 + it * 64;                                               \
            ra[it] = *(const float4*)(A + (long)(rowBase + r) * lda + (KT) + c4);\
            if (TB) {                                                           \
                rb[it] = *(const float4*)(B + (long)(colBase + r) * ldb + (KT) + c4);\
            } else {                                                            \
                int kk = kkn + it * 8;                                          \
                rb[it] = *(const float4*)(B + (long)((KT) + kk) * ldb + colBase + n4);\
            }                                                                   \
        }                                                                       \
    }

#define STS_TILE(BUF)                                                           \
    {                                                                           \
        _Pragma("unroll")                                                       \
        for (int it = 0; it < 2; it++) {                                        \
            int r = r0 + it * 64;                                               \
            float4 va;                                                          \
            va.x = __uint_as_float(f2tf(ra[it].x));                             \
            va.y = __uint_as_float(f2tf(ra[it].y));                             \
            va.z = __uint_as_float(f2tf(ra[it].z));                             \
            va.w = __uint_as_float(f2tf(ra[it].w));                             \
            *(float4*)&As[BUF][r * GS + c4] = va;                               \
            if (TB) {                                                           \
                float4 vb;                                                      \
                vb.x = __uint_as_float(f2tf(rb[it].x));                         \
                vb.y = __uint_as_float(f2tf(rb[it].y));                         \
                vb.z = __uint_as_float(f2tf(rb[it].z));                         \
                vb.w = __uint_as_float(f2tf(rb[it].w));                         \
                *(float4*)&Bs[BUF][r * GS + c4] = vb;                           \
            } else {                                                            \
                int kk = kkn + it * 8;                                          \
                Bs[BUF][(n4 + 0) * GS + kk] = __uint_as_float(f2tf(rb[it].x));  \
                Bs[BUF][(n4 + 1) * GS + kk] = __uint_as_float(f2tf(rb[it].y));  \
                Bs[BUF][(n4 + 2) * GS + kk] = __uint_as_float(f2tf(rb[it].z));  \
                Bs[BUF][(n4 + 3) * GS + kk] = __uint_as_float(f2tf(rb[it].w));  \
            }                                                                   \
        }                                                                       \
    }

#define COMPUTE(BUF)                                                            \
    {                                                                           \
        const float* AsF = As[BUF];                                             \
        const float* BsF = Bs[BUF];                                             \
        _Pragma("unroll")                                                       \
        for (int k8 = 0; k8 < 16; k8 += 8) {                                    \
            uint32_t af[2][4], bfr[8][2];                                       \
            _Pragma("unroll")                                                   \
            for (int i = 0; i < 2; i++) {                                       \
                int m = wm * 32 + i * 16 + g;                                   \
                af[i][0] = __float_as_uint(AsF[m * GS + k8 + tq]);              \
                af[i][1] = __float_as_uint(AsF[(m + 8) * GS + k8 + tq]);        \
                af[i][2] = __float_as_uint(AsF[m * GS + k8 + tq + 4]);          \
                af[i][3] = __float_as_uint(AsF[(m + 8) * GS + k8 + tq + 4]);    \
            }                                                                   \
            _Pragma("unroll")                                                   \
            for (int j = 0; j < 8; j++) {                                       \
                int n = wn * 64 + j * 8 + g;                                    \
                bfr[j][0] = __float_as_uint(BsF[n * GS + k8 + tq]);             \
                bfr[j][1] = __float_as_uint(BsF[n * GS + k8 + tq + 4]);         \
            }                                                                   \
            _Pragma("unroll")                                                   \
            for (int i = 0; i < 2; i++)                                         \
                _Pragma("unroll")                                               \
                for (int j = 0; j < 8; j++)                                     \
                    asm volatile(                                               \
                        "mma.sync.aligned.m16n8k8.row.col.f32.tf32.tf32.f32 "   \
                        "{%0,%1,%2,%3}, {%4,%5,%6,%7}, {%8,%9}, {%0,%1,%2,%3};" \
                        : "+f"(acc[i][j][0]), "+f"(acc[i][j][1]),               \
                          "+f"(acc[i][j][2]), "+f"(acc[i][j][3])                \
                        : "r"(af[i][0]), "r"(af[i][1]),                         \
                          "r"(af[i][2]), "r"(af[i][3]),                         \
                          "r"(bfr[j][0]), "r"(bfr[j][1]));                      \
        }                                                                       \
    }

    LDG_TILE(0);
    STS_TILE(0);
    __syncthreads();
    int buf = 0;
    for (int kt = 16; kt <= K; kt += 16) {
        bool more = kt < K;
        if (more) LDG_TILE(kt);
        COMPUTE(buf);
        if (more) {
            STS_TILE(buf ^ 1);
            __syncthreads();
            buf ^= 1;
        }
    }

    // epilogue
    #pragma unroll
    for (int i = 0; i < 2; i++) {
        int row = rowBase + wm * 32 + i * 16 + g;
        #pragma unroll
        for (int j = 0; j < 8; j++) {
            int col = colBase + wn * 64 + j * 8 + tq * 2;
            float2 v0, v1;
            v0.x = acc[i][j][0] * alpha; v0.y = acc[i][j][1] * alpha;
            v1.x = acc[i][j][2] * alpha; v1.y = acc[i][j][3] * alpha;
            if (EPI >= 1) {
                float2 bv = *(const float2*)(bias + col);
                v0.x += bv.x; v0.y += bv.y; v1.x += bv.x; v1.y += bv.y;
            }
            if (EPI == 2) {
                v0.x = gelu_exact(v0.x); v0.y = gelu_exact(v0.y);
                v1.x = gelu_exact(v1.x); v1.y = gelu_exact(v1.y);
            }
            *(float2*)(C + (long)row * ldc + col) = v0;
            *(float2*)(C + (long)(row + 8) * ldc + col) = v1;
        }
    }
#undef LDG_TILE
#undef STS_TILE
#undef COMPUTE
}

// ---------------- LayerNorm: out = LN(A (+R)) * g + b, one warp per row ----------------
__global__ void ln_kernel(const float* __restrict__ A, const float* __restrict__ R,
                          const float* __restrict__ g, const float* __restrict__ b,
                          float* __restrict__ out, int nrows)
{
    int warp = (blockIdx.x * blockDim.x + threadIdx.x) >> 5;
    int lane = threadIdx.x & 31;
    if (warp >= nrows) return;
    const float* a = A + (long)warp * DMODEL;
    float4 v[4];
    float s = 0.f;
    #pragma unroll
    for (int t = 0; t < 4; t++) {
        int c = (t * 32 + lane) * 4;
        v[t] = *(const float4*)(a + c);
        if (R) {
            float4 r4 = *(const float4*)(R + (long)warp * DMODEL + c);
            v[t].x += r4.x; v[t].y += r4.y; v[t].z += r4.z; v[t].w += r4.w;
        }
        s += v[t].x + v[t].y + v[t].z + v[t].w;
    }
    s = warp_sum(s);
    float mean = s * (1.f / DMODEL);
    float vs = 0.f;
    #pragma unroll
    for (int t = 0; t < 4; t++) {
        float dx = v[t].x - mean, dy = v[t].y - mean, dz = v[t].z - mean, dw = v[t].w - mean;
        vs += dx * dx + dy * dy + dz * dz + dw * dw;
    }
    vs = warp_sum(vs);
    float rstd = rsqrtf(vs * (1.f / DMODEL) + 1e-5f);
    #pragma unroll
    for (int t = 0; t < 4; t++) {
        int c = (t * 32 + lane) * 4;
        float4 gv = *(const float4*)(g + c);
        float4 bv = *(const float4*)(b + c);
        float4 o;
        o.x = (v[t].x - mean) * rstd * gv.x + bv.x;
        o.y = (v[t].y - mean) * rstd * gv.y + bv.y;
        o.z = (v[t].z - mean) * rstd * gv.z + bv.z;
        o.w = (v[t].w - mean) * rstd * gv.w + bv.w;
        *(float4*)(out + (long)warp * DMODEL + c) = o;
    }
}

// ---------------- row softmax over 512, one warp per row ----------------
__global__ void softmax_kernel(float* __restrict__ S, int nrows)
{
    int warp = (blockIdx.x * blockDim.x + threadIdx.x) >> 5;
    int lane = threadIdx.x & 31;
    if (warp >= nrows) return;
    float* r = S + (long)warp * SEQ;
    float4 v[4];
    float m = -3.4e38f;
    #pragma unroll
    for (int t = 0; t < 4; t++) {
        v[t] = *(const float4*)(r + (t * 32 + lane) * 4);
        m = fmaxf(m, fmaxf(fmaxf(v[t].x, v[t].y), fmaxf(v[t].z, v[t].w)));
    }
    m = warp_max(m);
    float s = 0.f;
    #pragma unroll
    for (int t = 0; t < 4; t++) {
        v[t].x = __expf(v[t].x - m); v[t].y = __expf(v[t].y - m);
        v[t].z = __expf(v[t].z - m); v[t].w = __expf(v[t].w - m);
        s += v[t].x + v[t].y + v[t].z + v[t].w;
    }
    s = warp_sum(s);
    float inv = 1.f / s;
    #pragma unroll
    for (int t = 0; t < 4; t++) {
        v[t].x *= inv; v[t].y *= inv; v[t].z *= inv; v[t].w *= inv;
        *(float4*)(r + (t * 32 + lane) * 4) = v[t];
    }
}

// ---------------- angles = xnorm @ qin_w^T + qin_b, one warp per row ----------------
__global__ void qin_kernel(const float* __restrict__ xn, const float* __restrict__ w,
                           const float* __restrict__ b, float* __restrict__ ang)
{
    int warp = (blockIdx.x * blockDim.x + threadIdx.x) >> 5;
    int lane = threadIdx.x & 31;
    if (warp >= ROWS) return;
    const float* xr = xn + (long)warp * DMODEL;
    float4 xv[4];
    #pragma unroll
    for (int t = 0; t < 4; t++) xv[t] = *(const float4*)(xr + (t * 32 + lane) * 4);
    float myang = 0.f;
    #pragma unroll
    for (int o = 0; o < NQ; o++) {
        const float* wr = w + o * DMODEL;
        float p = 0.f;
        #pragma unroll
        for (int t = 0; t < 4; t++) {
            float4 wv = *(const float4*)(wr + (t * 32 + lane) * 4);
            p += xv[t].x * wv.x + xv[t].y * wv.y + xv[t].z * wv.z + xv[t].w * wv.w;
        }
        p = warp_sum(p);
        if (lane == o) myang = p + b[o];
    }
    if (lane < NQ) ang[(long)warp * NQ + lane] = myang;
}

// ---------------- build real-ified circuit unitary Bq (512x512) ----------------
// Bq[n][k]: n<256 -> RePhi_s rows: [ReU[s][c] | -ImU[s][c]]
//           n>=256 -> ImPhi_s rows: [ImU[s][c] |  ReU[s][c]]
__global__ void build_u_kernel(const float* __restrict__ qw, float* __restrict__ Bq)
{
    __shared__ float2 st[DIMQ];
    int col = blockIdx.x;
    int t = threadIdx.x;   // 128 threads
    st[t] = make_float2(0.f, 0.f);
    st[t + 128] = make_float2(0.f, 0.f);
    __syncthreads();
    if (t == 0) st[col] = make_float2(1.f, 0.f);
    __syncthreads();

    for (int l = 0; l < 4; l++) {
        for (int i = 0; i < NQ; i++) {
            float w0 = qw[(l * 2 + 0) * NQ + i];
            float w1 = qw[(l * 2 + 1) * NQ + i];
            float sn, cs, sn2, cs2;
            sincosf(0.5f * w0, &sn, &cs);
            sincosf(0.5f * w1, &sn2, &cs2);
            // M = RZ(w1) * RX(w0)
            float2 M00 = make_float2( cs * cs2, -cs * sn2);
            float2 M01 = make_float2(-sn * sn2, -sn * cs2);
            float2 M10 = make_float2( sn * sn2, -sn * cs2);
            float2 M11 = make_float2( cs * cs2,  cs * sn2);
            int bpos = 7 - i;
            int lowmask = (1 << bpos) - 1;
            int s0 = ((t >> bpos) << (bpos + 1)) | (t & lowmask);
            int s1 = s0 | (1 << bpos);
            float2 a0 = st[s0], a1 = st[s1];
            float2 n0, n1;
            n0.x = M00.x * a0.x - M00.y * a0.y + M01.x * a1.x - M01.y * a1.y;
            n0.y = M00.x * a0.y + M00.y * a0.x + M01.x * a1.y + M01.y * a1.x;
            n1.x = M10.x * a0.x - M10.y * a0.y + M11.x * a1.x - M11.y * a1.y;
            n1.y = M10.x * a0.y + M10.y * a0.x + M11.x * a1.y + M11.y * a1.x;
            st[s0] = n0; st[s1] = n1;
            __syncthreads();
        }
        for (int i = 0; i < NQ - 1; i++) {
            int cb = 7 - i, tb = 6 - i;
            if (t < 64) {
                int tlow = t & ((1 << tb) - 1);
                int s0 = ((t >> tb) << (tb + 2)) | (1 << cb) | tlow;
                int s1 = s0 | (1 << tb);
                float2 tmp = st[s0]; st[s0] = st[s1]; st[s1] = tmp;
            }
            __syncthreads();
        }
    }
    #pragma unroll
    for (int h = 0; h < 2; h++) {
        int s = t + h * 128;
        float2 u = st[s];              // U[s][col]
        Bq[(long)s * 512 + col]              =  u.x;   // ReU
        Bq[(long)s * 512 + 256 + col]        = -u.y;   // -ImU
        Bq[(long)(256 + s) * 512 + col]      =  u.y;   // ImU
        Bq[(long)(256 + s) * 512 + 256 + col] = u.x;   // ReU
    }
}

// ---------------- product state Psi (split re/im), one block (256 thr) per row ----------------
__global__ void psi_kernel(const float* __restrict__ ang, float* __restrict__ psis)
{
    __shared__ float2 sq[NQ][2];
    int row = blockIdx.x;
    int s = threadIdx.x;
    if (s < NQ) {
        float a = ang[(long)row * NQ + s];
        float sn, cs;
        sincosf(0.5f * a, &sn, &cs);
        sq[s][0] = make_float2(cs * cs, -cs * sn);
        sq[s][1] = make_float2(sn * sn, -sn * cs);
    }
    __syncthreads();
    float2 amp = make_float2(1.f, 0.f);
    #pragma unroll
    for (int i = 0; i < NQ; i++) {
        float2 q = sq[i][(s >> (7 - i)) & 1];
        float2 na;
        na.x = amp.x * q.x - amp.y * q.y;
        na.y = amp.x * q.y + amp.y * q.x;
        amp = na;
    }
    psis[(long)row * 512 + s] = amp.x;
    psis[(long)row * 512 + 256 + s] = amp.y;
}

// ---------------- z_i = sum_s sign_i(s) |phi_s|^2, one block per row ----------------
__global__ void zexp_kernel(const float* __restrict__ Phis, float* __restrict__ Z)
{
    __shared__ float partial[8][9];
    int row = blockIdx.x;
    int s = threadIdx.x;
    float re = Phis[(long)row * 512 + s];
    float im = Phis[(long)row * 512 + 256 + s];
    float p = re * re + im * im;
    int lane = s & 31, wid = s >> 5;
    float vals[NQ];
    #pragma unroll
    for (int i = 0; i < NQ; i++)
        vals[i] = ((s >> (7 - i)) & 1) ? -p : p;
    #pragma unroll
    for (int o = 16; o; o >>= 1)
        #pragma unroll
        for (int i = 0; i < NQ; i++)
            vals[i] += __shfl_xor_sync(0xffffffffu, vals[i], o);
    if (lane == 0)
        #pragma unroll
        for (int i = 0; i < NQ; i++) partial[wid][i] = vals[i];
    __syncthreads();
    if (s < NQ) {
        float acc = 0.f;
        #pragma unroll
        for (int w = 0; w < 8; w++) acc += partial[w][s];
        Z[(long)row * NQ + s] = acc;
    }
}

// ---------------- x2 = x1 + z @ qout_w^T + qout_b ----------------
__global__ void qout_add_kernel(const float* __restrict__ x1, const float* __restrict__ z,
                                const float* __restrict__ w, const float* __restrict__ b,
                                float* __restrict__ out)
{
    long gidx = (long)blockIdx.x * 256 + threadIdx.x;
    int row = (int)(gidx >> 9);
    int col = (int)(gidx & 511);
    const float* zr = z + (long)row * NQ;
    float4 w0 = *(const float4*)(w + (long)col * NQ);
    float4 w1 = *(const float4*)(w + (long)col * NQ + 4);
    float acc = b[col];
    acc += zr[0] * w0.x + zr[1] * w0.y + zr[2] * w0.z + zr[3] * w0.w;
    acc += zr[4] * w1.x + zr[5] * w1.y + zr[6] * w1.z + zr[7] * w1.w;
    out[gidx] = x1[gidx] + acc;
}

// ---------------- launch ----------------
extern "C" void kernel_launch(void* const* d_in, const int* in_sizes, int n_in,
                              void* d_out, int out_size)
{
    const float* x          = (const float*)d_in[0];
    const float* attn_in_w  = (const float*)d_in[1];
    const float* attn_in_b  = (const float*)d_in[2];
    const float* attn_out_w = (const float*)d_in[3];
    const float* attn_out_b = (const float*)d_in[4];
    const float* ln1_g      = (const float*)d_in[5];
    const float* ln1_b      = (const float*)d_in[6];
    const float* ln2_g      = (const float*)d_in[7];
    const float* ln2_b      = (const float*)d_in[8];
    const float* ln3_g      = (const float*)d_in[9];
    const float* ln3_b      = (const float*)d_in[10];
    const float* qin_w      = (const float*)d_in[11];
    const float* qin_b      = (const float*)d_in[12];
    const float* qweights   = (const float*)d_in[13];
    const float* qout_w     = (const float*)d_in[14];
    const float* qout_b     = (const float*)d_in[15];
    const float* ffn_w1     = (const float*)d_in[16];
    const float* ffn_b1     = (const float*)d_in[17];
    const float* ffn_w2     = (const float*)d_in[18];
    const float* ffn_b2     = (const float*)d_in[19];
    float* out = (float*)d_out;

    float *qkv, *scores, *attnc, *attnproj, *x1, *xnorm, *angles, *uq, *psis, *phis,
          *zbuf, *x2, *hbuf, *ffnout;
    cudaGetSymbolAddress((void**)&qkv,      g_qkv);
    cudaGetSymbolAddress((void**)&scores,   g_scores);
    cudaGetSymbolAddress((void**)&attnc,    g_attnc);
    cudaGetSymbolAddress((void**)&attnproj, g_attnproj);
    cudaGetSymbolAddress((void**)&x1,       g_x1);
    cudaGetSymbolAddress((void**)&xnorm,    g_xnorm);
    cudaGetSymbolAddress((void**)&angles,   g_angles);
    cudaGetSymbolAddress((void**)&uq,       g_uq);
    cudaGetSymbolAddress((void**)&psis,     g_psis);
    cudaGetSymbolAddress((void**)&phis,     g_phis);
    cudaGetSymbolAddress((void**)&zbuf,     g_z);
    cudaGetSymbolAddress((void**)&x2,       g_x2);
    cudaGetSymbolAddress((void**)&hbuf,     g_hbuf);
    cudaGetSymbolAddress((void**)&ffnout,   g_ffnout);

    const float inv_sqrt_hd = 0.08838834764831845f;   // 1/sqrt(128)

    // 1) qkv = x @ in_w^T + in_b          [16384,1536]
    gemm_tf32<true, 1><<<dim3(1536 / 128, ROWS / 128, 1), 256>>>(
        x, attn_in_w, attn_in_b, qkv, DMODEL, DMODEL, DMODEL, 1536,
        1, 0, 0, 0, 0, 0, 0, 1.f);

    // 2) scores[bh] = Q K^T / sqrt(hd)
    gemm_tf32<true, 0><<<dim3(SEQ / 128, SEQ / 128, BATCH * NHEADS), 256>>>(
        qkv, qkv + 512, nullptr, scores, HDIM, 1536, 1536, SEQ,
        NHEADS,
        (long)SEQ * 1536, 128,
        (long)SEQ * 1536, 128,
        (long)NHEADS * SEQ * SEQ, (long)SEQ * SEQ,
        inv_sqrt_hd);

    // 3) softmax rows
    softmax_kernel<<<(BATCH * NHEADS * SEQ) / 8, 256>>>(scores, BATCH * NHEADS * SEQ);

    // 4) attnc[bh] = P V (concat layout), NN form
    gemm_tf32<false, 0><<<dim3(HDIM / 128, SEQ / 128, BATCH * NHEADS), 256>>>(
        scores, qkv + 1024, nullptr, attnc, SEQ, SEQ, 1536, DMODEL,
        NHEADS,
        (long)NHEADS * SEQ * SEQ, (long)SEQ * SEQ,
        (long)SEQ * 1536, 128,
        (long)SEQ * DMODEL, 128,
        1.f);

    // 5) attnproj = attnc @ out_w^T + out_b
    gemm_tf32<true, 1><<<dim3(DMODEL / 128, ROWS / 128, 1), 256>>>(
        attnc, attn_out_w, attn_out_b, attnproj, DMODEL, DMODEL, DMODEL, DMODEL,
        1, 0, 0, 0, 0, 0, 0, 1.f);

    // 6) x1 = LN(x + attnproj; ln1)
    ln_kernel<<<ROWS / 8, 256>>>(x, attnproj, ln1_g, ln1_b, x1, ROWS);

    // 7) xnorm = LN(x1; ln3)
    ln_kernel<<<ROWS / 8, 256>>>(x1, nullptr, ln3_g, ln3_b, xnorm, ROWS);

    // 8) angles = xnorm @ qin_w^T + qin_b (fp32)
    qin_kernel<<<ROWS / 8, 256>>>(xnorm, qin_w, qin_b, angles);

    // 9) real-ified circuit unitary (depends only on qweights)
    build_u_kernel<<<DIMQ, 128>>>(qweights, uq);

    // 10) product state Psi per row (split re/im)
    psi_kernel<<<ROWS, 256>>>(angles, psis);

    // 11) Phi = Psi @ U^T as a real tf32 GEMM [16384,512,512]
    gemm_tf32<true, 0><<<dim3(512 / 128, ROWS / 128, 1), 256>>>(
        psis, uq, nullptr, phis, 512, 512, 512, 512,
        1, 0, 0, 0, 0, 0, 0, 1.f);

    // 12) z expectations
    zexp_kernel<<<ROWS, 256>>>(phis, zbuf);

    // 13) x2 = x1 + z @ qout_w^T + qout_b
    qout_add_kernel<<<(ROWS * DMODEL) / 256, 256>>>(x1, zbuf, qout_w, qout_b, x2);

    // 14) hbuf = gelu(x2 @ ffn_w1^T + ffn_b1)   [16384,2048]
    gemm_tf32<true, 2><<<dim3(2048 / 128, ROWS / 128, 1), 256>>>(
        x2, ffn_w1, ffn_b1, hbuf, DMODEL, DMODEL, DMODEL, 2048,
        1, 0, 0, 0, 0, 0, 0, 1.f);

    // 15) ffnout = hbuf @ ffn_w2^T + ffn_b2
    gemm_tf32<true, 1><<<dim3(DMODEL / 128, ROWS / 128, 1), 256>>>(
        hbuf, ffn_w2, ffn_b2, ffnout, 2048, 2048, 2048, DMODEL,
        1, 0, 0, 0, 0, 0, 0, 1.f);

    // 16) out = LN(x2 + ffnout; ln2)
    ln_kernel<<<ROWS / 8, 256>>>(x2, ffnout, ln2_g, ln2_b, out, ROWS);
}

// round 3
// speedup vs baseline: 2.5659x; 1.0887x over previous
#include <cuda_runtime.h>
#include <math.h>
#include <stdint.h>

// ---------------- problem constants ----------------
#define ROWS  16384        // B*S = 32*512
#define DMODEL 512
#define NHEADS 4
#define HDIM   128
#define SEQ    512
#define BATCH  32
#define NQ     8
#define DIMQ   256         // 2^8
#define STAGES 3

// ---------------- scratch (static device memory; no allocs) ----------------
__device__ float  g_qkv    [ROWS * 1536];
__device__ float  g_scores [BATCH * NHEADS * SEQ * SEQ];
__device__ float  g_attnc  [ROWS * DMODEL];
__device__ float  g_attnproj[ROWS * DMODEL];
__device__ float  g_x1     [ROWS * DMODEL];
__device__ float  g_xnorm  [ROWS * DMODEL];
__device__ float  g_angles [ROWS * NQ];
__device__ float  g_uq     [512 * 512];       // real-ified circuit unitary
__device__ float  g_psis   [ROWS * 512];      // [Re(256) | Im(256)] per row
__device__ float  g_phis   [ROWS * 512];      // [Re(256) | Im(256)] per row
__device__ float  g_z      [ROWS * NQ];
__device__ float  g_x2     [ROWS * DMODEL];
__device__ float  g_hbuf   [ROWS * 2048];
__device__ float  g_ffnout [ROWS * DMODEL];

// ---------------- helpers ----------------
__device__ __forceinline__ float warp_sum(float v) {
    #pragma unroll
    for (int o = 16; o; o >>= 1) v += __shfl_xor_sync(0xffffffffu, v, o);
    return v;
}
__device__ __forceinline__ float warp_max(float v) {
    #pragma unroll
    for (int o = 16; o; o >>= 1) v = fmaxf(v, __shfl_xor_sync(0xffffffffu, v, o));
    return v;
}
__device__ __forceinline__ float gelu_exact(float x) {
    return 0.5f * x * (1.0f + erff(x * 0.7071067811865476f));
}

// ---------------- tf32 tensor-core GEMM (cp.async 3-stage, 64x64 warp tiles) ----
// C[m,n] = alpha * sum_k A[m,k] * (TB ? B[n,k] : B[k,n])  (+bias, +gelu per EPI)
// Batched via blockIdx.z. Requires M%BM==0, N%BN==0, K%16==0, ld%4==0.
// 256 threads = 8 warps in a (BM/64) x (BN/64) grid, each owning 64x64.
// tf32 operands are raw f32 bits (HW uses top mantissa bits).

template<int BM, int BN, bool TB, int EPI>
__global__ void __launch_bounds__(256) gemm_tf32(
    const float* __restrict__ A, const float* __restrict__ B,
    const float* __restrict__ bias, float* __restrict__ C,
    int K, int lda, int ldb, int ldc,
    int nh, long sAb, long sAh, long sBb, long sBh, long sCb, long sCh,
    float alpha)
{
    static_assert((BM / 64) * (BN / 64) == 8, "8 warps");
    static_assert(TB || BN == 128, "NN path assumes BN==128");
    constexpr int WGN     = BN / 64;
    constexpr int ASTAGE  = BM * 20;                       // floats
    constexpr int BSTAGE  = TB ? BN * 20 : 16 * 136;       // floats

    extern __shared__ float sm[];
    float* AsAll = sm;
    float* BsAll = sm + STAGES * ASTAGE;

    int bz = blockIdx.z;
    int bb = bz / nh, hh = bz - bb * nh;
    A += bb * sAb + hh * sAh;
    B += bb * sBb + hh * sBh;
    C += bb * sCb + hh * sCh;

    const int tid  = threadIdx.x;
    const int warp = tid >> 5, lane = tid & 31;
    const int wm = warp / WGN, wn = warp % WGN;
    const int g  = lane >> 2, tq = lane & 3;
    const long rowBase = (long)blockIdx.y * BM;
    const long colBase = (long)blockIdx.x * BN;

    float acc[4][8][4];
    #pragma unroll
    for (int i = 0; i < 4; i++)
        #pragma unroll
        for (int j = 0; j < 8; j++)
            #pragma unroll
            for (int q = 0; q < 4; q++) acc[i][j][q] = 0.f;

#define CP16(DSTP, SRCP)                                                        \
    {                                                                           \
        uint32_t _d = (uint32_t)__cvta_generic_to_shared(DSTP);                 \
        asm volatile("cp.async.cg.shared.global [%0], [%1], 16;\n"              \
                     :: "r"(_d), "l"(SRCP));                                    \
    }

#define ISSUE(STG, KT)                                                          \
    {                                                                           \
        float* Asst = AsAll + (STG) * ASTAGE;                                   \
        float* Bsst = BsAll + (STG) * BSTAGE;                                   \
        _Pragma("unroll")                                                       \
        for (int it = 0; it < BM / 64; it++) {                                  \
            int idx = tid + it * 256;                                           \
            int r = idx >> 2, c4 = (idx & 3) * 4;                               \
            CP16(Asst + r * 20 + c4, A + (rowBase + r) * lda + (KT) + c4);      \
        }                                                                       \
        if (TB) {                                                               \
            _Pragma("unroll")                                                   \
            for (int it = 0; it < BN / 64; it++) {                              \
                int idx = tid + it * 256;                                       \
                int r = idx >> 2, c4 = (idx & 3) * 4;                           \
                CP16(Bsst + r * 20 + c4, B + (colBase + r) * ldb + (KT) + c4);  \
            }                                                                   \
        } else {                                                                \
            _Pragma("unroll")                                                   \
            for (int it = 0; it < 2; it++) {                                    \
                int idx = tid + it * 256;                                       \
                int kk = idx >> 5, n4 = (idx & 31) * 4;                         \
                CP16(Bsst + kk * 136 + n4,                                      \
                     B + (long)((KT) + kk) * ldb + colBase + n4);               \
            }                                                                   \
        }                                                                       \
        asm volatile("cp.async.commit_group;\n" ::: "memory");                  \
    }

#define COMPUTE(STG)                                                            \
    {                                                                           \
        const float* AsF = AsAll + (STG) * ASTAGE;                              \
        const float* BsF = BsAll + (STG) * BSTAGE;                              \
        _Pragma("unroll")                                                       \
        for (int k8 = 0; k8 < 16; k8 += 8) {                                    \
            uint32_t af[4][4], bf[8][2];                                        \
            _Pragma("unroll")                                                   \
            for (int i = 0; i < 4; i++) {                                       \
                int m = wm * 64 + i * 16 + g;                                   \
                af[i][0] = __float_as_uint(AsF[m * 20 + k8 + tq]);              \
                af[i][1] = __float_as_uint(AsF[(m + 8) * 20 + k8 + tq]);        \
                af[i][2] = __float_as_uint(AsF[m * 20 + k8 + tq + 4]);          \
                af[i][3] = __float_as_uint(AsF[(m + 8) * 20 + k8 + tq + 4]);    \
            }                                                                   \
            _Pragma("unroll")                                                   \
            for (int j = 0; j < 8; j++) {                                       \
                int n = wn * 64 + j * 8 + g;                                    \
                if (TB) {                                                       \
                    bf[j][0] = __float_as_uint(BsF[n * 20 + k8 + tq]);          \
                    bf[j][1] = __float_as_uint(BsF[n * 20 + k8 + tq + 4]);      \
                } else {                                                        \
                    bf[j][0] = __float_as_uint(BsF[(k8 + tq) * 136 + n]);       \
                    bf[j][1] = __float_as_uint(BsF[(k8 + tq + 4) * 136 + n]);   \
                }                                                               \
            }                                                                   \
            _Pragma("unroll")                                                   \
            for (int i = 0; i < 4; i++)                                         \
                _Pragma("unroll")                                               \
                for (int j = 0; j < 8; j++)                                     \
                    asm volatile(                                               \
                        "mma.sync.aligned.m16n8k8.row.col.f32.tf32.tf32.f32 "   \
                        "{%0,%1,%2,%3}, {%4,%5,%6,%7}, {%8,%9}, {%0,%1,%2,%3};" \
                        : "+f"(acc[i][j][0]), "+f"(acc[i][j][1]),               \
                          "+f"(acc[i][j][2]), "+f"(acc[i][j][3])                \
                        : "r"(af[i][0]), "r"(af[i][1]),                         \
                          "r"(af[i][2]), "r"(af[i][3]),                         \
                          "r"(bf[j][0]), "r"(bf[j][1]));                        \
        }                                                                       \
    }

    const int NK = K >> 4;
    ISSUE(0, 0);
    ISSUE(1, 16);

    for (int t = 0; t < NK; t++) {
        if (t == NK - 1) {
            asm volatile("cp.async.wait_group 0;\n" ::: "memory");
        } else {
            asm volatile("cp.async.wait_group 1;\n" ::: "memory");
        }
        __syncthreads();
        int stg = t % STAGES;
        COMPUTE(stg);
        __syncthreads();
        if (t + 2 < NK) {
            int nst = (t + 2) % STAGES;
            ISSUE(nst, (t + 2) * 16);
        }
    }

    // epilogue
    #pragma unroll
    for (int i = 0; i < 4; i++) {
        long row = rowBase + wm * 64 + i * 16 + g;
        #pragma unroll
        for (int j = 0; j < 8; j++) {
            long col = colBase + wn * 64 + j * 8 + tq * 2;
            float2 v0, v1;
            v0.x = acc[i][j][0] * alpha; v0.y = acc[i][j][1] * alpha;
            v1.x = acc[i][j][2] * alpha; v1.y = acc[i][j][3] * alpha;
            if (EPI >= 1) {
                float2 bv = *(const float2*)(bias + col);
                v0.x += bv.x; v0.y += bv.y; v1.x += bv.x; v1.y += bv.y;
            }
            if (EPI == 2) {
                v0.x = gelu_exact(v0.x); v0.y = gelu_exact(v0.y);
                v1.x = gelu_exact(v1.x); v1.y = gelu_exact(v1.y);
            }
            *(float2*)(C + row * ldc + col) = v0;
            *(float2*)(C + (row + 8) * ldc + col) = v1;
        }
    }
#undef CP16
#undef ISSUE
#undef COMPUTE
}

// ---------------- LayerNorm: out = LN(A (+R)) * g + b, one warp per row ----------------
__global__ void ln_kernel(const float* __restrict__ A, const float* __restrict__ R,
                          const float* __restrict__ g, const float* __restrict__ b,
                          float* __restrict__ out, int nrows)
{
    int warp = (blockIdx.x * blockDim.x + threadIdx.x) >> 5;
    int lane = threadIdx.x & 31;
    if (warp >= nrows) return;
    const float* a = A + (long)warp * DMODEL;
    float4 v[4];
    float s = 0.f;
    #pragma unroll
    for (int t = 0; t < 4; t++) {
        int c = (t * 32 + lane) * 4;
        v[t] = *(const float4*)(a + c);
        if (R) {
            float4 r4 = *(const float4*)(R + (long)warp * DMODEL + c);
            v[t].x += r4.x; v[t].y += r4.y; v[t].z += r4.z; v[t].w += r4.w;
        }
        s += v[t].x + v[t].y + v[t].z + v[t].w;
    }
    s = warp_sum(s);
    float mean = s * (1.f / DMODEL);
    float vs = 0.f;
    #pragma unroll
    for (int t = 0; t < 4; t++) {
        float dx = v[t].x - mean, dy = v[t].y - mean, dz = v[t].z - mean, dw = v[t].w - mean;
        vs += dx * dx + dy * dy + dz * dz + dw * dw;
    }
    vs = warp_sum(vs);
    float rstd = rsqrtf(vs * (1.f / DMODEL) + 1e-5f);
    #pragma unroll
    for (int t = 0; t < 4; t++) {
        int c = (t * 32 + lane) * 4;
        float4 gv = *(const float4*)(g + c);
        float4 bv = *(const float4*)(b + c);
        float4 o;
        o.x = (v[t].x - mean) * rstd * gv.x + bv.x;
        o.y = (v[t].y - mean) * rstd * gv.y + bv.y;
        o.z = (v[t].z - mean) * rstd * gv.z + bv.z;
        o.w = (v[t].w - mean) * rstd * gv.w + bv.w;
        *(float4*)(out + (long)warp * DMODEL + c) = o;
    }
}

// ---------------- row softmax over 512, one warp per row ----------------
__global__ void softmax_kernel(float* __restrict__ S, int nrows)
{
    int warp = (blockIdx.x * blockDim.x + threadIdx.x) >> 5;
    int lane = threadIdx.x & 31;
    if (warp >= nrows) return;
    float* r = S + (long)warp * SEQ;
    float4 v[4];
    float m = -3.4e38f;
    #pragma unroll
    for (int t = 0; t < 4; t++) {
        v[t] = *(const float4*)(r + (t * 32 + lane) * 4);
        m = fmaxf(m, fmaxf(fmaxf(v[t].x, v[t].y), fmaxf(v[t].z, v[t].w)));
    }
    m = warp_max(m);
    float s = 0.f;
    #pragma unroll
    for (int t = 0; t < 4; t++) {
        v[t].x = __expf(v[t].x - m); v[t].y = __expf(v[t].y - m);
        v[t].z = __expf(v[t].z - m); v[t].w = __expf(v[t].w - m);
        s += v[t].x + v[t].y + v[t].z + v[t].w;
    }
    s = warp_sum(s);
    float inv = 1.f / s;
    #pragma unroll
    for (int t = 0; t < 4; t++) {
        v[t].x *= inv; v[t].y *= inv; v[t].z *= inv; v[t].w *= inv;
        *(float4*)(r + (t * 32 + lane) * 4) = v[t];
    }
}

// ---------------- angles = xnorm @ qin_w^T + qin_b, one warp per row ----------------
__global__ void qin_kernel(const float* __restrict__ xn, const float* __restrict__ w,
                           const float* __restrict__ b, float* __restrict__ ang)
{
    int warp = (blockIdx.x * blockDim.x + threadIdx.x) >> 5;
    int lane = threadIdx.x & 31;
    if (warp >= ROWS) return;
    const float* xr = xn + (long)warp * DMODEL;
    float4 xv[4];
    #pragma unroll
    for (int t = 0; t < 4; t++) xv[t] = *(const float4*)(xr + (t * 32 + lane) * 4);
    float myang = 0.f;
    #pragma unroll
    for (int o = 0; o < NQ; o++) {
        const float* wr = w + o * DMODEL;
        float p = 0.f;
        #pragma unroll
        for (int t = 0; t < 4; t++) {
            float4 wv = *(const float4*)(wr + (t * 32 + lane) * 4);
            p += xv[t].x * wv.x + xv[t].y * wv.y + xv[t].z * wv.z + xv[t].w * wv.w;
        }
        p = warp_sum(p);
        if (lane == o) myang = p + b[o];
    }
    if (lane < NQ) ang[(long)warp * NQ + lane] = myang;
}

// ---------------- build real-ified circuit unitary Bq (512x512) ----------------
__global__ void build_u_kernel(const float* __restrict__ qw, float* __restrict__ Bq)
{
    __shared__ float2 st[DIMQ];
    int col = blockIdx.x;
    int t = threadIdx.x;   // 128 threads
    st[t] = make_float2(0.f, 0.f);
    st[t + 128] = make_float2(0.f, 0.f);
    __syncthreads();
    if (t == 0) st[col] = make_float2(1.f, 0.f);
    __syncthreads();

    for (int l = 0; l < 4; l++) {
        for (int i = 0; i < NQ; i++) {
            float w0 = qw[(l * 2 + 0) * NQ + i];
            float w1 = qw[(l * 2 + 1) * NQ + i];
            float sn, cs, sn2, cs2;
            sincosf(0.5f * w0, &sn, &cs);
            sincosf(0.5f * w1, &sn2, &cs2);
            float2 M00 = make_float2( cs * cs2, -cs * sn2);
            float2 M01 = make_float2(-sn * sn2, -sn * cs2);
            float2 M10 = make_float2( sn * sn2, -sn * cs2);
            float2 M11 = make_float2( cs * cs2,  cs * sn2);
            int bpos = 7 - i;
            int lowmask = (1 << bpos) - 1;
            int s0 = ((t >> bpos) << (bpos + 1)) | (t & lowmask);
            int s1 = s0 | (1 << bpos);
            float2 a0 = st[s0], a1 = st[s1];
            float2 n0, n1;
            n0.x = M00.x * a0.x - M00.y * a0.y + M01.x * a1.x - M01.y * a1.y;
            n0.y = M00.x * a0.y + M00.y * a0.x + M01.x * a1.y + M01.y * a1.x;
            n1.x = M10.x * a0.x - M10.y * a0.y + M11.x * a1.x - M11.y * a1.y;
            n1.y = M10.x * a0.y + M10.y * a0.x + M11.x * a1.y + M11.y * a1.x;
            st[s0] = n0; st[s1] = n1;
            __syncthreads();
        }
        for (int i = 0; i < NQ - 1; i++) {
            int cb = 7 - i, tb = 6 - i;
            if (t < 64) {
                int tlow = t & ((1 << tb) - 1);
                int s0 = ((t >> tb) << (tb + 2)) | (1 << cb) | tlow;
                int s1 = s0 | (1 << tb);
                float2 tmp = st[s0]; st[s0] = st[s1]; st[s1] = tmp;
            }
            __syncthreads();
        }
    }
    #pragma unroll
    for (int h = 0; h < 2; h++) {
        int s = t + h * 128;
        float2 u = st[s];              // U[s][col]
        Bq[(long)s * 512 + col]               =  u.x;   // ReU
        Bq[(long)s * 512 + 256 + col]         = -u.y;   // -ImU
        Bq[(long)(256 + s) * 512 + col]       =  u.y;   // ImU
        Bq[(long)(256 + s) * 512 + 256 + col] =  u.x;   // ReU
    }
}

// ---------------- product state Psi (split re/im), one block (256 thr) per row ----------------
__global__ void psi_kernel(const float* __restrict__ ang, float* __restrict__ psis)
{
    __shared__ float2 sq[NQ][2];
    int row = blockIdx.x;
    int s = threadIdx.x;
    if (s < NQ) {
        float a = ang[(long)row * NQ + s];
        float sn, cs;
        sincosf(0.5f * a, &sn, &cs);
        sq[s][0] = make_float2(cs * cs, -cs * sn);
        sq[s][1] = make_float2(sn * sn, -sn * cs);
    }
    __syncthreads();
    float2 amp = make_float2(1.f, 0.f);
    #pragma unroll
    for (int i = 0; i < NQ; i++) {
        float2 q = sq[i][(s >> (7 - i)) & 1];
        float2 na;
        na.x = amp.x * q.x - amp.y * q.y;
        na.y = amp.x * q.y + amp.y * q.x;
        amp = na;
    }
    psis[(long)row * 512 + s] = amp.x;
    psis[(long)row * 512 + 256 + s] = amp.y;
}

// ---------------- z_i = sum_s sign_i(s) |phi_s|^2, one block per row ----------------
__global__ void zexp_kernel(const float* __restrict__ Phis, float* __restrict__ Z)
{
    __shared__ float partial[8][9];
    int row = blockIdx.x;
    int s = threadIdx.x;
    float re = Phis[(long)row * 512 + s];
    float im = Phis[(long)row * 512 + 256 + s];
    float p = re * re + im * im;
    int lane = s & 31, wid = s >> 5;
    float vals[NQ];
    #pragma unroll
    for (int i = 0; i < NQ; i++)
        vals[i] = ((s >> (7 - i)) & 1) ? -p : p;
    #pragma unroll
    for (int o = 16; o; o >>= 1)
        #pragma unroll
        for (int i = 0; i < NQ; i++)
            vals[i] += __shfl_xor_sync(0xffffffffu, vals[i], o);
    if (lane == 0)
        #pragma unroll
        for (int i = 0; i < NQ; i++) partial[wid][i] = vals[i];
    __syncthreads();
    if (s < NQ) {
        float acc = 0.f;
        #pragma unroll
        for (int w = 0; w < 8; w++) acc += partial[w][s];
        Z[(long)row * NQ + s] = acc;
    }
}

// ---------------- x2 = x1 + z @ qout_w^T + qout_b ----------------
__global__ void qout_add_kernel(const float* __restrict__ x1, const float* __restrict__ z,
                                const float* __restrict__ w, const float* __restrict__ b,
                                float* __restrict__ out)
{
    long gidx = (long)blockIdx.x * 256 + threadIdx.x;
    int row = (int)(gidx >> 9);
    int col = (int)(gidx & 511);
    const float* zr = z + (long)row * NQ;
    float4 w0 = *(const float4*)(w + (long)col * NQ);
    float4 w1 = *(const float4*)(w + (long)col * NQ + 4);
    float acc = b[col];
    acc += zr[0] * w0.x + zr[1] * w0.y + zr[2] * w0.z + zr[3] * w0.w;
    acc += zr[4] * w1.x + zr[5] * w1.y + zr[6] * w1.z + zr[7] * w1.w;
    out[gidx] = x1[gidx] + acc;
}

// ---------------- launch ----------------
extern "C" void kernel_launch(void* const* d_in, const int* in_sizes, int n_in,
                              void* d_out, int out_size)
{
    const float* x          = (const float*)d_in[0];
    const float* attn_in_w  = (const float*)d_in[1];
    const float* attn_in_b  = (const float*)d_in[2];
    const float* attn_out_w = (const float*)d_in[3];
    const float* attn_out_b = (const float*)d_in[4];
    const float* ln1_g      = (const float*)d_in[5];
    const float* ln1_b      = (const float*)d_in[6];
    const float* ln2_g      = (const float*)d_in[7];
    const float* ln2_b      = (const float*)d_in[8];
    const float* ln3_g      = (const float*)d_in[9];
    const float* ln3_b      = (const float*)d_in[10];
    const float* qin_w      = (const float*)d_in[11];
    const float* qin_b      = (const float*)d_in[12];
    const float* qweights   = (const float*)d_in[13];
    const float* qout_w     = (const float*)d_in[14];
    const float* qout_b     = (const float*)d_in[15];
    const float* ffn_w1     = (const float*)d_in[16];
    const float* ffn_b1     = (const float*)d_in[17];
    const float* ffn_w2     = (const float*)d_in[18];
    const float* ffn_b2     = (const float*)d_in[19];
    float* out = (float*)d_out;

    float *qkv, *scores, *attnc, *attnproj, *x1, *xnorm, *angles, *uq, *psis, *phis,
          *zbuf, *x2, *hbuf, *ffnout;
    cudaGetSymbolAddress((void**)&qkv,      g_qkv);
    cudaGetSymbolAddress((void**)&scores,   g_scores);
    cudaGetSymbolAddress((void**)&attnc,    g_attnc);
    cudaGetSymbolAddress((void**)&attnproj, g_attnproj);
    cudaGetSymbolAddress((void**)&x1,       g_x1);
    cudaGetSymbolAddress((void**)&xnorm,    g_xnorm);
    cudaGetSymbolAddress((void**)&angles,   g_angles);
    cudaGetSymbolAddress((void**)&uq,       g_uq);
    cudaGetSymbolAddress((void**)&psis,     g_psis);
    cudaGetSymbolAddress((void**)&phis,     g_phis);
    cudaGetSymbolAddress((void**)&zbuf,     g_z);
    cudaGetSymbolAddress((void**)&x2,       g_x2);
    cudaGetSymbolAddress((void**)&hbuf,     g_hbuf);
    cudaGetSymbolAddress((void**)&ffnout,   g_ffnout);

    const float inv_sqrt_hd = 0.08838834764831845f;   // 1/sqrt(128)

    // smem sizes per variant
    const int SMEM_NT = STAGES * (128 * 20 + 256 * 20) * 4;   // 92160
    const int SMEM_NN = STAGES * (256 * 20 + 16 * 136) * 4;   // 87552

    cudaFuncSetAttribute(gemm_tf32<128, 256, true, 0>,
                         cudaFuncAttributeMaxDynamicSharedMemorySize, SMEM_NT);
    cudaFuncSetAttribute(gemm_tf32<128, 256, true, 1>,
                         cudaFuncAttributeMaxDynamicSharedMemorySize, SMEM_NT);
    cudaFuncSetAttribute(gemm_tf32<128, 256, true, 2>,
                         cudaFuncAttributeMaxDynamicSharedMemorySize, SMEM_NT);
    cudaFuncSetAttribute(gemm_tf32<256, 128, false, 0>,
                         cudaFuncAttributeMaxDynamicSharedMemorySize, SMEM_NN);

    // 1) qkv = x @ in_w^T + in_b          [16384,1536]
    gemm_tf32<128, 256, true, 1><<<dim3(1536 / 256, ROWS / 128, 1), 256, SMEM_NT>>>(
        x, attn_in_w, attn_in_b, qkv, DMODEL, DMODEL, DMODEL, 1536,
        1, 0, 0, 0, 0, 0, 0, 1.f);

    // 2) scores[bh] = Q K^T / sqrt(hd)
    gemm_tf32<128, 256, true, 0><<<dim3(SEQ / 256, SEQ / 128, BATCH * NHEADS), 256, SMEM_NT>>>(
        qkv, qkv + 512, nullptr, scores, HDIM, 1536, 1536, SEQ,
        NHEADS,
        (long)SEQ * 1536, 128,
        (long)SEQ * 1536, 128,
        (long)NHEADS * SEQ * SEQ, (long)SEQ * SEQ,
        inv_sqrt_hd);

    // 3) softmax rows
    softmax_kernel<<<(BATCH * NHEADS * SEQ) / 8, 256>>>(scores, BATCH * NHEADS * SEQ);

    // 4) attnc[bh] = P V (concat layout), NN form, M=512 N=128
    gemm_tf32<256, 128, false, 0><<<dim3(HDIM / 128, SEQ / 256, BATCH * NHEADS), 256, SMEM_NN>>>(
        scores, qkv + 1024, nullptr, attnc, SEQ, SEQ, 1536, DMODEL,
        NHEADS,
        (long)NHEADS * SEQ * SEQ, (long)SEQ * SEQ,
        (long)SEQ * 1536, 128,
        (long)SEQ * DMODEL, 128,
        1.f);

    // 5) attnproj = attnc @ out_w^T + out_b
    gemm_tf32<128, 256, true, 1><<<dim3(DMODEL / 256, ROWS / 128, 1), 256, SMEM_NT>>>(
        attnc, attn_out_w, attn_out_b, attnproj, DMODEL, DMODEL, DMODEL, DMODEL,
        1, 0, 0, 0, 0, 0, 0, 1.f);

    // 6) x1 = LN(x + attnproj; ln1)
    ln_kernel<<<ROWS / 8, 256>>>(x, attnproj, ln1_g, ln1_b, x1, ROWS);

    // 7) xnorm = LN(x1; ln3)
    ln_kernel<<<ROWS / 8, 256>>>(x1, nullptr, ln3_g, ln3_b, xnorm, ROWS);

    // 8) angles = xnorm @ qin_w^T + qin_b (fp32)
    qin_kernel<<<ROWS / 8, 256>>>(xnorm, qin_w, qin_b, angles);

    // 9) real-ified circuit unitary (depends only on qweights)
    build_u_kernel<<<DIMQ, 128>>>(qweights, uq);

    // 10) product state Psi per row (split re/im)
    psi_kernel<<<ROWS, 256>>>(angles, psis);

    // 11) Phi = Psi @ U^T as a real tf32 GEMM [16384,512,512]
    gemm_tf32<128, 256, true, 0><<<dim3(512 / 256, ROWS / 128, 1), 256, SMEM_NT>>>(
        psis, uq, nullptr, phis, 512, 512, 512, 512,
        1, 0, 0, 0, 0, 0, 0, 1.f);

    // 12) z expectations
    zexp_kernel<<<ROWS, 256>>>(phis, zbuf);

    // 13) x2 = x1 + z @ qout_w^T + qout_b
    qout_add_kernel<<<(ROWS * DMODEL) / 256, 256>>>(x1, zbuf, qout_w, qout_b, x2);

    // 14) hbuf = gelu(x2 @ ffn_w1^T + ffn_b1)   [16384,2048]
    gemm_tf32<128, 256, true, 2><<<dim3(2048 / 256, ROWS / 128, 1), 256, SMEM_NT>>>(
        x2, ffn_w1, ffn_b1, hbuf, DMODEL, DMODEL, DMODEL, 2048,
        1, 0, 0, 0, 0, 0, 0, 1.f);

    // 15) ffnout = hbuf @ ffn_w2^T + ffn_b2
    gemm_tf32<128, 256, true, 1><<<dim3(DMODEL / 256, ROWS / 128, 1), 256, SMEM_NT>>>(
        hbuf, ffn_w2, ffn_b2, ffnout, 2048, 2048, 2048, DMODEL,
        1, 0, 0, 0, 0, 0, 0, 1.f);

    // 16) out = LN(x2 + ffnout; ln2)
    ln_kernel<<<ROWS / 8, 256>>>(x2, ffnout, ln2_g, ln2_b, out, ROWS);
}

// round 8
// speedup vs baseline: 4.0136x; 1.5642x over previous
#include <cuda_runtime.h>
#include <cuda_fp16.h>
#include <math.h>
#include <stdint.h>

// ---------------- problem constants ----------------
#define ROWS  16384        // B*S = 32*512
#define DMODEL 512
#define NHEADS 4
#define HDIM   128
#define SEQ    512
#define BATCH  32
#define NQ     8
#define DIMQ   256         // 2^8

// ---------------- scratch (static device memory; no allocs) ----------------
__device__ __half g_xh     [ROWS * DMODEL];
__device__ __half g_wih    [1536 * DMODEL];
__device__ __half g_woh    [DMODEL * DMODEL];
__device__ __half g_w1h    [2048 * DMODEL];
__device__ __half g_w2h    [DMODEL * 2048];
__device__ __half g_qkv_h  [ROWS * 1536];
__device__ float  g_scores [BATCH * NHEADS * SEQ * SEQ];
__device__ __half g_scores_h[BATCH * NHEADS * SEQ * SEQ];
__device__ __half g_vT_h   [BATCH * NHEADS * HDIM * SEQ];
__device__ __half g_attnc_h[ROWS * DMODEL];
__device__ float  g_attnproj[ROWS * DMODEL];
__device__ float  g_x1     [ROWS * DMODEL];
__device__ float  g_xnorm  [ROWS * DMODEL];
__device__ float  g_angles [ROWS * NQ];
__device__ __half g_uqh    [512 * 512];
__device__ __half g_psis_h [ROWS * 512];
__device__ float  g_phis   [ROWS * 512];
__device__ float  g_z      [ROWS * NQ];
__device__ float  g_x2     [ROWS * DMODEL];
__device__ __half g_x2h    [ROWS * DMODEL];
__device__ __half g_hbuf_h [ROWS * 2048];
__device__ float  g_ffnout [ROWS * DMODEL];

// ---------------- small helpers ----------------
__device__ __forceinline__ float warp_sum(float v) {
    #pragma unroll
    for (int o = 16; o; o >>= 1) v += __shfl_xor_sync(0xffffffffu, v, o);
    return v;
}
__device__ __forceinline__ float warp_max(float v) {
    #pragma unroll
    for (int o = 16; o; o >>= 1) v = fmaxf(v, __shfl_xor_sync(0xffffffffu, v, o));
    return v;
}
__device__ __forceinline__ float gelu_exact(float x) {
    return 0.5f * x * (1.0f + erff(x * 0.7071067811865476f));
}

// ---------------- fp16 tensor-core GEMM ----------------
// C[m,n] = alpha * sum_k A[m,k] * B[n,k]  (+bias, +gelu per EPI), A,B fp16 NT.
// CTA: 256 threads, BM=128, BN in {128,256}, BK=32 halves (64B rows + 16B pad).
// 3-stage cp.async ring, ldmatrix fragment loads, mma.m16n8k16 fp32 accum.
// OHALF: C stored as __half, else float.
#define RSTRIDE 80    // bytes per smem row (64 data + 16 pad): conflict-free LDSM

template<int BN, int EPI, bool OHALF>
__global__ void __launch_bounds__(256) gemm_h(
    const __half* __restrict__ A, const __half* __restrict__ B,
    const float* __restrict__ bias, void* __restrict__ Cv,
    int K, int lda, int ldb, int ldc,
    int nh, long sAb, long sAh, long sBb, long sBh, long sCb, long sCh,
    float alpha)
{
    constexpr int WARPS_M = (BN == 256) ? 2 : 4;
    constexpr int WM = 128 / WARPS_M;          // 64 or 32
    constexpr int MI = WM / 16;                // 4 or 2
    constexpr int NI = 8;                      // 64-wide n per warp
    constexpr int ASTAGE = 128 * RSTRIDE;      // bytes
    constexpr int BSTAGE = BN * RSTRIDE;

    extern __shared__ char smem[];
    const uint32_t tiles = (uint32_t)__cvta_generic_to_shared(smem);

    int bz = blockIdx.z;
    int bb = bz / nh, hh = bz - bb * nh;
    A += bb * sAb + hh * sAh;
    B += bb * sBb + hh * sBh;

    const int tid  = threadIdx.x;
    const int warp = tid >> 5, lane = tid & 31;
    const int wm = warp / (BN / 64), wn = warp % (BN / 64);
    const long rowBase = (long)blockIdx.y * 128;
    const long colBase = (long)blockIdx.x * BN;

    // per-thread ldmatrix address components
    const int aoff_row = wm * WM + (lane & 15);
    const int akb      = ((lane >> 4) & 1) * 16;
    const int boff_n   = wn * 64 + (lane & 7) + ((lane >> 4) & 1) * 8;
    const int bkb      = ((lane >> 3) & 1) * 16;

    float acc[MI][NI][4];
    #pragma unroll
    for (int i = 0; i < MI; i++)
        #pragma unroll
        for (int j = 0; j < NI; j++)
            #pragma unroll
            for (int q = 0; q < 4; q++) acc[i][j][q] = 0.f;

#define CPA16(DST, SRC)                                                        \
    asm volatile("cp.async.cg.shared.global [%0], [%1], 16;" :: "r"(DST), "l"(SRC))

#define ISSUE(STG, T)                                                          \
    {                                                                          \
        uint32_t abase = tiles + (STG) * ASTAGE;                               \
        uint32_t bbase = tiles + 3 * ASTAGE + (STG) * BSTAGE;                  \
        _Pragma("unroll")                                                      \
        for (int it = 0; it < 2; it++) {                                       \
            int idx = tid + it * 256;                                          \
            int r = idx >> 2, c = idx & 3;                                     \
            CPA16(abase + r * RSTRIDE + c * 16,                                \
                  A + (rowBase + r) * lda + (T) * 32 + c * 8);                 \
        }                                                                      \
        _Pragma("unroll")                                                      \
        for (int it = 0; it < BN / 64; it++) {                                 \
            int idx = tid + it * 256;                                          \
            int r = idx >> 2, c = idx & 3;                                     \
            CPA16(bbase + r * RSTRIDE + c * 16,                                \
                  B + (colBase + r) * ldb + (T) * 32 + c * 8);                 \
        }                                                                      \
        asm volatile("cp.async.commit_group;" ::: "memory");                   \
    }

#define COMPUTE(STG)                                                           \
    {                                                                          \
        uint32_t abase = tiles + (STG) * ASTAGE;                               \
        uint32_t bbase = tiles + 3 * ASTAGE + (STG) * BSTAGE;                  \
        _Pragma("unroll")                                                      \
        for (int k16 = 0; k16 < 2; k16++) {                                    \
            uint32_t af[MI][4], bf[NI][2];                                     \
            _Pragma("unroll")                                                  \
            for (int mi = 0; mi < MI; mi++) {                                  \
                uint32_t ad = abase + (aoff_row + mi * 16) * RSTRIDE           \
                            + k16 * 32 + akb;                                  \
                asm volatile(                                                  \
                    "ldmatrix.sync.aligned.m8n8.x4.shared.b16 "                \
                    "{%0,%1,%2,%3}, [%4];"                                     \
                    : "=r"(af[mi][0]), "=r"(af[mi][1]),                        \
                      "=r"(af[mi][2]), "=r"(af[mi][3]) : "r"(ad));             \
            }                                                                  \
            _Pragma("unroll")                                                  \
            for (int p = 0; p < NI / 2; p++) {                                 \
                uint32_t bd = bbase + (boff_n + p * 16) * RSTRIDE              \
                            + k16 * 32 + bkb;                                  \
                asm volatile(                                                  \
                    "ldmatrix.sync.aligned.m8n8.x4.shared.b16 "                \
                    "{%0,%1,%2,%3}, [%4];"                                     \
                    : "=r"(bf[2 * p][0]), "=r"(bf[2 * p][1]),                  \
                      "=r"(bf[2 * p + 1][0]), "=r"(bf[2 * p + 1][1])           \
                    : "r"(bd));                                                \
            }                                                                  \
            _Pragma("unroll")                                                  \
            for (int mi = 0; mi < MI; mi++)                                    \
                _Pragma("unroll")                                              \
                for (int ni = 0; ni < NI; ni++)                                \
                    asm volatile(                                              \
                        "mma.sync.aligned.m16n8k16.row.col.f32.f16.f16.f32 "   \
                        "{%0,%1,%2,%3}, {%4,%5,%6,%7}, {%8,%9}, {%0,%1,%2,%3};"\
                        : "+f"(acc[mi][ni][0]), "+f"(acc[mi][ni][1]),          \
                          "+f"(acc[mi][ni][2]), "+f"(acc[mi][ni][3])           \
                        : "r"(af[mi][0]), "r"(af[mi][1]),                      \
                          "r"(af[mi][2]), "r"(af[mi][3]),                      \
                          "r"(bf[ni][0]), "r"(bf[ni][1]));                     \
        }                                                                      \
    }

    const int NK = K >> 5;
    ISSUE(0, 0);
    ISSUE(1, 1);

    for (int t = 0; t < NK; t++) {
        if (t < NK - 1) asm volatile("cp.async.wait_group 1;" ::: "memory");
        else            asm volatile("cp.async.wait_group 0;" ::: "memory");
        __syncthreads();
        if (t + 2 < NK) ISSUE((t + 2) % 3, t + 2);
        COMPUTE(t % 3);
        __syncthreads();
    }

    // epilogue
    float* Cf = (float*)Cv;
    __half* Ch = (__half*)Cv;
    const long cadd = bb * sCb + hh * sCh;
    #pragma unroll
    for (int mi = 0; mi < MI; mi++) {
        long row = rowBase + wm * WM + mi * 16 + (lane >> 2);
        #pragma unroll
        for (int ni = 0; ni < NI; ni++) {
            long col = colBase + wn * 64 + ni * 8 + (lane & 3) * 2;
            float2 v0, v1;
            v0.x = acc[mi][ni][0] * alpha; v0.y = acc[mi][ni][1] * alpha;
            v1.x = acc[mi][ni][2] * alpha; v1.y = acc[mi][ni][3] * alpha;
            if (EPI >= 1) {
                float2 bv = *(const float2*)(bias + col);
                v0.x += bv.x; v0.y += bv.y; v1.x += bv.x; v1.y += bv.y;
            }
            if (EPI == 2) {
                v0.x = gelu_exact(v0.x); v0.y = gelu_exact(v0.y);
                v1.x = gelu_exact(v1.x); v1.y = gelu_exact(v1.y);
            }
            if (OHALF) {
                *(__half2*)(Ch + cadd + row * ldc + col) = __floats2half2_rn(v0.x, v0.y);
                *(__half2*)(Ch + cadd + (row + 8) * ldc + col) = __floats2half2_rn(v1.x, v1.y);
            } else {
                *(float2*)(Cf + cadd + row * ldc + col) = v0;
                *(float2*)(Cf + cadd + (row + 8) * ldc + col) = v1;
            }
        }
    }
#undef CPA16
#undef ISSUE
#undef COMPUTE
}

// ---------------- f32 -> f16 convert ----------------
__global__ void f2h_kernel(const float* __restrict__ in, __half* __restrict__ out, long n4)
{
    long i = blockIdx.x * 256 + threadIdx.x;
    if (i >= n4) return;
    float4 v = *(const float4*)(in + i * 4);
    __half2* o = (__half2*)(out + i * 4);
    o[0] = __floats2half2_rn(v.x, v.y);
    o[1] = __floats2half2_rn(v.z, v.w);
}

// ---------------- V transpose (half): vT[bh][n][k] = qkv_h[(b*512+k)][1024+h*128+n]
__global__ void transpose_v(const __half* __restrict__ qkv, __half* __restrict__ vT)
{
    __shared__ __half tile[32][34];
    int bh = blockIdx.z;
    int b = bh >> 2, h = bh & 3;
    int k0 = blockIdx.x * 32, n0 = blockIdx.y * 32;
    #pragma unroll
    for (int i = threadIdx.y; i < 32; i += 8)
        tile[i][threadIdx.x] =
            qkv[(long)(b * 512 + k0 + i) * 1536 + 1024 + h * 128 + n0 + threadIdx.x];
    __syncthreads();
    #pragma unroll
    for (int i = threadIdx.y; i < 32; i += 8)
        vT[((long)bh * HDIM + n0 + i) * SEQ + k0 + threadIdx.x] = tile[threadIdx.x][i];
}

// ---------------- LayerNorm (f32) ----------------
__global__ void ln_kernel(const float* __restrict__ A, const float* __restrict__ R,
                          const float* __restrict__ g, const float* __restrict__ b,
                          float* __restrict__ out, int nrows)
{
    int warp = (blockIdx.x * blockDim.x + threadIdx.x) >> 5;
    int lane = threadIdx.x & 31;
    if (warp >= nrows) return;
    const float* a = A + (long)warp * DMODEL;
    float4 v[4];
    float s = 0.f;
    #pragma unroll
    for (int t = 0; t < 4; t++) {
        int c = (t * 32 + lane) * 4;
        v[t] = *(const float4*)(a + c);
        if (R) {
            float4 r4 = *(const float4*)(R + (long)warp * DMODEL + c);
            v[t].x += r4.x; v[t].y += r4.y; v[t].z += r4.z; v[t].w += r4.w;
        }
        s += v[t].x + v[t].y + v[t].z + v[t].w;
    }
    s = warp_sum(s);
    float mean = s * (1.f / DMODEL);
    float vs = 0.f;
    #pragma unroll
    for (int t = 0; t < 4; t++) {
        float dx = v[t].x - mean, dy = v[t].y - mean, dz = v[t].z - mean, dw = v[t].w - mean;
        vs += dx * dx + dy * dy + dz * dz + dw * dw;
    }
    vs = warp_sum(vs);
    float rstd = rsqrtf(vs * (1.f / DMODEL) + 1e-5f);
    #pragma unroll
    for (int t = 0; t < 4; t++) {
        int c = (t * 32 + lane) * 4;
        float4 gv = *(const float4*)(g + c);
        float4 bv = *(const float4*)(b + c);
        float4 o;
        o.x = (v[t].x - mean) * rstd * gv.x + bv.x;
        o.y = (v[t].y - mean) * rstd * gv.y + bv.y;
        o.z = (v[t].z - mean) * rstd * gv.z + bv.z;
        o.w = (v[t].w - mean) * rstd * gv.w + bv.w;
        *(float4*)(out + (long)warp * DMODEL + c) = o;
    }
}

// ---------------- row softmax over 512: f32 in, f16 out ----------------
__global__ void softmax_kernel(const float* __restrict__ S, __half* __restrict__ Sh,
                               int nrows)
{
    int warp = (blockIdx.x * blockDim.x + threadIdx.x) >> 5;
    int lane = threadIdx.x & 31;
    if (warp >= nrows) return;
    const float* r = S + (long)warp * SEQ;
    float4 v[4];
    float m = -3.4e38f;
    #pragma unroll
    for (int t = 0; t < 4; t++) {
        v[t] = *(const float4*)(r + (t * 32 + lane) * 4);
        m = fmaxf(m, fmaxf(fmaxf(v[t].x, v[t].y), fmaxf(v[t].z, v[t].w)));
    }
    m = warp_max(m);
    float s = 0.f;
    #pragma unroll
    for (int t = 0; t < 4; t++) {
        v[t].x = __expf(v[t].x - m); v[t].y = __expf(v[t].y - m);
        v[t].z = __expf(v[t].z - m); v[t].w = __expf(v[t].w - m);
        s += v[t].x + v[t].y + v[t].z + v[t].w;
    }
    s = warp_sum(s);
    float inv = 1.f / s;
    __half* o = Sh + (long)warp * SEQ;
    #pragma unroll
    for (int t = 0; t < 4; t++) {
        int c = (t * 32 + lane) * 4;
        __half2* oh = (__half2*)(o + c);
        oh[0] = __floats2half2_rn(v[t].x * inv, v[t].y * inv);
        oh[1] = __floats2half2_rn(v[t].z * inv, v[t].w * inv);
    }
}

// ---------------- angles = xnorm @ qin_w^T + qin_b ----------------
__global__ void qin_kernel(const float* __restrict__ xn, const float* __restrict__ w,
                           const float* __restrict__ b, float* __restrict__ ang)
{
    int warp = (blockIdx.x * blockDim.x + threadIdx.x) >> 5;
    int lane = threadIdx.x & 31;
    if (warp >= ROWS) return;
    const float* xr = xn + (long)warp * DMODEL;
    float4 xv[4];
    #pragma unroll
    for (int t = 0; t < 4; t++) xv[t] = *(const float4*)(xr + (t * 32 + lane) * 4);
    float myang = 0.f;
    #pragma unroll
    for (int o = 0; o < NQ; o++) {
        const float* wr = w + o * DMODEL;
        float p = 0.f;
        #pragma unroll
        for (int t = 0; t < 4; t++) {
            float4 wv = *(const float4*)(wr + (t * 32 + lane) * 4);
            p += xv[t].x * wv.x + xv[t].y * wv.y + xv[t].z * wv.z + xv[t].w * wv.w;
        }
        p = warp_sum(p);
        if (lane == o) myang = p + b[o];
    }
    if (lane < NQ) ang[(long)warp * NQ + lane] = myang;
}

// ---------------- build real-ified circuit unitary (f16 out, 512x512) -------
__global__ void build_u_kernel(const float* __restrict__ qw, __half* __restrict__ Bq)
{
    __shared__ float2 st[DIMQ];
    int col = blockIdx.x;
    int t = threadIdx.x;
    st[t] = make_float2(0.f, 0.f);
    st[t + 128] = make_float2(0.f, 0.f);
    __syncthreads();
    if (t == 0) st[col] = make_float2(1.f, 0.f);
    __syncthreads();

    for (int l = 0; l < 4; l++) {
        for (int i = 0; i < NQ; i++) {
            float w0 = qw[(l * 2 + 0) * NQ + i];
            float w1 = qw[(l * 2 + 1) * NQ + i];
            float sn, cs, sn2, cs2;
            sincosf(0.5f * w0, &sn, &cs);
            sincosf(0.5f * w1, &sn2, &cs2);
            float2 M00 = make_float2( cs * cs2, -cs * sn2);
            float2 M01 = make_float2(-sn * sn2, -sn * cs2);
            float2 M10 = make_float2( sn * sn2, -sn * cs2);
            float2 M11 = make_float2( cs * cs2,  cs * sn2);
            int bpos = 7 - i;
            int lowmask = (1 << bpos) - 1;
            int s0 = ((t >> bpos) << (bpos + 1)) | (t & lowmask);
            int s1 = s0 | (1 << bpos);
            float2 a0 = st[s0], a1 = st[s1];
            float2 n0, n1;
            n0.x = M00.x * a0.x - M00.y * a0.y + M01.x * a1.x - M01.y * a1.y;
            n0.y = M00.x * a0.y + M00.y * a0.x + M01.x * a1.y + M01.y * a1.x;
            n1.x = M10.x * a0.x - M10.y * a0.y + M11.x * a1.x - M11.y * a1.y;
            n1.y = M10.x * a0.y + M10.y * a0.x + M11.x * a1.y + M11.y * a1.x;
            st[s0] = n0; st[s1] = n1;
            __syncthreads();
        }
        for (int i = 0; i < NQ - 1; i++) {
            int cb = 7 - i, tb = 6 - i;
            if (t < 64) {
                int tlow = t & ((1 << tb) - 1);
                int s0 = ((t >> tb) << (tb + 2)) | (1 << cb) | tlow;
                int s1 = s0 | (1 << tb);
                float2 tmp = st[s0]; st[s0] = st[s1]; st[s1] = tmp;
            }
            __syncthreads();
        }
    }
    #pragma unroll
    for (int h = 0; h < 2; h++) {
        int s = t + h * 128;
        float2 u = st[s];
        Bq[(long)s * 512 + col]               = __float2half( u.x);
        Bq[(long)s * 512 + 256 + col]         = __float2half(-u.y);
        Bq[(long)(256 + s) * 512 + col]       = __float2half( u.y);
        Bq[(long)(256 + s) * 512 + 256 + col] = __float2half( u.x);
    }
}

// ---------------- product state Psi (split re/im, f16 out) ----------------
__global__ void psi_kernel(const float* __restrict__ ang, __half* __restrict__ psis)
{
    __shared__ float2 sq[NQ][2];
    int row = blockIdx.x;
    int s = threadIdx.x;
    if (s < NQ) {
        float a = ang[(long)row * NQ + s];
        float sn, cs;
        sincosf(0.5f * a, &sn, &cs);
        sq[s][0] = make_float2(cs * cs, -cs * sn);
        sq[s][1] = make_float2(sn * sn, -sn * cs);
    }
    __syncthreads();
    float2 amp = make_float2(1.f, 0.f);
    #pragma unroll
    for (int i = 0; i < NQ; i++) {
        float2 q = sq[i][(s >> (7 - i)) & 1];
        float2 na;
        na.x = amp.x * q.x - amp.y * q.y;
        na.y = amp.x * q.y + amp.y * q.x;
        amp = na;
    }
    psis[(long)row * 512 + s] = __float2half(amp.x);
    psis[(long)row * 512 + 256 + s] = __float2half(amp.y);
}

// ---------------- z expectations ----------------
__global__ void zexp_kernel(const float* __restrict__ Phis, float* __restrict__ Z)
{
    __shared__ float partial[8][9];
    int row = blockIdx.x;
    int s = threadIdx.x;
    float re = Phis[(long)row * 512 + s];
    float im = Phis[(long)row * 512 + 256 + s];
    float p = re * re + im * im;
    int lane = s & 31, wid = s >> 5;
    float vals[NQ];
    #pragma unroll
    for (int i = 0; i < NQ; i++)
        vals[i] = ((s >> (7 - i)) & 1) ? -p : p;
    #pragma unroll
    for (int o = 16; o; o >>= 1)
        #pragma unroll
        for (int i = 0; i < NQ; i++)
            vals[i] += __shfl_xor_sync(0xffffffffu, vals[i], o);
    if (lane == 0)
        #pragma unroll
        for (int i = 0; i < NQ; i++) partial[wid][i] = vals[i];
    __syncthreads();
    if (s < NQ) {
        float acc = 0.f;
        #pragma unroll
        for (int w = 0; w < 8; w++) acc += partial[w][s];
        Z[(long)row * NQ + s] = acc;
    }
}

// ---------------- x2 = x1 + z @ qout_w^T + qout_b (f32 + f16 out) ----------
__global__ void qout_add_kernel(const float* __restrict__ x1, const float* __restrict__ z,
                                const float* __restrict__ w, const float* __restrict__ b,
                                float* __restrict__ out, __half* __restrict__ outh)
{
    long gidx = (long)blockIdx.x * 256 + threadIdx.x;
    int row = (int)(gidx >> 9);
    int col = (int)(gidx & 511);
    const float* zr = z + (long)row * NQ;
    float4 w0 = *(const float4*)(w + (long)col * NQ);
    float4 w1 = *(const float4*)(w + (long)col * NQ + 4);
    float acc = b[col];
    acc += zr[0] * w0.x + zr[1] * w0.y + zr[2] * w0.z + zr[3] * w0.w;
    acc += zr[4] * w1.x + zr[5] * w1.y + zr[6] * w1.z + zr[7] * w1.w;
    float val = x1[gidx] + acc;
    out[gidx] = val;
    outh[gidx] = __float2half(val);
}

// ---------------- launch ----------------
extern "C" void kernel_launch(void* const* d_in, const int* in_sizes, int n_in,
                              void* d_out, int out_size)
{
    const float* x          = (const float*)d_in[0];
    const float* attn_in_w  = (const float*)d_in[1];
    const float* attn_in_b  = (const float*)d_in[2];
    const float* attn_out_w = (const float*)d_in[3];
    const float* attn_out_b = (const float*)d_in[4];
    const float* ln1_g      = (const float*)d_in[5];
    const float* ln1_b      = (const float*)d_in[6];
    const float* ln2_g      = (const float*)d_in[7];
    const float* ln2_b      = (const float*)d_in[8];
    const float* ln3_g      = (const float*)d_in[9];
    const float* ln3_b      = (const float*)d_in[10];
    const float* qin_w      = (const float*)d_in[11];
    const float* qin_b      = (const float*)d_in[12];
    const float* qweights   = (const float*)d_in[13];
    const float* qout_w     = (const float*)d_in[14];
    const float* qout_b     = (const float*)d_in[15];
    const float* ffn_w1     = (const float*)d_in[16];
    const float* ffn_b1     = (const float*)d_in[17];
    const float* ffn_w2     = (const float*)d_in[18];
    const float* ffn_b2     = (const float*)d_in[19];
    float* out = (float*)d_out;

    __half *xh, *wih, *woh, *w1h, *w2h, *qkvh, *scoresh, *vTh, *attnch, *uqh,
           *psish, *x2h, *hbufh;
    float  *scores, *attnproj, *x1, *xnorm, *angles, *phis, *zbuf, *x2, *ffnout;
    cudaGetSymbolAddress((void**)&xh,       g_xh);
    cudaGetSymbolAddress((void**)&wih,      g_wih);
    cudaGetSymbolAddress((void**)&woh,      g_woh);
    cudaGetSymbolAddress((void**)&w1h,      g_w1h);
    cudaGetSymbolAddress((void**)&w2h,      g_w2h);
    cudaGetSymbolAddress((void**)&qkvh,     g_qkv_h);
    cudaGetSymbolAddress((void**)&scores,   g_scores);
    cudaGetSymbolAddress((void**)&scoresh,  g_scores_h);
    cudaGetSymbolAddress((void**)&vTh,      g_vT_h);
    cudaGetSymbolAddress((void**)&attnch,   g_attnc_h);
    cudaGetSymbolAddress((void**)&attnproj, g_attnproj);
    cudaGetSymbolAddress((void**)&x1,       g_x1);
    cudaGetSymbolAddress((void**)&xnorm,    g_xnorm);
    cudaGetSymbolAddress((void**)&angles,   g_angles);
    cudaGetSymbolAddress((void**)&uqh,      g_uqh);
    cudaGetSymbolAddress((void**)&psish,    g_psis_h);
    cudaGetSymbolAddress((void**)&phis,     g_phis);
    cudaGetSymbolAddress((void**)&zbuf,     g_z);
    cudaGetSymbolAddress((void**)&x2,       g_x2);
    cudaGetSymbolAddress((void**)&x2h,      g_x2h);
    cudaGetSymbolAddress((void**)&hbufh,    g_hbuf_h);
    cudaGetSymbolAddress((void**)&ffnout,   g_ffnout);

    const float inv_sqrt_hd = 0.08838834764831845f;   // 1/sqrt(128)

    const int SMEM_256 = 3 * (128 * RSTRIDE + 256 * RSTRIDE);   // 92160
    const int SMEM_128 = 3 * (128 * RSTRIDE + 128 * RSTRIDE);   // 61440

    cudaFuncSetAttribute(gemm_h<256, 1, true >, cudaFuncAttributeMaxDynamicSharedMemorySize, SMEM_256);
    cudaFuncSetAttribute(gemm_h<256, 0, false>, cudaFuncAttributeMaxDynamicSharedMemorySize, SMEM_256);
    cudaFuncSetAttribute(gemm_h<128, 0, true >, cudaFuncAttributeMaxDynamicSharedMemorySize, SMEM_128);
    cudaFuncSetAttribute(gemm_h<256, 1, false>, cudaFuncAttributeMaxDynamicSharedMemorySize, SMEM_256);
    cudaFuncSetAttribute(gemm_h<256, 2, true >, cudaFuncAttributeMaxDynamicSharedMemorySize, SMEM_256);

    // 0) dtype conversions
    f2h_kernel<<<(ROWS * DMODEL / 4 + 255) / 256, 256>>>(x, xh, ROWS * DMODEL / 4);
    f2h_kernel<<<(1536 * DMODEL / 4 + 255) / 256, 256>>>(attn_in_w, wih, 1536 * DMODEL / 4);
    f2h_kernel<<<(DMODEL * DMODEL / 4 + 255) / 256, 256>>>(attn_out_w, woh, DMODEL * DMODEL / 4);
    f2h_kernel<<<(2048 * DMODEL / 4 + 255) / 256, 256>>>(ffn_w1, w1h, 2048 * DMODEL / 4);
    f2h_kernel<<<(DMODEL * 2048 / 4 + 255) / 256, 256>>>(ffn_w2, w2h, DMODEL * 2048 / 4);

    // 1) qkv = x @ in_w^T + in_b  -> half
    gemm_h<256, 1, true><<<dim3(1536 / 256, ROWS / 128, 1), 256, SMEM_256>>>(
        xh, wih, attn_in_b, qkvh, DMODEL, DMODEL, DMODEL, 1536,
        1, 0, 0, 0, 0, 0, 0, 1.f);

    // 2) scores[bh] = Q K^T / sqrt(hd) -> f32
    gemm_h<256, 0, false><<<dim3(SEQ / 256, SEQ / 128, BATCH * NHEADS), 256, SMEM_256>>>(
        qkvh, qkvh + 512, nullptr, scores, HDIM, 1536, 1536, SEQ,
        NHEADS,
        (long)SEQ * 1536, 128,
        (long)SEQ * 1536, 128,
        (long)NHEADS * SEQ * SEQ, (long)SEQ * SEQ,
        inv_sqrt_hd);

    // 3) softmax rows f32 -> f16
    softmax_kernel<<<(BATCH * NHEADS * SEQ) / 8, 256>>>(scores, scoresh, BATCH * NHEADS * SEQ);

    // 3b) transpose V -> vT (half)
    transpose_v<<<dim3(SEQ / 32, HDIM / 32, BATCH * NHEADS), dim3(32, 8)>>>(qkvh, vTh);

    // 4) attnc[bh] = P V -> half, concat layout
    gemm_h<128, 0, true><<<dim3(1, SEQ / 128, BATCH * NHEADS), 256, SMEM_128>>>(
        scoresh, vTh, nullptr, attnch, SEQ, SEQ, SEQ, DMODEL,
        NHEADS,
        (long)NHEADS * SEQ * SEQ, (long)SEQ * SEQ,
        (long)NHEADS * HDIM * SEQ, (long)HDIM * SEQ,
        (long)SEQ * DMODEL, 128,
        1.f);

    // 5) attnproj = attnc @ out_w^T + out_b -> f32
    gemm_h<256, 1, false><<<dim3(DMODEL / 256, ROWS / 128, 1), 256, SMEM_256>>>(
        attnch, woh, attn_out_b, attnproj, DMODEL, DMODEL, DMODEL, DMODEL,
        1, 0, 0, 0, 0, 0, 0, 1.f);

    // 6) x1 = LN(x + attnproj; ln1)
    ln_kernel<<<ROWS / 8, 256>>>(x, attnproj, ln1_g, ln1_b, x1, ROWS);

    // 7) xnorm = LN(x1; ln3)
    ln_kernel<<<ROWS / 8, 256>>>(x1, nullptr, ln3_g, ln3_b, xnorm, ROWS);

    // 8) angles = xnorm @ qin_w^T + qin_b
    qin_kernel<<<ROWS / 8, 256>>>(xnorm, qin_w, qin_b, angles);

    // 9) real-ified circuit unitary -> half
    build_u_kernel<<<DIMQ, 128>>>(qweights, uqh);

    // 10) product state Psi -> half
    psi_kernel<<<ROWS, 256>>>(angles, psish);

    // 11) Phi = Psi @ Uq^T -> f32
    gemm_h<256, 0, false><<<dim3(512 / 256, ROWS / 128, 1), 256, SMEM_256>>>(
        psish, uqh, nullptr, phis, 512, 512, 512, 512,
        1, 0, 0, 0, 0, 0, 0, 1.f);

    // 12) z expectations
    zexp_kernel<<<ROWS, 256>>>(phis, zbuf);

    // 13) x2 = x1 + z @ qout_w^T + qout_b  (f32 + f16)
    qout_add_kernel<<<(ROWS * DMODEL) / 256, 256>>>(x1, zbuf, qout_w, qout_b, x2, x2h);

    // 14) hbuf = gelu(x2 @ ffn_w1^T + ffn_b1) -> half
    gemm_h<256, 2, true><<<dim3(2048 / 256, ROWS / 128, 1), 256, SMEM_256>>>(
        x2h, w1h, ffn_b1, hbufh, DMODEL, DMODEL, DMODEL, 2048,
        1, 0, 0, 0, 0, 0, 0, 1.f);

    // 15) ffnout = hbuf @ ffn_w2^T + ffn_b2 -> f32
    gemm_h<256, 1, false><<<dim3(DMODEL / 256, ROWS / 128, 1), 256, SMEM_256>>>(
        hbufh, w2h, ffn_b2, ffnout, 2048, 2048, 2048, DMODEL,
        1, 0, 0, 0, 0, 0, 0, 1.f);

    // 16) out = LN(x2 + ffnout; ln2)
    ln_kernel<<<ROWS / 8, 256>>>(x2, ffnout, ln2_g, ln2_b, out, ROWS);
}

// round 9
// speedup vs baseline: 4.2091x; 1.0487x over previous
#include <cuda_runtime.h>
#include <cuda_fp16.h>
#include <math.h>
#include <stdint.h>

// ---------------- problem constants ----------------
#define ROWS  16384        // B*S = 32*512
#define DMODEL 512
#define NHEADS 4
#define HDIM   128
#define SEQ    512
#define BATCH  32
#define NQ     8
#define DIMQ   256         // 2^8

// ---------------- scratch (static device memory; no allocs) ----------------
__device__ __half g_xh     [ROWS * DMODEL];
__device__ __half g_wih    [1536 * DMODEL];
__device__ __half g_woh    [DMODEL * DMODEL];
__device__ __half g_w1h    [2048 * DMODEL];
__device__ __half g_w2h    [DMODEL * 2048];
__device__ __half g_qkv_h  [ROWS * 1536];
__device__ __half g_scores_h[BATCH * NHEADS * SEQ * SEQ];
__device__ __half g_vT_h   [BATCH * NHEADS * HDIM * SEQ];
__device__ __half g_attnc_h[ROWS * DMODEL];
__device__ float  g_attnproj[ROWS * DMODEL];
__device__ float  g_x1     [ROWS * DMODEL];
__device__ float  g_angles [ROWS * NQ];
__device__ __half g_uqh    [512 * 512];
__device__ __half g_psis_h [ROWS * 512];
__device__ float  g_phis   [ROWS * 512];
__device__ float  g_x2     [ROWS * DMODEL];
__device__ __half g_x2h    [ROWS * DMODEL];
__device__ __half g_hbuf_h [ROWS * 2048];
__device__ float  g_ffnout [ROWS * DMODEL];

// ---------------- small helpers ----------------
__device__ __forceinline__ float warp_sum(float v) {
    #pragma unroll
    for (int o = 16; o; o >>= 1) v += __shfl_xor_sync(0xffffffffu, v, o);
    return v;
}
__device__ __forceinline__ float warp_max(float v) {
    #pragma unroll
    for (int o = 16; o; o >>= 1) v = fmaxf(v, __shfl_xor_sync(0xffffffffu, v, o));
    return v;
}
__device__ __forceinline__ float gelu_exact(float x) {
    return 0.5f * x * (1.0f + erff(x * 0.7071067811865476f));
}

// ---------------- fp16 tensor-core GEMM ----------------
// C[m,n] = alpha * sum_k A[m,k] * B[n,k]  (+bias, +gelu per EPI), A,B fp16 NT.
// 256 threads, BM=128, BN in {128,256}, BK=32 halves. 4-stage cp.async ring,
// ldmatrix fragments, mma.m16n8k16 fp32 accum. One barrier per K-iter.
#define RSTRIDE 80    // bytes per smem row (64 data + 16 pad): conflict-free LDSM

template<int BN, int EPI, bool OHALF>
__global__ void __launch_bounds__(256) gemm_h(
    const __half* __restrict__ A, const __half* __restrict__ B,
    const float* __restrict__ bias, void* __restrict__ Cv,
    int K, int lda, int ldb, int ldc,
    int nh, long sAb, long sAh, long sBb, long sBh, long sCb, long sCh,
    float alpha)
{
    constexpr int WARPS_M = (BN == 256) ? 2 : 4;
    constexpr int WM = 128 / WARPS_M;          // 64 or 32
    constexpr int MI = WM / 16;                // 4 or 2
    constexpr int NI = 8;                      // 64-wide n per warp
    constexpr int ASTAGE = 128 * RSTRIDE;      // bytes
    constexpr int BSTAGE = BN * RSTRIDE;

    extern __shared__ char smem[];
    const uint32_t tiles = (uint32_t)__cvta_generic_to_shared(smem);

    int bz = blockIdx.z;
    int bb = bz / nh, hh = bz - bb * nh;
    A += bb * sAb + hh * sAh;
    B += bb * sBb + hh * sBh;

    const int tid  = threadIdx.x;
    const int warp = tid >> 5, lane = tid & 31;
    const int wm = warp / (BN / 64), wn = warp % (BN / 64);
    const long rowBase = (long)blockIdx.y * 128;
    const long colBase = (long)blockIdx.x * BN;

    const int aoff_row = wm * WM + (lane & 15);
    const int akb      = ((lane >> 4) & 1) * 16;
    const int boff_n   = wn * 64 + (lane & 7) + ((lane >> 4) & 1) * 8;
    const int bkb      = ((lane >> 3) & 1) * 16;

    float acc[MI][NI][4];
    #pragma unroll
    for (int i = 0; i < MI; i++)
        #pragma unroll
        for (int j = 0; j < NI; j++)
            #pragma unroll
            for (int q = 0; q < 4; q++) acc[i][j][q] = 0.f;

#define CPA16(DST, SRC)                                                        \
    asm volatile("cp.async.cg.shared.global [%0], [%1], 16;" :: "r"(DST), "l"(SRC))

#define ISSUE(STG, T)                                                          \
    {                                                                          \
        uint32_t abase = tiles + (STG) * ASTAGE;                               \
        uint32_t bbase = tiles + 4 * ASTAGE + (STG) * BSTAGE;                  \
        _Pragma("unroll")                                                      \
        for (int it = 0; it < 2; it++) {                                       \
            int idx = tid + it * 256;                                          \
            int r = idx >> 2, c = idx & 3;                                     \
            CPA16(abase + r * RSTRIDE + c * 16,                                \
                  A + (rowBase + r) * lda + (T) * 32 + c * 8);                 \
        }                                                                      \
        _Pragma("unroll")                                                      \
        for (int it = 0; it < BN / 64; it++) {                                 \
            int idx = tid + it * 256;                                          \
            int r = idx >> 2, c = idx & 3;                                     \
            CPA16(bbase + r * RSTRIDE + c * 16,                                \
                  B + (colBase + r) * ldb + (T) * 32 + c * 8);                 \
        }                                                                      \
        asm volatile("cp.async.commit_group;" ::: "memory");                   \
    }

#define COMPUTE(STG)                                                           \
    {                                                                          \
        uint32_t abase = tiles + (STG) * ASTAGE;                               \
        uint32_t bbase = tiles + 4 * ASTAGE + (STG) * BSTAGE;                  \
        _Pragma("unroll")                                                      \
        for (int k16 = 0; k16 < 2; k16++) {                                    \
            uint32_t af[MI][4], bf[NI][2];                                     \
            _Pragma("unroll")                                                  \
            for (int mi = 0; mi < MI; mi++) {                                  \
                uint32_t ad = abase + (aoff_row + mi * 16) * RSTRIDE           \
                            + k16 * 32 + akb;                                  \
                asm volatile(                                                  \
                    "ldmatrix.sync.aligned.m8n8.x4.shared.b16 "                \
                    "{%0,%1,%2,%3}, [%4];"                                     \
                    : "=r"(af[mi][0]), "=r"(af[mi][1]),                        \
                      "=r"(af[mi][2]), "=r"(af[mi][3]) : "r"(ad));             \
            }                                                                  \
            _Pragma("unroll")                                                  \
            for (int p = 0; p < NI / 2; p++) {                                 \
                uint32_t bd = bbase + (boff_n + p * 16) * RSTRIDE              \
                            + k16 * 32 + bkb;                                  \
                asm volatile(                                                  \
                    "ldmatrix.sync.aligned.m8n8.x4.shared.b16 "                \
                    "{%0,%1,%2,%3}, [%4];"                                     \
                    : "=r"(bf[2 * p][0]), "=r"(bf[2 * p][1]),                  \
                      "=r"(bf[2 * p + 1][0]), "=r"(bf[2 * p + 1][1])           \
                    : "r"(bd));                                                \
            }                                                                  \
            _Pragma("unroll")                                                  \
            for (int mi = 0; mi < MI; mi++)                                    \
                _Pragma("unroll")                                              \
                for (int ni = 0; ni < NI; ni++)                                \
                    asm volatile(                                              \
                        "mma.sync.aligned.m16n8k16.row.col.f32.f16.f16.f32 "   \
                        "{%0,%1,%2,%3}, {%4,%5,%6,%7}, {%8,%9}, {%0,%1,%2,%3};"\
                        : "+f"(acc[mi][ni][0]), "+f"(acc[mi][ni][1]),          \
                          "+f"(acc[mi][ni][2]), "+f"(acc[mi][ni][3])           \
                        : "r"(af[mi][0]), "r"(af[mi][1]),                      \
                          "r"(af[mi][2]), "r"(af[mi][3]),                      \
                          "r"(bf[ni][0]), "r"(bf[ni][1]));                     \
        }                                                                      \
    }

    const int NK = K >> 5;          // all call sites have NK >= 4
    ISSUE(0, 0);
    ISSUE(1, 1);
    ISSUE(2, 2);

    for (int t = 0; t < NK; t++) {
        if (t < NK - 2)      asm volatile("cp.async.wait_group 2;" ::: "memory");
        else if (t == NK - 2) asm volatile("cp.async.wait_group 1;" ::: "memory");
        else                  asm volatile("cp.async.wait_group 0;" ::: "memory");
        __syncthreads();
        if (t + 3 < NK) ISSUE((t + 3) & 3, t + 3);
        COMPUTE(t & 3);
    }

    // epilogue
    float* Cf = (float*)Cv;
    __half* Ch = (__half*)Cv;
    const long cadd = bb * sCb + hh * sCh;
    #pragma unroll
    for (int mi = 0; mi < MI; mi++) {
        long row = rowBase + wm * WM + mi * 16 + (lane >> 2);
        #pragma unroll
        for (int ni = 0; ni < NI; ni++) {
            long col = colBase + wn * 64 + ni * 8 + (lane & 3) * 2;
            float2 v0, v1;
            v0.x = acc[mi][ni][0] * alpha; v0.y = acc[mi][ni][1] * alpha;
            v1.x = acc[mi][ni][2] * alpha; v1.y = acc[mi][ni][3] * alpha;
            if (EPI >= 1) {
                float2 bv = *(const float2*)(bias + col);
                v0.x += bv.x; v0.y += bv.y; v1.x += bv.x; v1.y += bv.y;
            }
            if (EPI == 2) {
                v0.x = gelu_exact(v0.x); v0.y = gelu_exact(v0.y);
                v1.x = gelu_exact(v1.x); v1.y = gelu_exact(v1.y);
            }
            if (OHALF) {
                *(__half2*)(Ch + cadd + row * ldc + col) = __floats2half2_rn(v0.x, v0.y);
                *(__half2*)(Ch + cadd + (row + 8) * ldc + col) = __floats2half2_rn(v1.x, v1.y);
            } else {
                *(float2*)(Cf + cadd + row * ldc + col) = v0;
                *(float2*)(Cf + cadd + (row + 8) * ldc + col) = v1;
            }
        }
    }
#undef CPA16
#undef ISSUE
#undef COMPUTE
}

// ---------------- f32 -> f16 convert ----------------
__global__ void f2h_kernel(const float* __restrict__ in, __half* __restrict__ out, long n4)
{
    long i = blockIdx.x * 256 + threadIdx.x;
    if (i >= n4) return;
    float4 v = *(const float4*)(in + i * 4);
    __half2* o = (__half2*)(out + i * 4);
    o[0] = __floats2half2_rn(v.x, v.y);
    o[1] = __floats2half2_rn(v.z, v.w);
}

// ---------------- V transpose (half) ----------------
__global__ void transpose_v(const __half* __restrict__ qkv, __half* __restrict__ vT)
{
    __shared__ __half tile[32][34];
    int bh = blockIdx.z;
    int b = bh >> 2, h = bh & 3;
    int k0 = blockIdx.x * 32, n0 = blockIdx.y * 32;
    #pragma unroll
    for (int i = threadIdx.y; i < 32; i += 8)
        tile[i][threadIdx.x] =
            qkv[(long)(b * 512 + k0 + i) * 1536 + 1024 + h * 128 + n0 + threadIdx.x];
    __syncthreads();
    #pragma unroll
    for (int i = threadIdx.y; i < 32; i += 8)
        vT[((long)bh * HDIM + n0 + i) * SEQ + k0 + threadIdx.x] = tile[threadIdx.x][i];
}

// ---------------- LayerNorm (f32), generic ----------------
__global__ void ln_kernel(const float* __restrict__ A, const float* __restrict__ R,
                          const float* __restrict__ g, const float* __restrict__ b,
                          float* __restrict__ out, int nrows)
{
    int warp = (blockIdx.x * blockDim.x + threadIdx.x) >> 5;
    int lane = threadIdx.x & 31;
    if (warp >= nrows) return;
    const float* a = A + (long)warp * DMODEL;
    float4 v[4];
    float s = 0.f;
    #pragma unroll
    for (int t = 0; t < 4; t++) {
        int c = (t * 32 + lane) * 4;
        v[t] = *(const float4*)(a + c);
        if (R) {
            float4 r4 = *(const float4*)(R + (long)warp * DMODEL + c);
            v[t].x += r4.x; v[t].y += r4.y; v[t].z += r4.z; v[t].w += r4.w;
        }
        s += v[t].x + v[t].y + v[t].z + v[t].w;
    }
    s = warp_sum(s);
    float mean = s * (1.f / DMODEL);
    float vs = 0.f;
    #pragma unroll
    for (int t = 0; t < 4; t++) {
        float dx = v[t].x - mean, dy = v[t].y - mean, dz = v[t].z - mean, dw = v[t].w - mean;
        vs += dx * dx + dy * dy + dz * dz + dw * dw;
    }
    vs = warp_sum(vs);
    float rstd = rsqrtf(vs * (1.f / DMODEL) + 1e-5f);
    #pragma unroll
    for (int t = 0; t < 4; t++) {
        int c = (t * 32 + lane) * 4;
        float4 gv = *(const float4*)(g + c);
        float4 bv = *(const float4*)(b + c);
        float4 o;
        o.x = (v[t].x - mean) * rstd * gv.x + bv.x;
        o.y = (v[t].y - mean) * rstd * gv.y + bv.y;
        o.z = (v[t].z - mean) * rstd * gv.z + bv.z;
        o.w = (v[t].w - mean) * rstd * gv.w + bv.w;
        *(float4*)(out + (long)warp * DMODEL + c) = o;
    }
}

// ---------------- fused LN1 -> x1, LN3 (regs), qin angles ----------------
__global__ void ln13_qin_kernel(
    const float* __restrict__ X, const float* __restrict__ R,
    const float* __restrict__ g1, const float* __restrict__ b1,
    const float* __restrict__ g3, const float* __restrict__ b3,
    const float* __restrict__ qw, const float* __restrict__ qb,
    float* __restrict__ x1out, float* __restrict__ ang)
{
    int row = (blockIdx.x * blockDim.x + threadIdx.x) >> 5;
    int lane = threadIdx.x & 31;
    if (row >= ROWS) return;
    const float* a = X + (long)row * DMODEL;
    const float* r = R + (long)row * DMODEL;
    float4 v[4];
    float s = 0.f;
    #pragma unroll
    for (int t = 0; t < 4; t++) {
        int c = (t * 32 + lane) * 4;
        v[t] = *(const float4*)(a + c);
        float4 r4 = *(const float4*)(r + c);
        v[t].x += r4.x; v[t].y += r4.y; v[t].z += r4.z; v[t].w += r4.w;
        s += v[t].x + v[t].y + v[t].z + v[t].w;
    }
    s = warp_sum(s);
    float mean = s * (1.f / DMODEL);
    float vs = 0.f;
    #pragma unroll
    for (int t = 0; t < 4; t++) {
        float dx = v[t].x - mean, dy = v[t].y - mean, dz = v[t].z - mean, dw = v[t].w - mean;
        vs += dx * dx + dy * dy + dz * dz + dw * dw;
    }
    vs = warp_sum(vs);
    float rstd = rsqrtf(vs * (1.f / DMODEL) + 1e-5f);

    // x1 = LN1(x + attnproj); write + keep in regs, accumulate LN3 stats
    float s3 = 0.f;
    #pragma unroll
    for (int t = 0; t < 4; t++) {
        int c = (t * 32 + lane) * 4;
        float4 gv = *(const float4*)(g1 + c);
        float4 bv = *(const float4*)(b1 + c);
        v[t].x = (v[t].x - mean) * rstd * gv.x + bv.x;
        v[t].y = (v[t].y - mean) * rstd * gv.y + bv.y;
        v[t].z = (v[t].z - mean) * rstd * gv.z + bv.z;
        v[t].w = (v[t].w - mean) * rstd * gv.w + bv.w;
        *(float4*)(x1out + (long)row * DMODEL + c) = v[t];
        s3 += v[t].x + v[t].y + v[t].z + v[t].w;
    }
    s3 = warp_sum(s3);
    float mean3 = s3 * (1.f / DMODEL);
    float vs3 = 0.f;
    #pragma unroll
    for (int t = 0; t < 4; t++) {
        float dx = v[t].x - mean3, dy = v[t].y - mean3, dz = v[t].z - mean3, dw = v[t].w - mean3;
        vs3 += dx * dx + dy * dy + dz * dz + dw * dw;
    }
    vs3 = warp_sum(vs3);
    float rstd3 = rsqrtf(vs3 * (1.f / DMODEL) + 1e-5f);
    #pragma unroll
    for (int t = 0; t < 4; t++) {
        int c = (t * 32 + lane) * 4;
        float4 gv = *(const float4*)(g3 + c);
        float4 bv = *(const float4*)(b3 + c);
        v[t].x = (v[t].x - mean3) * rstd3 * gv.x + bv.x;
        v[t].y = (v[t].y - mean3) * rstd3 * gv.y + bv.y;
        v[t].z = (v[t].z - mean3) * rstd3 * gv.z + bv.z;
        v[t].w = (v[t].w - mean3) * rstd3 * gv.w + bv.w;
    }
    // angles = xnorm @ qin_w^T + qin_b
    float myang = 0.f;
    #pragma unroll
    for (int o = 0; o < NQ; o++) {
        const float* wr = qw + o * DMODEL;
        float p = 0.f;
        #pragma unroll
        for (int t = 0; t < 4; t++) {
            int c = (t * 32 + lane) * 4;
            float4 wv = *(const float4*)(wr + c);
            p += v[t].x * wv.x + v[t].y * wv.y + v[t].z * wv.z + v[t].w * wv.w;
        }
        p = warp_sum(p);
        if (lane == o) myang = p + qb[o];
    }
    if (lane < NQ) ang[(long)row * NQ + lane] = myang;
}

// ---------------- row softmax over 512, half in/out (in place) ----------------
__global__ void softmax_h_kernel(__half* __restrict__ S, int nrows)
{
    int row = (blockIdx.x * blockDim.x + threadIdx.x) >> 5;
    int lane = threadIdx.x & 31;
    if (row >= nrows) return;
    __half* r = S + (long)row * SEQ;
    float v[16];
    float m = -3.4e38f;
    #pragma unroll
    for (int t = 0; t < 4; t++) {
        int c = (t * 32 + lane) * 4;
        __half2 h0 = *(__half2*)(r + c);
        __half2 h1 = *(__half2*)(r + c + 2);
        float2 f0 = __half22float2(h0), f1 = __half22float2(h1);
        v[t * 4 + 0] = f0.x; v[t * 4 + 1] = f0.y;
        v[t * 4 + 2] = f1.x; v[t * 4 + 3] = f1.y;
        m = fmaxf(m, fmaxf(fmaxf(f0.x, f0.y), fmaxf(f1.x, f1.y)));
    }
    m = warp_max(m);
    float s = 0.f;
    #pragma unroll
    for (int i = 0; i < 16; i++) { v[i] = __expf(v[i] - m); s += v[i]; }
    s = warp_sum(s);
    float inv = 1.f / s;
    #pragma unroll
    for (int t = 0; t < 4; t++) {
        int c = (t * 32 + lane) * 4;
        *(__half2*)(r + c)     = __floats2half2_rn(v[t * 4 + 0] * inv, v[t * 4 + 1] * inv);
        *(__half2*)(r + c + 2) = __floats2half2_rn(v[t * 4 + 2] * inv, v[t * 4 + 3] * inv);
    }
}

// ---------------- build real-ified circuit unitary (f16 out, 512x512) -------
__global__ void build_u_kernel(const float* __restrict__ qw, __half* __restrict__ Bq)
{
    __shared__ float2 st[DIMQ];
    int col = blockIdx.x;
    int t = threadIdx.x;
    st[t] = make_float2(0.f, 0.f);
    st[t + 128] = make_float2(0.f, 0.f);
    __syncthreads();
    if (t == 0) st[col] = make_float2(1.f, 0.f);
    __syncthreads();

    for (int l = 0; l < 4; l++) {
        for (int i = 0; i < NQ; i++) {
            float w0 = qw[(l * 2 + 0) * NQ + i];
            float w1 = qw[(l * 2 + 1) * NQ + i];
            float sn, cs, sn2, cs2;
            sincosf(0.5f * w0, &sn, &cs);
            sincosf(0.5f * w1, &sn2, &cs2);
            float2 M00 = make_float2( cs * cs2, -cs * sn2);
            float2 M01 = make_float2(-sn * sn2, -sn * cs2);
            float2 M10 = make_float2( sn * sn2, -sn * cs2);
            float2 M11 = make_float2( cs * cs2,  cs * sn2);
            int bpos = 7 - i;
            int lowmask = (1 << bpos) - 1;
            int s0 = ((t >> bpos) << (bpos + 1)) | (t & lowmask);
            int s1 = s0 | (1 << bpos);
            float2 a0 = st[s0], a1 = st[s1];
            float2 n0, n1;
            n0.x = M00.x * a0.x - M00.y * a0.y + M01.x * a1.x - M01.y * a1.y;
            n0.y = M00.x * a0.y + M00.y * a0.x + M01.x * a1.y + M01.y * a1.x;
            n1.x = M10.x * a0.x - M10.y * a0.y + M11.x * a1.x - M11.y * a1.y;
            n1.y = M10.x * a0.y + M10.y * a0.x + M11.x * a1.y + M11.y * a1.x;
            st[s0] = n0; st[s1] = n1;
            __syncthreads();
        }
        for (int i = 0; i < NQ - 1; i++) {
            int cb = 7 - i, tb = 6 - i;
            if (t < 64) {
                int tlow = t & ((1 << tb) - 1);
                int s0 = ((t >> tb) << (tb + 2)) | (1 << cb) | tlow;
                int s1 = s0 | (1 << tb);
                float2 tmp = st[s0]; st[s0] = st[s1]; st[s1] = tmp;
            }
            __syncthreads();
        }
    }
    #pragma unroll
    for (int h = 0; h < 2; h++) {
        int s = t + h * 128;
        float2 u = st[s];
        Bq[(long)s * 512 + col]               = __float2half( u.x);
        Bq[(long)s * 512 + 256 + col]         = __float2half(-u.y);
        Bq[(long)(256 + s) * 512 + col]       = __float2half( u.y);
        Bq[(long)(256 + s) * 512 + 256 + col] = __float2half( u.x);
    }
}

// ---------------- product state Psi (split re/im, f16 out) ----------------
__global__ void psi_kernel(const float* __restrict__ ang, __half* __restrict__ psis)
{
    __shared__ float2 sq[NQ][2];
    int row = blockIdx.x;
    int s = threadIdx.x;
    if (s < NQ) {
        float a = ang[(long)row * NQ + s];
        float sn, cs;
        sincosf(0.5f * a, &sn, &cs);
        sq[s][0] = make_float2(cs * cs, -cs * sn);
        sq[s][1] = make_float2(sn * sn, -sn * cs);
    }
    __syncthreads();
    float2 amp = make_float2(1.f, 0.f);
    #pragma unroll
    for (int i = 0; i < NQ; i++) {
        float2 q = sq[i][(s >> (7 - i)) & 1];
        float2 na;
        na.x = amp.x * q.x - amp.y * q.y;
        na.y = amp.x * q.y + amp.y * q.x;
        amp = na;
    }
    psis[(long)row * 512 + s] = __float2half(amp.x);
    psis[(long)row * 512 + 256 + s] = __float2half(amp.y);
}

// ---------------- fused z expectations + x2 = x1 + z @ qout_w^T + qout_b ----
__global__ void zexp_qout_kernel(
    const float* __restrict__ Phis, const float* __restrict__ x1,
    const float* __restrict__ w, const float* __restrict__ b,
    float* __restrict__ out, __half* __restrict__ outh)
{
    __shared__ float partial[8][9];
    __shared__ float zsh[NQ];
    int row = blockIdx.x;
    int s = threadIdx.x;
    float re = Phis[(long)row * 512 + s];
    float im = Phis[(long)row * 512 + 256 + s];
    float p = re * re + im * im;
    int lane = s & 31, wid = s >> 5;
    float vals[NQ];
    #pragma unroll
    for (int i = 0; i < NQ; i++)
        vals[i] = ((s >> (7 - i)) & 1) ? -p : p;
    #pragma unroll
    for (int o = 16; o; o >>= 1)
        #pragma unroll
        for (int i = 0; i < NQ; i++)
            vals[i] += __shfl_xor_sync(0xffffffffu, vals[i], o);
    if (lane == 0)
        #pragma unroll
        for (int i = 0; i < NQ; i++) partial[wid][i] = vals[i];
    __syncthreads();
    if (s < NQ) {
        float acc = 0.f;
        #pragma unroll
        for (int wv = 0; wv < 8; wv++) acc += partial[wv][s];
        zsh[s] = acc;
    }
    __syncthreads();
    float z0 = zsh[0], z1 = zsh[1], z2 = zsh[2], z3 = zsh[3];
    float z4 = zsh[4], z5 = zsh[5], z6 = zsh[6], z7 = zsh[7];
    #pragma unroll
    for (int half_i = 0; half_i < 2; half_i++) {
        int col = s + half_i * 256;
        float4 w0 = *(const float4*)(w + (long)col * NQ);
        float4 w1 = *(const float4*)(w + (long)col * NQ + 4);
        float acc = b[col];
        acc += z0 * w0.x + z1 * w0.y + z2 * w0.z + z3 * w0.w;
        acc += z4 * w1.x + z5 * w1.y + z6 * w1.z + z7 * w1.w;
        long gidx = (long)row * DMODEL + col;
        float val = x1[gidx] + acc;
        out[gidx] = val;
        outh[gidx] = __float2half(val);
    }
}

// ---------------- launch ----------------
extern "C" void kernel_launch(void* const* d_in, const int* in_sizes, int n_in,
                              void* d_out, int out_size)
{
    const float* x          = (const float*)d_in[0];
    const float* attn_in_w  = (const float*)d_in[1];
    const float* attn_in_b  = (const float*)d_in[2];
    const float* attn_out_w = (const float*)d_in[3];
    const float* attn_out_b = (const float*)d_in[4];
    const float* ln1_g      = (const float*)d_in[5];
    const float* ln1_b      = (const float*)d_in[6];
    const float* ln2_g      = (const float*)d_in[7];
    const float* ln2_b      = (const float*)d_in[8];
    const float* ln3_g      = (const float*)d_in[9];
    const float* ln3_b      = (const float*)d_in[10];
    const float* qin_w      = (const float*)d_in[11];
    const float* qin_b      = (const float*)d_in[12];
    const float* qweights   = (const float*)d_in[13];
    const float* qout_w     = (const float*)d_in[14];
    const float* qout_b     = (const float*)d_in[15];
    const float* ffn_w1     = (const float*)d_in[16];
    const float* ffn_b1     = (const float*)d_in[17];
    const float* ffn_w2     = (const float*)d_in[18];
    const float* ffn_b2     = (const float*)d_in[19];
    float* out = (float*)d_out;

    __half *xh, *wih, *woh, *w1h, *w2h, *qkvh, *scoresh, *vTh, *attnch, *uqh,
           *psish, *x2h, *hbufh;
    float  *attnproj, *x1, *angles, *phis, *x2, *ffnout;
    cudaGetSymbolAddress((void**)&xh,       g_xh);
    cudaGetSymbolAddress((void**)&wih,      g_wih);
    cudaGetSymbolAddress((void**)&woh,      g_woh);
    cudaGetSymbolAddress((void**)&w1h,      g_w1h);
    cudaGetSymbolAddress((void**)&w2h,      g_w2h);
    cudaGetSymbolAddress((void**)&qkvh,     g_qkv_h);
    cudaGetSymbolAddress((void**)&scoresh,  g_scores_h);
    cudaGetSymbolAddress((void**)&vTh,      g_vT_h);
    cudaGetSymbolAddress((void**)&attnch,   g_attnc_h);
    cudaGetSymbolAddress((void**)&attnproj, g_attnproj);
    cudaGetSymbolAddress((void**)&x1,       g_x1);
    cudaGetSymbolAddress((void**)&angles,   g_angles);
    cudaGetSymbolAddress((void**)&uqh,      g_uqh);
    cudaGetSymbolAddress((void**)&psish,    g_psis_h);
    cudaGetSymbolAddress((void**)&phis,     g_phis);
    cudaGetSymbolAddress((void**)&x2,       g_x2);
    cudaGetSymbolAddress((void**)&x2h,      g_x2h);
    cudaGetSymbolAddress((void**)&hbufh,    g_hbuf_h);
    cudaGetSymbolAddress((void**)&ffnout,   g_ffnout);

    const float inv_sqrt_hd = 0.08838834764831845f;   // 1/sqrt(128)

    const int SMEM_256 = 4 * (128 * RSTRIDE + 256 * RSTRIDE);   // 122880
    const int SMEM_128 = 4 * (128 * RSTRIDE + 128 * RSTRIDE);   // 81920

    cudaFuncSetAttribute(gemm_h<256, 1, true >, cudaFuncAttributeMaxDynamicSharedMemorySize, SMEM_256);
    cudaFuncSetAttribute(gemm_h<256, 0, true >, cudaFuncAttributeMaxDynamicSharedMemorySize, SMEM_256);
    cudaFuncSetAttribute(gemm_h<128, 0, true >, cudaFuncAttributeMaxDynamicSharedMemorySize, SMEM_128);
    cudaFuncSetAttribute(gemm_h<256, 0, false>, cudaFuncAttributeMaxDynamicSharedMemorySize, SMEM_256);
    cudaFuncSetAttribute(gemm_h<256, 1, false>, cudaFuncAttributeMaxDynamicSharedMemorySize, SMEM_256);
    cudaFuncSetAttribute(gemm_h<256, 2, true >, cudaFuncAttributeMaxDynamicSharedMemorySize, SMEM_256);

    // 0) dtype conversions
    f2h_kernel<<<(ROWS * DMODEL / 4 + 255) / 256, 256>>>(x, xh, ROWS * DMODEL / 4);
    f2h_kernel<<<(1536 * DMODEL / 4 + 255) / 256, 256>>>(attn_in_w, wih, 1536 * DMODEL / 4);
    f2h_kernel<<<(DMODEL * DMODEL / 4 + 255) / 256, 256>>>(attn_out_w, woh, DMODEL * DMODEL / 4);
    f2h_kernel<<<(2048 * DMODEL / 4 + 255) / 256, 256>>>(ffn_w1, w1h, 2048 * DMODEL / 4);
    f2h_kernel<<<(DMODEL * 2048 / 4 + 255) / 256, 256>>>(ffn_w2, w2h, DMODEL * 2048 / 4);

    // 1) qkv = x @ in_w^T + in_b  -> half
    gemm_h<256, 1, true><<<dim3(1536 / 256, ROWS / 128, 1), 256, SMEM_256>>>(
        xh, wih, attn_in_b, qkvh, DMODEL, DMODEL, DMODEL, 1536,
        1, 0, 0, 0, 0, 0, 0, 1.f);

    // 2) scores[bh] = Q K^T / sqrt(hd) -> half (f32 accum)
    gemm_h<256, 0, true><<<dim3(SEQ / 256, SEQ / 128, BATCH * NHEADS), 256, SMEM_256>>>(
        qkvh, qkvh + 512, nullptr, scoresh, HDIM, 1536, 1536, SEQ,
        NHEADS,
        (long)SEQ * 1536, 128,
        (long)SEQ * 1536, 128,
        (long)NHEADS * SEQ * SEQ, (long)SEQ * SEQ,
        inv_sqrt_hd);

    // 3) softmax rows, half in place
    softmax_h_kernel<<<(BATCH * NHEADS * SEQ) / 8, 256>>>(scoresh, BATCH * NHEADS * SEQ);

    // 3b) transpose V -> vT (half)
    transpose_v<<<dim3(SEQ / 32, HDIM / 32, BATCH * NHEADS), dim3(32, 8)>>>(qkvh, vTh);

    // 4) attnc[bh] = P V -> half, concat layout
    gemm_h<128, 0, true><<<dim3(1, SEQ / 128, BATCH * NHEADS), 256, SMEM_128>>>(
        scoresh, vTh, nullptr, attnch, SEQ, SEQ, SEQ, DMODEL,
        NHEADS,
        (long)NHEADS * SEQ * SEQ, (long)SEQ * SEQ,
        (long)NHEADS * HDIM * SEQ, (long)HDIM * SEQ,
        (long)SEQ * DMODEL, 128,
        1.f);

    // 5) attnproj = attnc @ out_w^T + out_b -> f32
    gemm_h<256, 1, false><<<dim3(DMODEL / 256, ROWS / 128, 1), 256, SMEM_256>>>(
        attnch, woh, attn_out_b, attnproj, DMODEL, DMODEL, DMODEL, DMODEL,
        1, 0, 0, 0, 0, 0, 0, 1.f);

    // 6+7+8) fused: x1 = LN1(x+attnproj); angles = LN3(x1) @ qin_w^T + qin_b
    ln13_qin_kernel<<<ROWS / 8, 256>>>(x, attnproj, ln1_g, ln1_b, ln3_g, ln3_b,
                                       qin_w, qin_b, x1, angles);

    // 9) real-ified circuit unitary -> half
    build_u_kernel<<<DIMQ, 128>>>(qweights, uqh);

    // 10) product state Psi -> half
    psi_kernel<<<ROWS, 256>>>(angles, psish);

    // 11) Phi = Psi @ Uq^T -> f32
    gemm_h<256, 0, false><<<dim3(512 / 256, ROWS / 128, 1), 256, SMEM_256>>>(
        psish, uqh, nullptr, phis, 512, 512, 512, 512,
        1, 0, 0, 0, 0, 0, 0, 1.f);

    // 12+13) fused: z expectations + x2 = x1 + z @ qout_w^T + qout_b
    zexp_qout_kernel<<<ROWS, 256>>>(phis, x1, qout_w, qout_b, x2, x2h);

    // 14) hbuf = gelu(x2 @ ffn_w1^T + ffn_b1) -> half
    gemm_h<256, 2, true><<<dim3(2048 / 256, ROWS / 128, 1), 256, SMEM_256>>>(
        x2h, w1h, ffn_b1, hbufh, DMODEL, DMODEL, DMODEL, 2048,
        1, 0, 0, 0, 0, 0, 0, 1.f);

    // 15) ffnout = hbuf @ ffn_w2^T + ffn_b2 -> f32
    gemm_h<256, 1, false><<<dim3(DMODEL / 256, ROWS / 128, 1), 256, SMEM_256>>>(
        hbufh, w2h, ffn_b2, ffnout, 2048, 2048, 2048, DMODEL,
        1, 0, 0, 0, 0, 0, 0, 1.f);

    // 16) out = LN(x2 + ffnout; ln2)
    ln_kernel<<<ROWS / 8, 256>>>(x2, ffnout, ln2_g, ln2_b, out, ROWS);
}

// round 13
// speedup vs baseline: 4.9702x; 1.1808x over previous
#include <cuda_runtime.h>
#include <cuda_fp16.h>
#include <math.h>
#include <stdint.h>

// ---------------- problem constants ----------------
#define ROWS  16384        // B*S = 32*512
#define DMODEL 512
#define NHEADS 4
#define HDIM   128
#define SEQ    512
#define BATCH  32
#define NQ     8
#define DIMQ   256         // 2^8

// ---------------- scratch (static device memory; no allocs) ----------------
__device__ __half g_xh     [ROWS * DMODEL];
__device__ __half g_wih    [1536 * DMODEL];
__device__ __half g_woh    [DMODEL * DMODEL];
__device__ __half g_w1h    [2048 * DMODEL];
__device__ __half g_w2h    [DMODEL * 2048];
__device__ __half g_qkv_h  [ROWS * 1536];
__device__ __half g_attnc_h[ROWS * DMODEL];
__device__ float  g_attnproj[ROWS * DMODEL];
__device__ float  g_x1     [ROWS * DMODEL];
__device__ float  g_angles [ROWS * NQ];
__device__ __half g_uqh    [512 * 512];
__device__ __half g_psis_h [ROWS * 512];
__device__ float  g_phis   [ROWS * 512];
__device__ float  g_x2     [ROWS * DMODEL];
__device__ __half g_x2h    [ROWS * DMODEL];
__device__ __half g_hbuf_h [ROWS * 2048];
__device__ float  g_ffnout [ROWS * DMODEL];

// ---------------- small helpers ----------------
__device__ __forceinline__ float warp_sum(float v) {
    #pragma unroll
    for (int o = 16; o; o >>= 1) v += __shfl_xor_sync(0xffffffffu, v, o);
    return v;
}
__device__ __forceinline__ float gelu_exact(float x) {
    return 0.5f * x * (1.0f + erff(x * 0.7071067811865476f));
}

// ---------------- fp16 tensor-core GEMM (NT) ----------------
// C[m,n] = alpha * sum_k A[m,k] * B[n,k]  (+bias, +gelu per EPI)
// 256 threads, BM=128. STAGES-deep cp.async ring, ldmatrix, mma.m16n8k16.
#define RSTRIDE 80    // bytes per smem row (64 data + 16 pad)

template<int BN, int EPI, bool OHALF, int STAGES, int MINCTA>
__global__ void __launch_bounds__(256, MINCTA) gemm_h(
    const __half* __restrict__ A, const __half* __restrict__ B,
    const float* __restrict__ bias, void* __restrict__ Cv,
    int K, int lda, int ldb, int ldc,
    int nh, long sAb, long sAh, long sBb, long sBh, long sCb, long sCh,
    float alpha)
{
    constexpr int WARPS_M = (BN == 256) ? 2 : 4;
    constexpr int WM = 128 / WARPS_M;
    constexpr int MI = WM / 16;
    constexpr int NI = 8;
    constexpr int ASTAGE = 128 * RSTRIDE;
    constexpr int BSTAGE = BN * RSTRIDE;

    extern __shared__ char smem[];
    const uint32_t tiles = (uint32_t)__cvta_generic_to_shared(smem);

    int bz = blockIdx.z;
    int bb = bz / nh, hh = bz - bb * nh;
    A += bb * sAb + hh * sAh;
    B += bb * sBb + hh * sBh;

    const int tid  = threadIdx.x;
    const int warp = tid >> 5, lane = tid & 31;
    const int wm = warp / (BN / 64), wn = warp % (BN / 64);
    const long rowBase = (long)blockIdx.y * 128;
    const long colBase = (long)blockIdx.x * BN;

    const int aoff_row = wm * WM + (lane & 15);
    const int akb      = ((lane >> 4) & 1) * 16;
    const int boff_n   = wn * 64 + (lane & 7) + ((lane >> 4) & 1) * 8;
    const int bkb      = ((lane >> 3) & 1) * 16;

    float acc[MI][NI][4];
    #pragma unroll
    for (int i = 0; i < MI; i++)
        #pragma unroll
        for (int j = 0; j < NI; j++)
            #pragma unroll
            for (int q = 0; q < 4; q++) acc[i][j][q] = 0.f;

#define CPA16(DST, SRC)                                                        \
    asm volatile("cp.async.cg.shared.global [%0], [%1], 16;" :: "r"(DST), "l"(SRC))

#define ISSUE(STG, T)                                                          \
    {                                                                          \
        uint32_t abase = tiles + (STG) * ASTAGE;                               \
        uint32_t bbase = tiles + STAGES * ASTAGE + (STG) * BSTAGE;             \
        _Pragma("unroll")                                                      \
        for (int it = 0; it < 2; it++) {                                       \
            int idx = tid + it * 256;                                          \
            int r = idx >> 2, c = idx & 3;                                     \
            CPA16(abase + r * RSTRIDE + c * 16,                                \
                  A + (rowBase + r) * lda + (T) * 32 + c * 8);                 \
        }                                                                      \
        _Pragma("unroll")                                                      \
        for (int it = 0; it < BN / 64; it++) {                                 \
            int idx = tid + it * 256;                                          \
            int r = idx >> 2, c = idx & 3;                                     \
            CPA16(bbase + r * RSTRIDE + c * 16,                                \
                  B + (colBase + r) * ldb + (T) * 32 + c * 8);                 \
        }                                                                      \
        asm volatile("cp.async.commit_group;" ::: "memory");                   \
    }

#define COMPUTE(STG)                                                           \
    {                                                                          \
        uint32_t abase = tiles + (STG) * ASTAGE;                               \
        uint32_t bbase = tiles + STAGES * ASTAGE + (STG) * BSTAGE;             \
        _Pragma("unroll")                                                      \
        for (int k16 = 0; k16 < 2; k16++) {                                    \
            uint32_t af[MI][4], bf[NI][2];                                     \
            _Pragma("unroll")                                                  \
            for (int mi = 0; mi < MI; mi++) {                                  \
                uint32_t ad = abase + (aoff_row + mi * 16) * RSTRIDE           \
                            + k16 * 32 + akb;                                  \
                asm volatile(                                                  \
                    "ldmatrix.sync.aligned.m8n8.x4.shared.b16 "                \
                    "{%0,%1,%2,%3}, [%4];"                                     \
                    : "=r"(af[mi][0]), "=r"(af[mi][1]),                        \
                      "=r"(af[mi][2]), "=r"(af[mi][3]) : "r"(ad));             \
            }                                                                  \
            _Pragma("unroll")                                                  \
            for (int p = 0; p < NI / 2; p++) {                                 \
                uint32_t bd = bbase + (boff_n + p * 16) * RSTRIDE              \
                            + k16 * 32 + bkb;                                  \
                asm volatile(                                                  \
                    "ldmatrix.sync.aligned.m8n8.x4.shared.b16 "                \
                    "{%0,%1,%2,%3}, [%4];"                                     \
                    : "=r"(bf[2 * p][0]), "=r"(bf[2 * p][1]),                  \
                      "=r"(bf[2 * p + 1][0]), "=r"(bf[2 * p + 1][1])           \
                    : "r"(bd));                                                \
            }                                                                  \
            _Pragma("unroll")                                                  \
            for (int mi = 0; mi < MI; mi++)                                    \
                _Pragma("unroll")                                              \
                for (int ni = 0; ni < NI; ni++)                                \
                    asm volatile(                                              \
                        "mma.sync.aligned.m16n8k16.row.col.f32.f16.f16.f32 "   \
                        "{%0,%1,%2,%3}, {%4,%5,%6,%7}, {%8,%9}, {%0,%1,%2,%3};"\
                        : "+f"(acc[mi][ni][0]), "+f"(acc[mi][ni][1]),          \
                          "+f"(acc[mi][ni][2]), "+f"(acc[mi][ni][3])           \
                        : "r"(af[mi][0]), "r"(af[mi][1]),                      \
                          "r"(af[mi][2]), "r"(af[mi][3]),                      \
                          "r"(bf[ni][0]), "r"(bf[ni][1]));                     \
        }                                                                      \
    }

    const int NK = K >> 5;          // all call sites have NK >= STAGES
    #pragma unroll
    for (int s = 0; s < STAGES - 1; s++) ISSUE(s, s);

    for (int t = 0; t < NK; t++) {
        if (STAGES == 4) {
            if (t < NK - 2)       asm volatile("cp.async.wait_group 2;" ::: "memory");
            else if (t == NK - 2) asm volatile("cp.async.wait_group 1;" ::: "memory");
            else                  asm volatile("cp.async.wait_group 0;" ::: "memory");
        } else {
            if (t < NK - 1)       asm volatile("cp.async.wait_group 1;" ::: "memory");
            else                  asm volatile("cp.async.wait_group 0;" ::: "memory");
        }
        __syncthreads();
        if (t + STAGES - 1 < NK) ISSUE((t + STAGES - 1) % STAGES, t + STAGES - 1);
        COMPUTE(t % STAGES);
    }

    // epilogue
    float* Cf = (float*)Cv;
    __half* Ch = (__half*)Cv;
    const long cadd = bb * sCb + hh * sCh;
    #pragma unroll
    for (int mi = 0; mi < MI; mi++) {
        long row = rowBase + wm * WM + mi * 16 + (lane >> 2);
        #pragma unroll
        for (int ni = 0; ni < NI; ni++) {
            long col = colBase + wn * 64 + ni * 8 + (lane & 3) * 2;
            float2 v0, v1;
            v0.x = acc[mi][ni][0] * alpha; v0.y = acc[mi][ni][1] * alpha;
            v1.x = acc[mi][ni][2] * alpha; v1.y = acc[mi][ni][3] * alpha;
            if (EPI >= 1) {
                float2 bv = *(const float2*)(bias + col);
                v0.x += bv.x; v0.y += bv.y; v1.x += bv.x; v1.y += bv.y;
            }
            if (EPI == 2) {
                v0.x = gelu_exact(v0.x); v0.y = gelu_exact(v0.y);
                v1.x = gelu_exact(v1.x); v1.y = gelu_exact(v1.y);
            }
            if (OHALF) {
                *(__half2*)(Ch + cadd + row * ldc + col) = __floats2half2_rn(v0.x, v0.y);
                *(__half2*)(Ch + cadd + (row + 8) * ldc + col) = __floats2half2_rn(v1.x, v1.y);
            } else {
                *(float2*)(Cf + cadd + row * ldc + col) = v0;
                *(float2*)(Cf + cadd + (row + 8) * ldc + col) = v1;
            }
        }
    }
#undef CPA16
#undef ISSUE
#undef COMPUTE
}

// ---------------- fused flash attention ----------------
// grid (bh=128, qt=4), 256 threads. Q tile resident; K/V double-buffered.
// Each warp: 16 q-rows; online softmax in fp32; P->fp16 regs feed PV mma.
#define FSTRIDE 272   // 128 halves (256B) + 16B pad

__global__ void __launch_bounds__(256) flash_attn(
    const __half* __restrict__ qkv, __half* __restrict__ attnc)
{
    extern __shared__ char smem[];
    const uint32_t Qs = (uint32_t)__cvta_generic_to_shared(smem);
    const uint32_t Ks = Qs + 128 * FSTRIDE;
    const uint32_t Vs = Ks + 2 * 128 * FSTRIDE;

    const int bh = blockIdx.x;
    const int qt = blockIdx.y;
    const int b = bh >> 2, h = bh & 3;
    const int tid = threadIdx.x, warp = tid >> 5, lane = tid & 31;
    const int g = lane >> 2, tq = lane & 3;

    const __half* Qg = qkv + (long)(b * 512 + qt * 128) * 1536 + h * 128;
    const __half* Kg = qkv + (long)(b * 512) * 1536 + 512 + h * 128;
    const __half* Vg = qkv + (long)(b * 512) * 1536 + 1024 + h * 128;

#define CPA16F(DST, SRC)                                                       \
    asm volatile("cp.async.cg.shared.global [%0], [%1], 16;" :: "r"(DST), "l"(SRC))

    // Q load (group 0)
    #pragma unroll
    for (int it = 0; it < 8; it++) {
        int idx = tid + it * 256;
        int r = idx >> 4, c = idx & 15;
        CPA16F(Qs + r * FSTRIDE + c * 16, Qg + (long)r * 1536 + c * 8);
    }
    asm volatile("cp.async.commit_group;" ::: "memory");

#define LOAD_KV(J, BB)                                                         \
    {                                                                          \
        uint32_t kb = Ks + (BB) * 128 * FSTRIDE;                               \
        uint32_t vb = Vs + (BB) * 128 * FSTRIDE;                               \
        _Pragma("unroll")                                                      \
        for (int it = 0; it < 8; it++) {                                       \
            int idx = tid + it * 256;                                          \
            int r = idx >> 4, c = idx & 15;                                    \
            CPA16F(kb + r * FSTRIDE + c * 16,                                  \
                   Kg + (long)((J) * 128 + r) * 1536 + c * 8);                 \
        }                                                                      \
        _Pragma("unroll")                                                      \
        for (int it = 0; it < 8; it++) {                                       \
            int idx = tid + it * 256;                                          \
            int r = idx >> 4, c = idx & 15;                                    \
            CPA16F(vb + r * FSTRIDE + c * 16,                                  \
                   Vg + (long)((J) * 128 + r) * 1536 + c * 8);                 \
        }                                                                      \
        asm volatile("cp.async.commit_group;" ::: "memory");                   \
    }

    LOAD_KV(0, 0);
    LOAD_KV(1, 1);

    const int aoff_row = warp * 16 + (lane & 15);
    const int akb      = ((lane >> 4) & 1) * 16;
    const int boff_n   = (lane & 7) + ((lane >> 4) & 1) * 8;
    const int bkb      = ((lane >> 3) & 1) * 16;

    float oacc[16][4];
    #pragma unroll
    for (int i = 0; i < 16; i++)
        #pragma unroll
        for (int q = 0; q < 4; q++) oacc[i][q] = 0.f;
    float m0 = -3.4e38f, m1 = -3.4e38f, l0 = 0.f, l1 = 0.f;
    const float scale = 0.08838834764831845f;

    for (int j = 0; j < 4; j++) {
        if (j < 3) asm volatile("cp.async.wait_group 1;" ::: "memory");
        else       asm volatile("cp.async.wait_group 0;" ::: "memory");
        __syncthreads();
        const uint32_t Kb = Ks + (j & 1) * 128 * FSTRIDE;
        const uint32_t Vb = Vs + (j & 1) * 128 * FSTRIDE;

        // ---- S = Q K^T for this 128-key tile ----
        float sacc[16][4];
        #pragma unroll
        for (int i = 0; i < 16; i++)
            #pragma unroll
            for (int q = 0; q < 4; q++) sacc[i][q] = 0.f;

        #pragma unroll
        for (int kk = 0; kk < 8; kk++) {
            uint32_t af[4];
            uint32_t ad = Qs + aoff_row * FSTRIDE + kk * 32 + akb;
            asm volatile("ldmatrix.sync.aligned.m8n8.x4.shared.b16 {%0,%1,%2,%3}, [%4];"
                : "=r"(af[0]), "=r"(af[1]), "=r"(af[2]), "=r"(af[3]) : "r"(ad));
            uint32_t bf[16][2];
            #pragma unroll
            for (int p = 0; p < 8; p++) {
                uint32_t bd = Kb + (boff_n + p * 16) * FSTRIDE + kk * 32 + bkb;
                asm volatile("ldmatrix.sync.aligned.m8n8.x4.shared.b16 {%0,%1,%2,%3}, [%4];"
                    : "=r"(bf[2 * p][0]), "=r"(bf[2 * p][1]),
                      "=r"(bf[2 * p + 1][0]), "=r"(bf[2 * p + 1][1]) : "r"(bd));
            }
            #pragma unroll
            for (int ni = 0; ni < 16; ni++)
                asm volatile(
                    "mma.sync.aligned.m16n8k16.row.col.f32.f16.f16.f32 "
                    "{%0,%1,%2,%3}, {%4,%5,%6,%7}, {%8,%9}, {%0,%1,%2,%3};"
                    : "+f"(sacc[ni][0]), "+f"(sacc[ni][1]),
                      "+f"(sacc[ni][2]), "+f"(sacc[ni][3])
                    : "r"(af[0]), "r"(af[1]), "r"(af[2]), "r"(af[3]),
                      "r"(bf[ni][0]), "r"(bf[ni][1]));
        }

        // ---- online softmax ----
        float mt0 = -3.4e38f, mt1 = -3.4e38f;
        #pragma unroll
        for (int ni = 0; ni < 16; ni++) {
            #pragma unroll
            for (int q = 0; q < 4; q++) sacc[ni][q] *= scale;
            mt0 = fmaxf(mt0, fmaxf(sacc[ni][0], sacc[ni][1]));
            mt1 = fmaxf(mt1, fmaxf(sacc[ni][2], sacc[ni][3]));
        }
        mt0 = fmaxf(mt0, __shfl_xor_sync(0xffffffffu, mt0, 1));
        mt0 = fmaxf(mt0, __shfl_xor_sync(0xffffffffu, mt0, 2));
        mt1 = fmaxf(mt1, __shfl_xor_sync(0xffffffffu, mt1, 1));
        mt1 = fmaxf(mt1, __shfl_xor_sync(0xffffffffu, mt1, 2));
        float mn0 = fmaxf(m0, mt0), mn1 = fmaxf(m1, mt1);
        float al0 = __expf(m0 - mn0), al1 = __expf(m1 - mn1);
        m0 = mn0; m1 = mn1;
        l0 *= al0; l1 *= al1;
        #pragma unroll
        for (int ni = 0; ni < 16; ni++) {
            oacc[ni][0] *= al0; oacc[ni][1] *= al0;
            oacc[ni][2] *= al1; oacc[ni][3] *= al1;
        }
        uint32_t ph[16][2];
        #pragma unroll
        for (int ni = 0; ni < 16; ni++) {
            float p0 = __expf(sacc[ni][0] - mn0);
            float p1 = __expf(sacc[ni][1] - mn0);
            float p2 = __expf(sacc[ni][2] - mn1);
            float p3 = __expf(sacc[ni][3] - mn1);
            l0 += p0 + p1; l1 += p2 + p3;
            __half2 h0 = __floats2half2_rn(p0, p1);
            __half2 h1 = __floats2half2_rn(p2, p3);
            ph[ni][0] = *reinterpret_cast<uint32_t*>(&h0);
            ph[ni][1] = *reinterpret_cast<uint32_t*>(&h1);
        }

        // ---- O += P V ----
        #pragma unroll
        for (int kk = 0; kk < 8; kk++) {
            uint32_t a0 = ph[2 * kk][0], a1 = ph[2 * kk][1];
            uint32_t a2 = ph[2 * kk + 1][0], a3 = ph[2 * kk + 1][1];
            #pragma unroll
            for (int p = 0; p < 8; p++) {
                uint32_t vb0, vb1, vb2, vb3;
                uint32_t vd = Vb + (kk * 16 + (lane & 15)) * FSTRIDE
                            + p * 32 + ((lane >> 4) & 1) * 16;
                asm volatile("ldmatrix.sync.aligned.m8n8.x4.trans.shared.b16 {%0,%1,%2,%3}, [%4];"
                    : "=r"(vb0), "=r"(vb1), "=r"(vb2), "=r"(vb3) : "r"(vd));
                asm volatile(
                    "mma.sync.aligned.m16n8k16.row.col.f32.f16.f16.f32 "
                    "{%0,%1,%2,%3}, {%4,%5,%6,%7}, {%8,%9}, {%0,%1,%2,%3};"
                    : "+f"(oacc[2 * p][0]), "+f"(oacc[2 * p][1]),
                      "+f"(oacc[2 * p][2]), "+f"(oacc[2 * p][3])
                    : "r"(a0), "r"(a1), "r"(a2), "r"(a3), "r"(vb0), "r"(vb1));
                asm volatile(
                    "mma.sync.aligned.m16n8k16.row.col.f32.f16.f16.f32 "
                    "{%0,%1,%2,%3}, {%4,%5,%6,%7}, {%8,%9}, {%0,%1,%2,%3};"
                    : "+f"(oacc[2 * p + 1][0]), "+f"(oacc[2 * p + 1][1]),
                      "+f"(oacc[2 * p + 1][2]), "+f"(oacc[2 * p + 1][3])
                    : "r"(a0), "r"(a1), "r"(a2), "r"(a3), "r"(vb2), "r"(vb3));
            }
        }
        __syncthreads();
        if (j + 2 < 4) LOAD_KV(j + 2, j & 1);
    }

    // final normalize + store
    l0 += __shfl_xor_sync(0xffffffffu, l0, 1);
    l0 += __shfl_xor_sync(0xffffffffu, l0, 2);
    l1 += __shfl_xor_sync(0xffffffffu, l1, 1);
    l1 += __shfl_xor_sync(0xffffffffu, l1, 2);
    float inv0 = 1.f / l0, inv1 = 1.f / l1;
    long rowg = (long)(b * 512 + qt * 128 + warp * 16 + g);
    #pragma unroll
    for (int ni = 0; ni < 16; ni++) {
        long col = h * 128 + ni * 8 + tq * 2;
        *(__half2*)(attnc + rowg * DMODEL + col) =
            __floats2half2_rn(oacc[ni][0] * inv0, oacc[ni][1] * inv0);
        *(__half2*)(attnc + (rowg + 8) * DMODEL + col) =
            __floats2half2_rn(oacc[ni][2] * inv1, oacc[ni][3] * inv1);
    }
#undef CPA16F
#undef LOAD_KV
}

// ---------------- f32 -> f16 convert ----------------
__global__ void f2h_kernel(const float* __restrict__ in, __half* __restrict__ out, long n4)
{
    long i = blockIdx.x * 256 + threadIdx.x;
    if (i >= n4) return;
    float4 v = *(const float4*)(in + i * 4);
    __half2* o = (__half2*)(out + i * 4);
    o[0] = __floats2half2_rn(v.x, v.y);
    o[1] = __floats2half2_rn(v.z, v.w);
}

// ---------------- LayerNorm (f32), generic ----------------
__global__ void ln_kernel(const float* __restrict__ A, const float* __restrict__ R,
                          const float* __restrict__ g, const float* __restrict__ b,
                          float* __restrict__ out, int nrows)
{
    int warp = (blockIdx.x * blockDim.x + threadIdx.x) >> 5;
    int lane = threadIdx.x & 31;
    if (warp >= nrows) return;
    const float* a = A + (long)warp * DMODEL;
    float4 v[4];
    float s = 0.f;
    #pragma unroll
    for (int t = 0; t < 4; t++) {
        int c = (t * 32 + lane) * 4;
        v[t] = *(const float4*)(a + c);
        if (R) {
            float4 r4 = *(const float4*)(R + (long)warp * DMODEL + c);
            v[t].x += r4.x; v[t].y += r4.y; v[t].z += r4.z; v[t].w += r4.w;
        }
        s += v[t].x + v[t].y + v[t].z + v[t].w;
    }
    s = warp_sum(s);
    float mean = s * (1.f / DMODEL);
    float vs = 0.f;
    #pragma unroll
    for (int t = 0; t < 4; t++) {
        float dx = v[t].x - mean, dy = v[t].y - mean, dz = v[t].z - mean, dw = v[t].w - mean;
        vs += dx * dx + dy * dy + dz * dz + dw * dw;
    }
    vs = warp_sum(vs);
    float rstd = rsqrtf(vs * (1.f / DMODEL) + 1e-5f);
    #pragma unroll
    for (int t = 0; t < 4; t++) {
        int c = (t * 32 + lane) * 4;
        float4 gv = *(const float4*)(g + c);
        float4 bv = *(const float4*)(b + c);
        float4 o;
        o.x = (v[t].x - mean) * rstd * gv.x + bv.x;
        o.y = (v[t].y - mean) * rstd * gv.y + bv.y;
        o.z = (v[t].z - mean) * rstd * gv.z + bv.z;
        o.w = (v[t].w - mean) * rstd * gv.w + bv.w;
        *(float4*)(out + (long)warp * DMODEL + c) = o;
    }
}

// ---------------- fused LN1 -> x1, LN3 (regs), qin angles ----------------
__global__ void ln13_qin_kernel(
    const float* __restrict__ X, const float* __restrict__ R,
    const float* __restrict__ g1, const float* __restrict__ b1,
    const float* __restrict__ g3, const float* __restrict__ b3,
    const float* __restrict__ qw, const float* __restrict__ qb,
    float* __restrict__ x1out, float* __restrict__ ang)
{
    int row = (blockIdx.x * blockDim.x + threadIdx.x) >> 5;
    int lane = threadIdx.x & 31;
    if (row >= ROWS) return;
    const float* a = X + (long)row * DMODEL;
    const float* r = R + (long)row * DMODEL;
    float4 v[4];
    float s = 0.f;
    #pragma unroll
    for (int t = 0; t < 4; t++) {
        int c = (t * 32 + lane) * 4;
        v[t] = *(const float4*)(a + c);
        float4 r4 = *(const float4*)(r + c);
        v[t].x += r4.x; v[t].y += r4.y; v[t].z += r4.z; v[t].w += r4.w;
        s += v[t].x + v[t].y + v[t].z + v[t].w;
    }
    s = warp_sum(s);
    float mean = s * (1.f / DMODEL);
    float vs = 0.f;
    #pragma unroll
    for (int t = 0; t < 4; t++) {
        float dx = v[t].x - mean, dy = v[t].y - mean, dz = v[t].z - mean, dw = v[t].w - mean;
        vs += dx * dx + dy * dy + dz * dz + dw * dw;
    }
    vs = warp_sum(vs);
    float rstd = rsqrtf(vs * (1.f / DMODEL) + 1e-5f);

    float s3 = 0.f;
    #pragma unroll
    for (int t = 0; t < 4; t++) {
        int c = (t * 32 + lane) * 4;
        float4 gv = *(const float4*)(g1 + c);
        float4 bv = *(const float4*)(b1 + c);
        v[t].x = (v[t].x - mean) * rstd * gv.x + bv.x;
        v[t].y = (v[t].y - mean) * rstd * gv.y + bv.y;
        v[t].z = (v[t].z - mean) * rstd * gv.z + bv.z;
        v[t].w = (v[t].w - mean) * rstd * gv.w + bv.w;
        *(float4*)(x1out + (long)row * DMODEL + c) = v[t];
        s3 += v[t].x + v[t].y + v[t].z + v[t].w;
    }
    s3 = warp_sum(s3);
    float mean3 = s3 * (1.f / DMODEL);
    float vs3 = 0.f;
    #pragma unroll
    for (int t = 0; t < 4; t++) {
        float dx = v[t].x - mean3, dy = v[t].y - mean3, dz = v[t].z - mean3, dw = v[t].w - mean3;
        vs3 += dx * dx + dy * dy + dz * dz + dw * dw;
    }
    vs3 = warp_sum(vs3);
    float rstd3 = rsqrtf(vs3 * (1.f / DMODEL) + 1e-5f);
    #pragma unroll
    for (int t = 0; t < 4; t++) {
        int c = (t * 32 + lane) * 4;
        float4 gv = *(const float4*)(g3 + c);
        float4 bv = *(const float4*)(b3 + c);
        v[t].x = (v[t].x - mean3) * rstd3 * gv.x + bv.x;
        v[t].y = (v[t].y - mean3) * rstd3 * gv.y + bv.y;
        v[t].z = (v[t].z - mean3) * rstd3 * gv.z + bv.z;
        v[t].w = (v[t].w - mean3) * rstd3 * gv.w + bv.w;
    }
    float myang = 0.f;
    #pragma unroll
    for (int o = 0; o < NQ; o++) {
        const float* wr = qw + o * DMODEL;
        float p = 0.f;
        #pragma unroll
        for (int t = 0; t < 4; t++) {
            int c = (t * 32 + lane) * 4;
            float4 wv = *(const float4*)(wr + c);
            p += v[t].x * wv.x + v[t].y * wv.y + v[t].z * wv.z + v[t].w * wv.w;
        }
        p = warp_sum(p);
        if (lane == o) myang = p + qb[o];
    }
    if (lane < NQ) ang[(long)row * NQ + lane] = myang;
}

// ---------------- build real-ified circuit unitary (f16 out, 512x512) -------
__global__ void build_u_kernel(const float* __restrict__ qw, __half* __restrict__ Bq)
{
    __shared__ float2 st[DIMQ];
    int col = blockIdx.x;
    int t = threadIdx.x;
    st[t] = make_float2(0.f, 0.f);
    st[t + 128] = make_float2(0.f, 0.f);
    __syncthreads();
    if (t == 0) st[col] = make_float2(1.f, 0.f);
    __syncthreads();

    for (int l = 0; l < 4; l++) {
        for (int i = 0; i < NQ; i++) {
            float w0 = qw[(l * 2 + 0) * NQ + i];
            float w1 = qw[(l * 2 + 1) * NQ + i];
            float sn, cs, sn2, cs2;
            sincosf(0.5f * w0, &sn, &cs);
            sincosf(0.5f * w1, &sn2, &cs2);
            float2 M00 = make_float2( cs * cs2, -cs * sn2);
            float2 M01 = make_float2(-sn * sn2, -sn * cs2);
            float2 M10 = make_float2( sn * sn2, -sn * cs2);
            float2 M11 = make_float2( cs * cs2,  cs * sn2);
            int bpos = 7 - i;
            int lowmask = (1 << bpos) - 1;
            int s0 = ((t >> bpos) << (bpos + 1)) | (t & lowmask);
            int s1 = s0 | (1 << bpos);
            float2 a0 = st[s0], a1 = st[s1];
            float2 n0, n1;
            n0.x = M00.x * a0.x - M00.y * a0.y + M01.x * a1.x - M01.y * a1.y;
            n0.y = M00.x * a0.y + M00.y * a0.x + M01.x * a1.y + M01.y * a1.x;
            n1.x = M10.x * a0.x - M10.y * a0.y + M11.x * a1.x - M11.y * a1.y;
            n1.y = M10.x * a0.y + M10.y * a0.x + M11.x * a1.y + M11.y * a1.x;
            st[s0] = n0; st[s1] = n1;
            __syncthreads();
        }
        for (int i = 0; i < NQ - 1; i++) {
            int cb = 7 - i, tb = 6 - i;
            if (t < 64) {
                int tlow = t & ((1 << tb) - 1);
                int s0 = ((t >> tb) << (tb + 2)) | (1 << cb) | tlow;
                int s1 = s0 | (1 << tb);
                float2 tmp = st[s0]; st[s0] = st[s1]; st[s1] = tmp;
            }
            __syncthreads();
        }
    }
    #pragma unroll
    for (int h = 0; h < 2; h++) {
        int s = t + h * 128;
        float2 u = st[s];
        Bq[(long)s * 512 + col]               = __float2half( u.x);
        Bq[(long)s * 512 + 256 + col]         = __float2half(-u.y);
        Bq[(long)(256 + s) * 512 + col]       = __float2half( u.y);
        Bq[(long)(256 + s) * 512 + 256 + col] = __float2half( u.x);
    }
}

// ---------------- product state Psi (split re/im, f16 out) ----------------
__global__ void psi_kernel(const float* __restrict__ ang, __half* __restrict__ psis)
{
    __shared__ float2 sq[NQ][2];
    int row = blockIdx.x;
    int s = threadIdx.x;
    if (s < NQ) {
        float a = ang[(long)row * NQ + s];
        float sn, cs;
        sincosf(0.5f * a, &sn, &cs);
        sq[s][0] = make_float2(cs * cs, -cs * sn);
        sq[s][1] = make_float2(sn * sn, -sn * cs);
    }
    __syncthreads();
    float2 amp = make_float2(1.f, 0.f);
    #pragma unroll
    for (int i = 0; i < NQ; i++) {
        float2 q = sq[i][(s >> (7 - i)) & 1];
        float2 na;
        na.x = amp.x * q.x - amp.y * q.y;
        na.y = amp.x * q.y + amp.y * q.x;
        amp = na;
    }
    psis[(long)row * 512 + s] = __float2half(amp.x);
    psis[(long)row * 512 + 256 + s] = __float2half(amp.y);
}

// ---------------- fused z expectations + x2 = x1 + z @ qout_w^T + qout_b ----
__global__ void zexp_qout_kernel(
    const float* __restrict__ Phis, const float* __restrict__ x1,
    const float* __restrict__ w, const float* __restrict__ b,
    float* __restrict__ out, __half* __restrict__ outh)
{
    __shared__ float partial[8][9];
    __shared__ float zsh[NQ];
    int row = blockIdx.x;
    int s = threadIdx.x;
    float re = Phis[(long)row * 512 + s];
    float im = Phis[(long)row * 512 + 256 + s];
    float p = re * re + im * im;
    int lane = s & 31, wid = s >> 5;
    float vals[NQ];
    #pragma unroll
    for (int i = 0; i < NQ; i++)
        vals[i] = ((s >> (7 - i)) & 1) ? -p : p;
    #pragma unroll
    for (int o = 16; o; o >>= 1)
        #pragma unroll
        for (int i = 0; i < NQ; i++)
            vals[i] += __shfl_xor_sync(0xffffffffu, vals[i], o);
    if (lane == 0)
        #pragma unroll
        for (int i = 0; i < NQ; i++) partial[wid][i] = vals[i];
    __syncthreads();
    if (s < NQ) {
        float acc = 0.f;
        #pragma unroll
        for (int wv = 0; wv < 8; wv++) acc += partial[wv][s];
        zsh[s] = acc;
    }
    __syncthreads();
    float z0 = zsh[0], z1 = zsh[1], z2 = zsh[2], z3 = zsh[3];
    float z4 = zsh[4], z5 = zsh[5], z6 = zsh[6], z7 = zsh[7];
    #pragma unroll
    for (int half_i = 0; half_i < 2; half_i++) {
        int col = s + half_i * 256;
        float4 w0 = *(const float4*)(w + (long)col * NQ);
        float4 w1 = *(const float4*)(w + (long)col * NQ + 4);
        float acc = b[col];
        acc += z0 * w0.x + z1 * w0.y + z2 * w0.z + z3 * w0.w;
        acc += z4 * w1.x + z5 * w1.y + z6 * w1.z + z7 * w1.w;
        long gidx = (long)row * DMODEL + col;
        float val = x1[gidx] + acc;
        out[gidx] = val;
        outh[gidx] = __float2half(val);
    }
}

// ---------------- launch ----------------
extern "C" void kernel_launch(void* const* d_in, const int* in_sizes, int n_in,
                              void* d_out, int out_size)
{
    const float* x          = (const float*)d_in[0];
    const float* attn_in_w  = (const float*)d_in[1];
    const float* attn_in_b  = (const float*)d_in[2];
    const float* attn_out_w = (const float*)d_in[3];
    const float* attn_out_b = (const float*)d_in[4];
    const float* ln1_g      = (const float*)d_in[5];
    const float* ln1_b      = (const float*)d_in[6];
    const float* ln2_g      = (const float*)d_in[7];
    const float* ln2_b      = (const float*)d_in[8];
    const float* ln3_g      = (const float*)d_in[9];
    const float* ln3_b      = (const float*)d_in[10];
    const float* qin_w      = (const float*)d_in[11];
    const float* qin_b      = (const float*)d_in[12];
    const float* qweights   = (const float*)d_in[13];
    const float* qout_w     = (const float*)d_in[14];
    const float* qout_b     = (const float*)d_in[15];
    const float* ffn_w1     = (const float*)d_in[16];
    const float* ffn_b1     = (const float*)d_in[17];
    const float* ffn_w2     = (const float*)d_in[18];
    const float* ffn_b2     = (const float*)d_in[19];
    float* out = (float*)d_out;

    __half *xh, *wih, *woh, *w1h, *w2h, *qkvh, *attnch, *uqh, *psish, *x2h, *hbufh;
    float  *attnproj, *x1, *angles, *phis, *x2, *ffnout;
    cudaGetSymbolAddress((void**)&xh,       g_xh);
    cudaGetSymbolAddress((void**)&wih,      g_wih);
    cudaGetSymbolAddress((void**)&woh,      g_woh);
    cudaGetSymbolAddress((void**)&w1h,      g_w1h);
    cudaGetSymbolAddress((void**)&w2h,      g_w2h);
    cudaGetSymbolAddress((void**)&qkvh,     g_qkv_h);
    cudaGetSymbolAddress((void**)&attnch,   g_attnc_h);
    cudaGetSymbolAddress((void**)&attnproj, g_attnproj);
    cudaGetSymbolAddress((void**)&x1,       g_x1);
    cudaGetSymbolAddress((void**)&angles,   g_angles);
    cudaGetSymbolAddress((void**)&uqh,      g_uqh);
    cudaGetSymbolAddress((void**)&psish,    g_psis_h);
    cudaGetSymbolAddress((void**)&phis,     g_phis);
    cudaGetSymbolAddress((void**)&x2,       g_x2);
    cudaGetSymbolAddress((void**)&x2h,      g_x2h);
    cudaGetSymbolAddress((void**)&hbufh,    g_hbuf_h);
    cudaGetSymbolAddress((void**)&ffnout,   g_ffnout);

    const int SMEM_G  = 3 * (128 * RSTRIDE + 128 * RSTRIDE);   // 61440
    const int SMEM_FA = 5 * 128 * FSTRIDE;                     // 174080

    cudaFuncSetAttribute(gemm_h<128, 1, true , 3, 2>, cudaFuncAttributeMaxDynamicSharedMemorySize, SMEM_G);
    cudaFuncSetAttribute(gemm_h<128, 1, false, 3, 2>, cudaFuncAttributeMaxDynamicSharedMemorySize, SMEM_G);
    cudaFuncSetAttribute(gemm_h<128, 0, false, 3, 2>, cudaFuncAttributeMaxDynamicSharedMemorySize, SMEM_G);
    cudaFuncSetAttribute(gemm_h<128, 2, true , 3, 2>, cudaFuncAttributeMaxDynamicSharedMemorySize, SMEM_G);
    cudaFuncSetAttribute(flash_attn, cudaFuncAttributeMaxDynamicSharedMemorySize, SMEM_FA);

    // 0) dtype conversions
    f2h_kernel<<<(ROWS * DMODEL / 4 + 255) / 256, 256>>>(x, xh, ROWS * DMODEL / 4);
    f2h_kernel<<<(1536 * DMODEL / 4 + 255) / 256, 256>>>(attn_in_w, wih, 1536 * DMODEL / 4);
    f2h_kernel<<<(DMODEL * DMODEL / 4 + 255) / 256, 256>>>(attn_out_w, woh, DMODEL * DMODEL / 4);
    f2h_kernel<<<(2048 * DMODEL / 4 + 255) / 256, 256>>>(ffn_w1, w1h, 2048 * DMODEL / 4);
    f2h_kernel<<<(DMODEL * 2048 / 4 + 255) / 256, 256>>>(ffn_w2, w2h, DMODEL * 2048 / 4);

    // 1) qkv = x @ in_w^T + in_b  -> half
    gemm_h<128, 1, true, 3, 2><<<dim3(1536 / 128, ROWS / 128, 1), 256, SMEM_G>>>(
        xh, wih, attn_in_b, qkvh, DMODEL, DMODEL, DMODEL, 1536,
        1, 0, 0, 0, 0, 0, 0, 1.f);

    // 2-4) fused attention: QK^T, softmax, PV -> attnc (half, concat layout)
    flash_attn<<<dim3(BATCH * NHEADS, SEQ / 128), 256, SMEM_FA>>>(qkvh, attnch);

    // 5) attnproj = attnc @ out_w^T + out_b -> f32
    gemm_h<128, 1, false, 3, 2><<<dim3(DMODEL / 128, ROWS / 128, 1), 256, SMEM_G>>>(
        attnch, woh, attn_out_b, attnproj, DMODEL, DMODEL, DMODEL, DMODEL,
        1, 0, 0, 0, 0, 0, 0, 1.f);

    // 6+7+8) fused: x1 = LN1(x+attnproj); angles = LN3(x1) @ qin_w^T + qin_b
    ln13_qin_kernel<<<ROWS / 8, 256>>>(x, attnproj, ln1_g, ln1_b, ln3_g, ln3_b,
                                       qin_w, qin_b, x1, angles);

    // 9) real-ified circuit unitary -> half
    build_u_kernel<<<DIMQ, 128>>>(qweights, uqh);

    // 10) product state Psi -> half
    psi_kernel<<<ROWS, 256>>>(angles, psish);

    // 11) Phi = Psi @ Uq^T -> f32
    gemm_h<128, 0, false, 3, 2><<<dim3(512 / 128, ROWS / 128, 1), 256, SMEM_G>>>(
        psish, uqh, nullptr, phis, 512, 512, 512, 512,
        1, 0, 0, 0, 0, 0, 0, 1.f);

    // 12+13) fused: z expectations + x2 = x1 + z @ qout_w^T + qout_b
    zexp_qout_kernel<<<ROWS, 256>>>(phis, x1, qout_w, qout_b, x2, x2h);

    // 14) hbuf = gelu(x2 @ ffn_w1^T + ffn_b1) -> half
    gemm_h<128, 2, true, 3, 2><<<dim3(2048 / 128, ROWS / 128, 1), 256, SMEM_G>>>(
        x2h, w1h, ffn_b1, hbufh, DMODEL, DMODEL, DMODEL, 2048,
        1, 0, 0, 0, 0, 0, 0, 1.f);

    // 15) ffnout = hbuf @ ffn_w2^T + ffn_b2 -> f32
    gemm_h<128, 1, false, 3, 2><<<dim3(DMODEL / 128, ROWS / 128, 1), 256, SMEM_G>>>(
        hbufh, w2h, ffn_b2, ffnout, 2048, 2048, 2048, DMODEL,
        1, 0, 0, 0, 0, 0, 0, 1.f);

    // 16) out = LN(x2 + ffnout; ln2)
    ln_kernel<<<ROWS / 8, 256>>>(x2, ffnout, ln2_g, ln2_b, out, ROWS);
}

// round 14
// speedup vs baseline: 5.2261x; 1.0515x over previous
#include <cuda_runtime.h>
#include <cuda_fp16.h>
#include <math.h>
#include <stdint.h>

// ---------------- problem constants ----------------
#define ROWS  16384        // B*S = 32*512
#define DMODEL 512
#define NHEADS 4
#define HDIM   128
#define SEQ    512
#define BATCH  32
#define NQ     8
#define DIMQ   256         // 2^8

// ---------------- scratch (static device memory; no allocs) ----------------
__device__ __half g_xh     [ROWS * DMODEL];
__device__ __half g_wih    [1536 * DMODEL];
__device__ __half g_woh    [DMODEL * DMODEL];
__device__ __half g_w1h    [2048 * DMODEL];
__device__ __half g_w2h    [DMODEL * 2048];
__device__ __half g_qkv_h  [ROWS * 1536];
__device__ __half g_attnc_h[ROWS * DMODEL];
__device__ float  g_xsum   [ROWS * DMODEL];   // x + attnproj (fused epilogue)
__device__ float  g_x1     [ROWS * DMODEL];
__device__ float  g_angles [ROWS * NQ];
__device__ __half g_uqh    [512 * 512];
__device__ __half g_psis_h [ROWS * 512];
__device__ float  g_phis   [ROWS * 512];
__device__ float  g_x2     [ROWS * DMODEL];
__device__ __half g_x2h    [ROWS * DMODEL];
__device__ __half g_hbuf_h [ROWS * 2048];
__device__ float  g_ffnsum [ROWS * DMODEL];   // x2 + ffnout (fused epilogue)

// ---------------- small helpers ----------------
__device__ __forceinline__ float warp_sum(float v) {
    #pragma unroll
    for (int o = 16; o; o >>= 1) v += __shfl_xor_sync(0xffffffffu, v, o);
    return v;
}
__device__ __forceinline__ float gelu_exact(float x) {
    return 0.5f * x * (1.0f + erff(x * 0.7071067811865476f));
}

// ---------------- fp16 tensor-core GEMM (NT) ----------------
// C[m,n] = alpha * sum_k A[m,k] * B[n,k]
// EPI: 0 none, 1 +bias, 2 +bias+gelu, 3 +bias+residual(f32)
// 256 threads, BM=128, BN=128, BK=64 halves. 3-stage cp.async ring.
#define RSTRIDE 144   // bytes per smem row (128 data + 16 pad); LDSM conflict-free

template<int BN, int EPI, bool OHALF, int STAGES, int MINCTA>
__global__ void __launch_bounds__(256, MINCTA) gemm_h(
    const __half* __restrict__ A, const __half* __restrict__ B,
    const float* __restrict__ bias, const float* __restrict__ res,
    void* __restrict__ Cv,
    int K, int lda, int ldb, int ldc,
    int nh, long sAb, long sAh, long sBb, long sBh, long sCb, long sCh,
    float alpha)
{
    constexpr int WARPS_M = (BN == 256) ? 2 : 4;
    constexpr int WM = 128 / WARPS_M;
    constexpr int MI = WM / 16;
    constexpr int NI = 8;
    constexpr int ASTAGE = 128 * RSTRIDE;
    constexpr int BSTAGE = BN * RSTRIDE;

    extern __shared__ char smem[];
    const uint32_t tiles = (uint32_t)__cvta_generic_to_shared(smem);

    int bz = blockIdx.z;
    int bb = bz / nh, hh = bz - bb * nh;
    A += bb * sAb + hh * sAh;
    B += bb * sBb + hh * sBh;

    const int tid  = threadIdx.x;
    const int warp = tid >> 5, lane = tid & 31;
    const int wm = warp / (BN / 64), wn = warp % (BN / 64);
    const long rowBase = (long)blockIdx.y * 128;
    const long colBase = (long)blockIdx.x * BN;

    const int aoff_row = wm * WM + (lane & 15);
    const int akb      = ((lane >> 4) & 1) * 16;
    const int boff_n   = wn * 64 + (lane & 7) + ((lane >> 4) & 1) * 8;
    const int bkb      = ((lane >> 3) & 1) * 16;

    float acc[MI][NI][4];
    #pragma unroll
    for (int i = 0; i < MI; i++)
        #pragma unroll
        for (int j = 0; j < NI; j++)
            #pragma unroll
            for (int q = 0; q < 4; q++) acc[i][j][q] = 0.f;

#define CPA16(DST, SRC)                                                        \
    asm volatile("cp.async.cg.shared.global [%0], [%1], 16;" :: "r"(DST), "l"(SRC))

#define ISSUE(STG, T)                                                          \
    {                                                                          \
        uint32_t abase = tiles + (STG) * ASTAGE;                               \
        uint32_t bbase = tiles + STAGES * ASTAGE + (STG) * BSTAGE;             \
        _Pragma("unroll")                                                      \
        for (int it = 0; it < 4; it++) {                                       \
            int idx = tid + it * 256;                                          \
            int r = idx >> 3, c = idx & 7;                                     \
            CPA16(abase + r * RSTRIDE + c * 16,                                \
                  A + (rowBase + r) * lda + (T) * 64 + c * 8);                 \
        }                                                                      \
        _Pragma("unroll")                                                      \
        for (int it = 0; it < BN / 32; it++) {                                 \
            int idx = tid + it * 256;                                          \
            int r = idx >> 3, c = idx & 7;                                     \
            CPA16(bbase + r * RSTRIDE + c * 16,                                \
                  B + (colBase + r) * ldb + (T) * 64 + c * 8);                 \
        }                                                                      \
        asm volatile("cp.async.commit_group;" ::: "memory");                   \
    }

#define COMPUTE(STG)                                                           \
    {                                                                          \
        uint32_t abase = tiles + (STG) * ASTAGE;                               \
        uint32_t bbase = tiles + STAGES * ASTAGE + (STG) * BSTAGE;             \
        _Pragma("unroll")                                                      \
        for (int k16 = 0; k16 < 4; k16++) {                                    \
            uint32_t af[MI][4], bf[NI][2];                                     \
            _Pragma("unroll")                                                  \
            for (int mi = 0; mi < MI; mi++) {                                  \
                uint32_t ad = abase + (aoff_row + mi * 16) * RSTRIDE           \
                            + k16 * 32 + akb;                                  \
                asm volatile(                                                  \
                    "ldmatrix.sync.aligned.m8n8.x4.shared.b16 "                \
                    "{%0,%1,%2,%3}, [%4];"                                     \
                    : "=r"(af[mi][0]), "=r"(af[mi][1]),                        \
                      "=r"(af[mi][2]), "=r"(af[mi][3]) : "r"(ad));             \
            }                                                                  \
            _Pragma("unroll")                                                  \
            for (int p = 0; p < NI / 2; p++) {                                 \
                uint32_t bd = bbase + (boff_n + p * 16) * RSTRIDE              \
                            + k16 * 32 + bkb;                                  \
                asm volatile(                                                  \
                    "ldmatrix.sync.aligned.m8n8.x4.shared.b16 "                \
                    "{%0,%1,%2,%3}, [%4];"                                     \
                    : "=r"(bf[2 * p][0]), "=r"(bf[2 * p][1]),                  \
                      "=r"(bf[2 * p + 1][0]), "=r"(bf[2 * p + 1][1])           \
                    : "r"(bd));                                                \
            }                                                                  \
            _Pragma("unroll")                                                  \
            for (int mi = 0; mi < MI; mi++)                                    \
                _Pragma("unroll")                                              \
                for (int ni = 0; ni < NI; ni++)                                \
                    asm volatile(                                              \
                        "mma.sync.aligned.m16n8k16.row.col.f32.f16.f16.f32 "   \
                        "{%0,%1,%2,%3}, {%4,%5,%6,%7}, {%8,%9}, {%0,%1,%2,%3};"\
                        : "+f"(acc[mi][ni][0]), "+f"(acc[mi][ni][1]),          \
                          "+f"(acc[mi][ni][2]), "+f"(acc[mi][ni][3])           \
                        : "r"(af[mi][0]), "r"(af[mi][1]),                      \
                          "r"(af[mi][2]), "r"(af[mi][3]),                      \
                          "r"(bf[ni][0]), "r"(bf[ni][1]));                     \
        }                                                                      \
    }

    const int NK = K >> 6;          // BK=64; all call sites have NK >= STAGES
    #pragma unroll
    for (int s = 0; s < STAGES - 1; s++) ISSUE(s, s);

    for (int t = 0; t < NK; t++) {
        if (t < NK - 1) asm volatile("cp.async.wait_group 1;" ::: "memory");
        else            asm volatile("cp.async.wait_group 0;" ::: "memory");
        __syncthreads();
        if (t + STAGES - 1 < NK) ISSUE((t + STAGES - 1) % STAGES, t + STAGES - 1);
        COMPUTE(t % STAGES);
    }

    // epilogue
    float* Cf = (float*)Cv;
    __half* Ch = (__half*)Cv;
    const long cadd = bb * sCb + hh * sCh;
    #pragma unroll
    for (int mi = 0; mi < MI; mi++) {
        long row = rowBase + wm * WM + mi * 16 + (lane >> 2);
        #pragma unroll
        for (int ni = 0; ni < NI; ni++) {
            long col = colBase + wn * 64 + ni * 8 + (lane & 3) * 2;
            float2 v0, v1;
            v0.x = acc[mi][ni][0] * alpha; v0.y = acc[mi][ni][1] * alpha;
            v1.x = acc[mi][ni][2] * alpha; v1.y = acc[mi][ni][3] * alpha;
            if (EPI >= 1) {
                float2 bv = *(const float2*)(bias + col);
                v0.x += bv.x; v0.y += bv.y; v1.x += bv.x; v1.y += bv.y;
            }
            if (EPI == 2) {
                v0.x = gelu_exact(v0.x); v0.y = gelu_exact(v0.y);
                v1.x = gelu_exact(v1.x); v1.y = gelu_exact(v1.y);
            }
            if (EPI == 3) {
                float2 r0 = *(const float2*)(res + row * ldc + col);
                float2 r1 = *(const float2*)(res + (row + 8) * ldc + col);
                v0.x += r0.x; v0.y += r0.y; v1.x += r1.x; v1.y += r1.y;
            }
            if (OHALF) {
                *(__half2*)(Ch + cadd + row * ldc + col) = __floats2half2_rn(v0.x, v0.y);
                *(__half2*)(Ch + cadd + (row + 8) * ldc + col) = __floats2half2_rn(v1.x, v1.y);
            } else {
                *(float2*)(Cf + cadd + row * ldc + col) = v0;
                *(float2*)(Cf + cadd + (row + 8) * ldc + col) = v1;
            }
        }
    }
#undef CPA16
#undef ISSUE
#undef COMPUTE
}

// ---------------- fused flash attention ----------------
// grid (bh=128, qt=4), 256 threads. Q tile resident; K/V double-buffered.
#define FSTRIDE 272   // 128 halves (256B) + 16B pad

__global__ void __launch_bounds__(256) flash_attn(
    const __half* __restrict__ qkv, __half* __restrict__ attnc)
{
    extern __shared__ char smem[];
    const uint32_t Qs = (uint32_t)__cvta_generic_to_shared(smem);
    const uint32_t Ks = Qs + 128 * FSTRIDE;
    const uint32_t Vs = Ks + 2 * 128 * FSTRIDE;

    const int bh = blockIdx.x;
    const int qt = blockIdx.y;
    const int b = bh >> 2, h = bh & 3;
    const int tid = threadIdx.x, warp = tid >> 5, lane = tid & 31;
    const int g = lane >> 2, tq = lane & 3;

    const __half* Qg = qkv + (long)(b * 512 + qt * 128) * 1536 + h * 128;
    const __half* Kg = qkv + (long)(b * 512) * 1536 + 512 + h * 128;
    const __half* Vg = qkv + (long)(b * 512) * 1536 + 1024 + h * 128;

#define CPA16F(DST, SRC)                                                       \
    asm volatile("cp.async.cg.shared.global [%0], [%1], 16;" :: "r"(DST), "l"(SRC))

    #pragma unroll
    for (int it = 0; it < 8; it++) {
        int idx = tid + it * 256;
        int r = idx >> 4, c = idx & 15;
        CPA16F(Qs + r * FSTRIDE + c * 16, Qg + (long)r * 1536 + c * 8);
    }
    asm volatile("cp.async.commit_group;" ::: "memory");

#define LOAD_KV(J, BB)                                                         \
    {                                                                          \
        uint32_t kb = Ks + (BB) * 128 * FSTRIDE;                               \
        uint32_t vb = Vs + (BB) * 128 * FSTRIDE;                               \
        _Pragma("unroll")                                                      \
        for (int it = 0; it < 8; it++) {                                       \
            int idx = tid + it * 256;                                          \
            int r = idx >> 4, c = idx & 15;                                    \
            CPA16F(kb + r * FSTRIDE + c * 16,                                  \
                   Kg + (long)((J) * 128 + r) * 1536 + c * 8);                 \
        }                                                                      \
        _Pragma("unroll")                                                      \
        for (int it = 0; it < 8; it++) {                                       \
            int idx = tid + it * 256;                                          \
            int r = idx >> 4, c = idx & 15;                                    \
            CPA16F(vb + r * FSTRIDE + c * 16,                                  \
                   Vg + (long)((J) * 128 + r) * 1536 + c * 8);                 \
        }                                                                      \
        asm volatile("cp.async.commit_group;" ::: "memory");                   \
    }

    LOAD_KV(0, 0);
    LOAD_KV(1, 1);

    const int aoff_row = warp * 16 + (lane & 15);
    const int akb      = ((lane >> 4) & 1) * 16;
    const int boff_n   = (lane & 7) + ((lane >> 4) & 1) * 8;
    const int bkb      = ((lane >> 3) & 1) * 16;

    float oacc[16][4];
    #pragma unroll
    for (int i = 0; i < 16; i++)
        #pragma unroll
        for (int q = 0; q < 4; q++) oacc[i][q] = 0.f;
    float m0 = -3.4e38f, m1 = -3.4e38f, l0 = 0.f, l1 = 0.f;
    const float scale = 0.08838834764831845f;

    for (int j = 0; j < 4; j++) {
        if (j < 3) asm volatile("cp.async.wait_group 1;" ::: "memory");
        else       asm volatile("cp.async.wait_group 0;" ::: "memory");
        __syncthreads();
        const uint32_t Kb = Ks + (j & 1) * 128 * FSTRIDE;
        const uint32_t Vb = Vs + (j & 1) * 128 * FSTRIDE;

        float sacc[16][4];
        #pragma unroll
        for (int i = 0; i < 16; i++)
            #pragma unroll
            for (int q = 0; q < 4; q++) sacc[i][q] = 0.f;

        #pragma unroll
        for (int kk = 0; kk < 8; kk++) {
            uint32_t af[4];
            uint32_t ad = Qs + aoff_row * FSTRIDE + kk * 32 + akb;
            asm volatile("ldmatrix.sync.aligned.m8n8.x4.shared.b16 {%0,%1,%2,%3}, [%4];"
                : "=r"(af[0]), "=r"(af[1]), "=r"(af[2]), "=r"(af[3]) : "r"(ad));
            uint32_t bf[16][2];
            #pragma unroll
            for (int p = 0; p < 8; p++) {
                uint32_t bd = Kb + (boff_n + p * 16) * FSTRIDE + kk * 32 + bkb;
                asm volatile("ldmatrix.sync.aligned.m8n8.x4.shared.b16 {%0,%1,%2,%3}, [%4];"
                    : "=r"(bf[2 * p][0]), "=r"(bf[2 * p][1]),
                      "=r"(bf[2 * p + 1][0]), "=r"(bf[2 * p + 1][1]) : "r"(bd));
            }
            #pragma unroll
            for (int ni = 0; ni < 16; ni++)
                asm volatile(
                    "mma.sync.aligned.m16n8k16.row.col.f32.f16.f16.f32 "
                    "{%0,%1,%2,%3}, {%4,%5,%6,%7}, {%8,%9}, {%0,%1,%2,%3};"
                    : "+f"(sacc[ni][0]), "+f"(sacc[ni][1]),
                      "+f"(sacc[ni][2]), "+f"(sacc[ni][3])
                    : "r"(af[0]), "r"(af[1]), "r"(af[2]), "r"(af[3]),
                      "r"(bf[ni][0]), "r"(bf[ni][1]));
        }

        float mt0 = -3.4e38f, mt1 = -3.4e38f;
        #pragma unroll
        for (int ni = 0; ni < 16; ni++) {
            #pragma unroll
            for (int q = 0; q < 4; q++) sacc[ni][q] *= scale;
            mt0 = fmaxf(mt0, fmaxf(sacc[ni][0], sacc[ni][1]));
            mt1 = fmaxf(mt1, fmaxf(sacc[ni][2], sacc[ni][3]));
        }
        mt0 = fmaxf(mt0, __shfl_xor_sync(0xffffffffu, mt0, 1));
        mt0 = fmaxf(mt0, __shfl_xor_sync(0xffffffffu, mt0, 2));
        mt1 = fmaxf(mt1, __shfl_xor_sync(0xffffffffu, mt1, 1));
        mt1 = fmaxf(mt1, __shfl_xor_sync(0xffffffffu, mt1, 2));
        float mn0 = fmaxf(m0, mt0), mn1 = fmaxf(m1, mt1);
        float al0 = __expf(m0 - mn0), al1 = __expf(m1 - mn1);
        m0 = mn0; m1 = mn1;
        l0 *= al0; l1 *= al1;
        #pragma unroll
        for (int ni = 0; ni < 16; ni++) {
            oacc[ni][0] *= al0; oacc[ni][1] *= al0;
            oacc[ni][2] *= al1; oacc[ni][3] *= al1;
        }
        uint32_t ph[16][2];
        #pragma unroll
        for (int ni = 0; ni < 16; ni++) {
            float p0 = __expf(sacc[ni][0] - mn0);
            float p1 = __expf(sacc[ni][1] - mn0);
            float p2 = __expf(sacc[ni][2] - mn1);
            float p3 = __expf(sacc[ni][3] - mn1);
            l0 += p0 + p1; l1 += p2 + p3;
            __half2 h0 = __floats2half2_rn(p0, p1);
            __half2 h1 = __floats2half2_rn(p2, p3);
            ph[ni][0] = *reinterpret_cast<uint32_t*>(&h0);
            ph[ni][1] = *reinterpret_cast<uint32_t*>(&h1);
        }

        #pragma unroll
        for (int kk = 0; kk < 8; kk++) {
            uint32_t a0 = ph[2 * kk][0], a1 = ph[2 * kk][1];
            uint32_t a2 = ph[2 * kk + 1][0], a3 = ph[2 * kk + 1][1];
            #pragma unroll
            for (int p = 0; p < 8; p++) {
                uint32_t vb0, vb1, vb2, vb3;
                uint32_t vd = Vb + (kk * 16 + (lane & 15)) * FSTRIDE
                            + p * 32 + ((lane >> 4) & 1) * 16;
                asm volatile("ldmatrix.sync.aligned.m8n8.x4.trans.shared.b16 {%0,%1,%2,%3}, [%4];"
                    : "=r"(vb0), "=r"(vb1), "=r"(vb2), "=r"(vb3) : "r"(vd));
                asm volatile(
                    "mma.sync.aligned.m16n8k16.row.col.f32.f16.f16.f32 "
                    "{%0,%1,%2,%3}, {%4,%5,%6,%7}, {%8,%9}, {%0,%1,%2,%3};"
                    : "+f"(oacc[2 * p][0]), "+f"(oacc[2 * p][1]),
                      "+f"(oacc[2 * p][2]), "+f"(oacc[2 * p][3])
                    : "r"(a0), "r"(a1), "r"(a2), "r"(a3), "r"(vb0), "r"(vb1));
                asm volatile(
                    "mma.sync.aligned.m16n8k16.row.col.f32.f16.f16.f32 "
                    "{%0,%1,%2,%3}, {%4,%5,%6,%7}, {%8,%9}, {%0,%1,%2,%3};"
                    : "+f"(oacc[2 * p + 1][0]), "+f"(oacc[2 * p + 1][1]),
                      "+f"(oacc[2 * p + 1][2]), "+f"(oacc[2 * p + 1][3])
                    : "r"(a0), "r"(a1), "r"(a2), "r"(a3), "r"(vb2), "r"(vb3));
            }
        }
        __syncthreads();
        if (j + 2 < 4) LOAD_KV(j + 2, j & 1);
    }

    l0 += __shfl_xor_sync(0xffffffffu, l0, 1);
    l0 += __shfl_xor_sync(0xffffffffu, l0, 2);
    l1 += __shfl_xor_sync(0xffffffffu, l1, 1);
    l1 += __shfl_xor_sync(0xffffffffu, l1, 2);
    float inv0 = 1.f / l0, inv1 = 1.f / l1;
    long rowg = (long)(b * 512 + qt * 128 + warp * 16 + g);
    #pragma unroll
    for (int ni = 0; ni < 16; ni++) {
        long col = h * 128 + ni * 8 + tq * 2;
        *(__half2*)(attnc + rowg * DMODEL + col) =
            __floats2half2_rn(oacc[ni][0] * inv0, oacc[ni][1] * inv0);
        *(__half2*)(attnc + (rowg + 8) * DMODEL + col) =
            __floats2half2_rn(oacc[ni][2] * inv1, oacc[ni][3] * inv1);
    }
#undef CPA16F
#undef LOAD_KV
}

// ---------------- f32 -> f16 convert ----------------
__global__ void f2h_kernel(const float* __restrict__ in, __half* __restrict__ out, long n4)
{
    long i = blockIdx.x * 256 + threadIdx.x;
    if (i >= n4) return;
    float4 v = *(const float4*)(in + i * 4);
    __half2* o = (__half2*)(out + i * 4);
    o[0] = __floats2half2_rn(v.x, v.y);
    o[1] = __floats2half2_rn(v.z, v.w);
}

// ---------------- LayerNorm (f32), generic ----------------
__global__ void ln_kernel(const float* __restrict__ A, const float* __restrict__ R,
                          const float* __restrict__ g, const float* __restrict__ b,
                          float* __restrict__ out, int nrows)
{
    int warp = (blockIdx.x * blockDim.x + threadIdx.x) >> 5;
    int lane = threadIdx.x & 31;
    if (warp >= nrows) return;
    const float* a = A + (long)warp * DMODEL;
    float4 v[4];
    float s = 0.f;
    #pragma unroll
    for (int t = 0; t < 4; t++) {
        int c = (t * 32 + lane) * 4;
        v[t] = *(const float4*)(a + c);
        if (R) {
            float4 r4 = *(const float4*)(R + (long)warp * DMODEL + c);
            v[t].x += r4.x; v[t].y += r4.y; v[t].z += r4.z; v[t].w += r4.w;
        }
        s += v[t].x + v[t].y + v[t].z + v[t].w;
    }
    s = warp_sum(s);
    float mean = s * (1.f / DMODEL);
    float vs = 0.f;
    #pragma unroll
    for (int t = 0; t < 4; t++) {
        float dx = v[t].x - mean, dy = v[t].y - mean, dz = v[t].z - mean, dw = v[t].w - mean;
        vs += dx * dx + dy * dy + dz * dz + dw * dw;
    }
    vs = warp_sum(vs);
    float rstd = rsqrtf(vs * (1.f / DMODEL) + 1e-5f);
    #pragma unroll
    for (int t = 0; t < 4; t++) {
        int c = (t * 32 + lane) * 4;
        float4 gv = *(const float4*)(g + c);
        float4 bv = *(const float4*)(b + c);
        float4 o;
        o.x = (v[t].x - mean) * rstd * gv.x + bv.x;
        o.y = (v[t].y - mean) * rstd * gv.y + bv.y;
        o.z = (v[t].z - mean) * rstd * gv.z + bv.z;
        o.w = (v[t].w - mean) * rstd * gv.w + bv.w;
        *(float4*)(out + (long)warp * DMODEL + c) = o;
    }
}

// ---------------- fused LN1 -> x1, LN3 (regs), qin angles ----------------
// X = x + attnproj (pre-summed in GEMM epilogue)
__global__ void ln13_qin_kernel(
    const float* __restrict__ X,
    const float* __restrict__ g1, const float* __restrict__ b1,
    const float* __restrict__ g3, const float* __restrict__ b3,
    const float* __restrict__ qw, const float* __restrict__ qb,
    float* __restrict__ x1out, float* __restrict__ ang)
{
    int row = (blockIdx.x * blockDim.x + threadIdx.x) >> 5;
    int lane = threadIdx.x & 31;
    if (row >= ROWS) return;
    const float* a = X + (long)row * DMODEL;
    float4 v[4];
    float s = 0.f;
    #pragma unroll
    for (int t = 0; t < 4; t++) {
        int c = (t * 32 + lane) * 4;
        v[t] = *(const float4*)(a + c);
        s += v[t].x + v[t].y + v[t].z + v[t].w;
    }
    s = warp_sum(s);
    float mean = s * (1.f / DMODEL);
    float vs = 0.f;
    #pragma unroll
    for (int t = 0; t < 4; t++) {
        float dx = v[t].x - mean, dy = v[t].y - mean, dz = v[t].z - mean, dw = v[t].w - mean;
        vs += dx * dx + dy * dy + dz * dz + dw * dw;
    }
    vs = warp_sum(vs);
    float rstd = rsqrtf(vs * (1.f / DMODEL) + 1e-5f);

    float s3 = 0.f;
    #pragma unroll
    for (int t = 0; t < 4; t++) {
        int c = (t * 32 + lane) * 4;
        float4 gv = *(const float4*)(g1 + c);
        float4 bv = *(const float4*)(b1 + c);
        v[t].x = (v[t].x - mean) * rstd * gv.x + bv.x;
        v[t].y = (v[t].y - mean) * rstd * gv.y + bv.y;
        v[t].z = (v[t].z - mean) * rstd * gv.z + bv.z;
        v[t].w = (v[t].w - mean) * rstd * gv.w + bv.w;
        *(float4*)(x1out + (long)row * DMODEL + c) = v[t];
        s3 += v[t].x + v[t].y + v[t].z + v[t].w;
    }
    s3 = warp_sum(s3);
    float mean3 = s3 * (1.f / DMODEL);
    float vs3 = 0.f;
    #pragma unroll
    for (int t = 0; t < 4; t++) {
        float dx = v[t].x - mean3, dy = v[t].y - mean3, dz = v[t].z - mean3, dw = v[t].w - mean3;
        vs3 += dx * dx + dy * dy + dz * dz + dw * dw;
    }
    vs3 = warp_sum(vs3);
    float rstd3 = rsqrtf(vs3 * (1.f / DMODEL) + 1e-5f);
    #pragma unroll
    for (int t = 0; t < 4; t++) {
        int c = (t * 32 + lane) * 4;
        float4 gv = *(const float4*)(g3 + c);
        float4 bv = *(const float4*)(b3 + c);
        v[t].x = (v[t].x - mean3) * rstd3 * gv.x + bv.x;
        v[t].y = (v[t].y - mean3) * rstd3 * gv.y + bv.y;
        v[t].z = (v[t].z - mean3) * rstd3 * gv.z + bv.z;
        v[t].w = (v[t].w - mean3) * rstd3 * gv.w + bv.w;
    }
    float myang = 0.f;
    #pragma unroll
    for (int o = 0; o < NQ; o++) {
        const float* wr = qw + o * DMODEL;
        float p = 0.f;
        #pragma unroll
        for (int t = 0; t < 4; t++) {
            int c = (t * 32 + lane) * 4;
            float4 wv = *(const float4*)(wr + c);
            p += v[t].x * wv.x + v[t].y * wv.y + v[t].z * wv.z + v[t].w * wv.w;
        }
        p = warp_sum(p);
        if (lane == o) myang = p + qb[o];
    }
    if (lane < NQ) ang[(long)row * NQ + lane] = myang;
}

// ---------------- build real-ified circuit unitary (f16 out, 512x512) -------
__global__ void build_u_kernel(const float* __restrict__ qw, __half* __restrict__ Bq)
{
    __shared__ float2 st[DIMQ];
    int col = blockIdx.x;
    int t = threadIdx.x;
    st[t] = make_float2(0.f, 0.f);
    st[t + 128] = make_float2(0.f, 0.f);
    __syncthreads();
    if (t == 0) st[col] = make_float2(1.f, 0.f);
    __syncthreads();

    for (int l = 0; l < 4; l++) {
        for (int i = 0; i < NQ; i++) {
            float w0 = qw[(l * 2 + 0) * NQ + i];
            float w1 = qw[(l * 2 + 1) * NQ + i];
            float sn, cs, sn2, cs2;
            sincosf(0.5f * w0, &sn, &cs);
            sincosf(0.5f * w1, &sn2, &cs2);
            float2 M00 = make_float2( cs * cs2, -cs * sn2);
            float2 M01 = make_float2(-sn * sn2, -sn * cs2);
            float2 M10 = make_float2( sn * sn2, -sn * cs2);
            float2 M11 = make_float2( cs * cs2,  cs * sn2);
            int bpos = 7 - i;
            int lowmask = (1 << bpos) - 1;
            int s0 = ((t >> bpos) << (bpos + 1)) | (t & lowmask);
            int s1 = s0 | (1 << bpos);
            float2 a0 = st[s0], a1 = st[s1];
            float2 n0, n1;
            n0.x = M00.x * a0.x - M00.y * a0.y + M01.x * a1.x - M01.y * a1.y;
            n0.y = M00.x * a0.y + M00.y * a0.x + M01.x * a1.y + M01.y * a1.x;
            n1.x = M10.x * a0.x - M10.y * a0.y + M11.x * a1.x - M11.y * a1.y;
            n1.y = M10.x * a0.y + M10.y * a0.x + M11.x * a1.y + M11.y * a1.x;
            st[s0] = n0; st[s1] = n1;
            __syncthreads();
        }
        for (int i = 0; i < NQ - 1; i++) {
            int cb = 7 - i, tb = 6 - i;
            if (t < 64) {
                int tlow = t & ((1 << tb) - 1);
                int s0 = ((t >> tb) << (tb + 2)) | (1 << cb) | tlow;
                int s1 = s0 | (1 << tb);
                float2 tmp = st[s0]; st[s0] = st[s1]; st[s1] = tmp;
            }
            __syncthreads();
        }
    }
    #pragma unroll
    for (int h = 0; h < 2; h++) {
        int s = t + h * 128;
        float2 u = st[s];
        Bq[(long)s * 512 + col]               = __float2half( u.x);
        Bq[(long)s * 512 + 256 + col]         = __float2half(-u.y);
        Bq[(long)(256 + s) * 512 + col]       = __float2half( u.y);
        Bq[(long)(256 + s) * 512 + 256 + col] = __float2half( u.x);
    }
}

// ---------------- product state Psi (split re/im, f16 out) ----------------
__global__ void psi_kernel(const float* __restrict__ ang, __half* __restrict__ psis)
{
    __shared__ float2 sq[NQ][2];
    int row = blockIdx.x;
    int s = threadIdx.x;
    if (s < NQ) {
        float a = ang[(long)row * NQ + s];
        float sn, cs;
        sincosf(0.5f * a, &sn, &cs);
        sq[s][0] = make_float2(cs * cs, -cs * sn);
        sq[s][1] = make_float2(sn * sn, -sn * cs);
    }
    __syncthreads();
    float2 amp = make_float2(1.f, 0.f);
    #pragma unroll
    for (int i = 0; i < NQ; i++) {
        float2 q = sq[i][(s >> (7 - i)) & 1];
        float2 na;
        na.x = amp.x * q.x - amp.y * q.y;
        na.y = amp.x * q.y + amp.y * q.x;
        amp = na;
    }
    psis[(long)row * 512 + s] = __float2half(amp.x);
    psis[(long)row * 512 + 256 + s] = __float2half(amp.y);
}

// ---------------- fused z expectations + x2 = x1 + z @ qout_w^T + qout_b ----
__global__ void zexp_qout_kernel(
    const float* __restrict__ Phis, const float* __restrict__ x1,
    const float* __restrict__ w, const float* __restrict__ b,
    float* __restrict__ out, __half* __restrict__ outh)
{
    __shared__ float partial[8][9];
    __shared__ float zsh[NQ];
    int row = blockIdx.x;
    int s = threadIdx.x;
    float re = Phis[(long)row * 512 + s];
    float im = Phis[(long)row * 512 + 256 + s];
    float p = re * re + im * im;
    int lane = s & 31, wid = s >> 5;
    float vals[NQ];
    #pragma unroll
    for (int i = 0; i < NQ; i++)
        vals[i] = ((s >> (7 - i)) & 1) ? -p : p;
    #pragma unroll
    for (int o = 16; o; o >>= 1)
        #pragma unroll
        for (int i = 0; i < NQ; i++)
            vals[i] += __shfl_xor_sync(0xffffffffu, vals[i], o);
    if (lane == 0)
        #pragma unroll
        for (int i = 0; i < NQ; i++) partial[wid][i] = vals[i];
    __syncthreads();
    if (s < NQ) {
        float acc = 0.f;
        #pragma unroll
        for (int wv = 0; wv < 8; wv++) acc += partial[wv][s];
        zsh[s] = acc;
    }
    __syncthreads();
    float z0 = zsh[0], z1 = zsh[1], z2 = zsh[2], z3 = zsh[3];
    float z4 = zsh[4], z5 = zsh[5], z6 = zsh[6], z7 = zsh[7];
    #pragma unroll
    for (int half_i = 0; half_i < 2; half_i++) {
        int col = s + half_i * 256;
        float4 w0 = *(const float4*)(w + (long)col * NQ);
        float4 w1 = *(const float4*)(w + (long)col * NQ + 4);
        float acc = b[col];
        acc += z0 * w0.x + z1 * w0.y + z2 * w0.z + z3 * w0.w;
        acc += z4 * w1.x + z5 * w1.y + z6 * w1.z + z7 * w1.w;
        long gidx = (long)row * DMODEL + col;
        float val = x1[gidx] + acc;
        out[gidx] = val;
        outh[gidx] = __float2half(val);
    }
}

// ---------------- launch ----------------
extern "C" void kernel_launch(void* const* d_in, const int* in_sizes, int n_in,
                              void* d_out, int out_size)
{
    const float* x          = (const float*)d_in[0];
    const float* attn_in_w  = (const float*)d_in[1];
    const float* attn_in_b  = (const float*)d_in[2];
    const float* attn_out_w = (const float*)d_in[3];
    const float* attn_out_b = (const float*)d_in[4];
    const float* ln1_g      = (const float*)d_in[5];
    const float* ln1_b      = (const float*)d_in[6];
    const float* ln2_g      = (const float*)d_in[7];
    const float* ln2_b      = (const float*)d_in[8];
    const float* ln3_g      = (const float*)d_in[9];
    const float* ln3_b      = (const float*)d_in[10];
    const float* qin_w      = (const float*)d_in[11];
    const float* qin_b      = (const float*)d_in[12];
    const float* qweights   = (const float*)d_in[13];
    const float* qout_w     = (const float*)d_in[14];
    const float* qout_b     = (const float*)d_in[15];
    const float* ffn_w1     = (const float*)d_in[16];
    const float* ffn_b1     = (const float*)d_in[17];
    const float* ffn_w2     = (const float*)d_in[18];
    const float* ffn_b2     = (const float*)d_in[19];
    float* out = (float*)d_out;

    __half *xh, *wih, *woh, *w1h, *w2h, *qkvh, *attnch, *uqh, *psish, *x2h, *hbufh;
    float  *xsum, *x1, *angles, *phis, *x2, *ffnsum;
    cudaGetSymbolAddress((void**)&xh,       g_xh);
    cudaGetSymbolAddress((void**)&wih,      g_wih);
    cudaGetSymbolAddress((void**)&woh,      g_woh);
    cudaGetSymbolAddress((void**)&w1h,      g_w1h);
    cudaGetSymbolAddress((void**)&w2h,      g_w2h);
    cudaGetSymbolAddress((void**)&qkvh,     g_qkv_h);
    cudaGetSymbolAddress((void**)&attnch,   g_attnc_h);
    cudaGetSymbolAddress((void**)&xsum,     g_xsum);
    cudaGetSymbolAddress((void**)&x1,       g_x1);
    cudaGetSymbolAddress((void**)&angles,   g_angles);
    cudaGetSymbolAddress((void**)&uqh,      g_uqh);
    cudaGetSymbolAddress((void**)&psish,    g_psis_h);
    cudaGetSymbolAddress((void**)&phis,     g_phis);
    cudaGetSymbolAddress((void**)&x2,       g_x2);
    cudaGetSymbolAddress((void**)&x2h,      g_x2h);
    cudaGetSymbolAddress((void**)&hbufh,    g_hbuf_h);
    cudaGetSymbolAddress((void**)&ffnsum,   g_ffnsum);

    const int SMEM_G  = 3 * (128 * RSTRIDE + 128 * RSTRIDE);   // 110592
    const int SMEM_FA = 5 * 128 * FSTRIDE;                     // 174080

    cudaFuncSetAttribute(gemm_h<128, 1, true , 3, 2>, cudaFuncAttributeMaxDynamicSharedMemorySize, SMEM_G);
    cudaFuncSetAttribute(gemm_h<128, 3, false, 3, 2>, cudaFuncAttributeMaxDynamicSharedMemorySize, SMEM_G);
    cudaFuncSetAttribute(gemm_h<128, 0, false, 3, 2>, cudaFuncAttributeMaxDynamicSharedMemorySize, SMEM_G);
    cudaFuncSetAttribute(gemm_h<128, 2, true , 3, 2>, cudaFuncAttributeMaxDynamicSharedMemorySize, SMEM_G);
    cudaFuncSetAttribute(flash_attn, cudaFuncAttributeMaxDynamicSharedMemorySize, SMEM_FA);

    // 0) dtype conversions
    f2h_kernel<<<(ROWS * DMODEL / 4 + 255) / 256, 256>>>(x, xh, ROWS * DMODEL / 4);
    f2h_kernel<<<(1536 * DMODEL / 4 + 255) / 256, 256>>>(attn_in_w, wih, 1536 * DMODEL / 4);
    f2h_kernel<<<(DMODEL * DMODEL / 4 + 255) / 256, 256>>>(attn_out_w, woh, DMODEL * DMODEL / 4);
    f2h_kernel<<<(2048 * DMODEL / 4 + 255) / 256, 256>>>(ffn_w1, w1h, 2048 * DMODEL / 4);
    f2h_kernel<<<(DMODEL * 2048 / 4 + 255) / 256, 256>>>(ffn_w2, w2h, DMODEL * 2048 / 4);

    // 1) qkv = x @ in_w^T + in_b  -> half
    gemm_h<128, 1, true, 3, 2><<<dim3(1536 / 128, ROWS / 128, 1), 256, SMEM_G>>>(
        xh, wih, attn_in_b, nullptr, qkvh, DMODEL, DMODEL, DMODEL, 1536,
        1, 0, 0, 0, 0, 0, 0, 1.f);

    // 2-4) fused attention -> attnc (half, concat layout)
    flash_attn<<<dim3(BATCH * NHEADS, SEQ / 128), 256, SMEM_FA>>>(qkvh, attnch);

    // 5) xsum = x + attnc @ out_w^T + out_b  (residual fused)
    gemm_h<128, 3, false, 3, 2><<<dim3(DMODEL / 128, ROWS / 128, 1), 256, SMEM_G>>>(
        attnch, woh, attn_out_b, x, xsum, DMODEL, DMODEL, DMODEL, DMODEL,
        1, 0, 0, 0, 0, 0, 0, 1.f);

    // 6+7+8) fused: x1 = LN1(xsum); angles = LN3(x1) @ qin_w^T + qin_b
    ln13_qin_kernel<<<ROWS / 8, 256>>>(xsum, ln1_g, ln1_b, ln3_g, ln3_b,
                                       qin_w, qin_b, x1, angles);

    // 9) real-ified circuit unitary -> half
    build_u_kernel<<<DIMQ, 128>>>(qweights, uqh);

    // 10) product state Psi -> half
    psi_kernel<<<ROWS, 256>>>(angles, psish);

    // 11) Phi = Psi @ Uq^T -> f32
    gemm_h<128, 0, false, 3, 2><<<dim3(512 / 128, ROWS / 128, 1), 256, SMEM_G>>>(
        psish, uqh, nullptr, nullptr, phis, 512, 512, 512, 512,
        1, 0, 0, 0, 0, 0, 0, 1.f);

    // 12+13) fused: z expectations + x2 = x1 + z @ qout_w^T + qout_b
    zexp_qout_kernel<<<ROWS, 256>>>(phis, x1, qout_w, qout_b, x2, x2h);

    // 14) hbuf = gelu(x2 @ ffn_w1^T + ffn_b1) -> half
    gemm_h<128, 2, true, 3, 2><<<dim3(2048 / 128, ROWS / 128, 1), 256, SMEM_G>>>(
        x2h, w1h, ffn_b1, nullptr, hbufh, DMODEL, DMODEL, DMODEL, 2048,
        1, 0, 0, 0, 0, 0, 0, 1.f);

    // 15) ffnsum = x2 + hbuf @ ffn_w2^T + ffn_b2  (residual fused)
    gemm_h<128, 3, false, 3, 2><<<dim3(DMODEL / 128, ROWS / 128, 1), 256, SMEM_G>>>(
        hbufh, w2h, ffn_b2, x2, ffnsum, 2048, 2048, 2048, DMODEL,
        1, 0, 0, 0, 0, 0, 0, 1.f);

    // 16) out = LN(ffnsum; ln2)
    ln_kernel<<<ROWS / 8, 256>>>(ffnsum, nullptr, ln2_g, ln2_b, out, ROWS);
}